// round 2
// baseline (speedup 1.0000x reference)
#include <cuda_runtime.h>

#define NB   12544      // 196*64 token rows
#define MTOT 2048       // memory slots
#define DDIM 256        // feature dim == H*W

// ---------------- scratch (no allocs allowed) ----------------
__device__ float g_Qc[NB * DDIM];
__device__ float g_Qf[NB * DDIM];
__device__ float g_Kc[MTOT * DDIM];
__device__ float g_Vc[MTOT * DDIM];
__device__ float g_Kf[MTOT * DDIM];
__device__ float g_Vf[MTOT * DDIM];
__device__ float g_qm[NB];
__device__ float g_qv[NB];
__device__ float g_km[MTOT];
__device__ float g_kv[MTOT];
__device__ float g_OutS[NB * DDIM];

// ---------------- C[R,256] = A[R,256] @ W[256,256]^T ----------------
__global__ __launch_bounds__(256) void gemm_nt(const float* __restrict__ A,
                                               const float* __restrict__ W,
                                               float* __restrict__ C) {
    __shared__ float As[16][68];
    __shared__ float Ws[16][68];
    const int tid = threadIdx.x;
    const int tx = tid & 15, ty = tid >> 4;
    const int bm = blockIdx.x * 64;
    const int bn = blockIdx.y * 64;
    const int lr = tid >> 2;          // 0..63
    const int lk = (tid & 3) * 4;     // 0,4,8,12

    float acc[4][4];
#pragma unroll
    for (int i = 0; i < 4; i++)
#pragma unroll
        for (int j = 0; j < 4; j++) acc[i][j] = 0.f;

    for (int k0 = 0; k0 < 256; k0 += 16) {
        float4 av = *(const float4*)(A + (size_t)(bm + lr) * 256 + k0 + lk);
        float4 wv = *(const float4*)(W + (size_t)(bn + lr) * 256 + k0 + lk);
        As[lk + 0][lr] = av.x; As[lk + 1][lr] = av.y;
        As[lk + 2][lr] = av.z; As[lk + 3][lr] = av.w;
        Ws[lk + 0][lr] = wv.x; Ws[lk + 1][lr] = wv.y;
        Ws[lk + 2][lr] = wv.z; Ws[lk + 3][lr] = wv.w;
        __syncthreads();
#pragma unroll
        for (int k = 0; k < 16; k++) {
            float4 a = *(const float4*)&As[k][ty * 4];
            float4 b = *(const float4*)&Ws[k][tx * 4];
            acc[0][0] += a.x * b.x; acc[0][1] += a.x * b.y; acc[0][2] += a.x * b.z; acc[0][3] += a.x * b.w;
            acc[1][0] += a.y * b.x; acc[1][1] += a.y * b.y; acc[1][2] += a.y * b.z; acc[1][3] += a.y * b.w;
            acc[2][0] += a.z * b.x; acc[2][1] += a.z * b.y; acc[2][2] += a.z * b.z; acc[2][3] += a.z * b.w;
            acc[3][0] += a.w * b.x; acc[3][1] += a.w * b.y; acc[3][2] += a.w * b.z; acc[3][3] += a.w * b.w;
        }
        __syncthreads();
    }
#pragma unroll
    for (int i = 0; i < 4; i++) {
        float4 o = make_float4(acc[i][0], acc[i][1], acc[i][2], acc[i][3]);
        *(float4*)(C + (size_t)(bm + ty * 4 + i) * 256 + bn + tx * 4) = o;
    }
}

// ---------------- per-row mean / var(ddof=1), 1 warp per row ----------------
__global__ __launch_bounds__(256) void row_stats(const float* __restrict__ X,
                                                 float* __restrict__ mean,
                                                 float* __restrict__ var) {
    const int row = blockIdx.x * 8 + (threadIdx.x >> 5);
    const int lane = threadIdx.x & 31;
    const float* xr = X + (size_t)row * 256;
    float s = 0.f, ss = 0.f;
#pragma unroll
    for (int c = 0; c < 256; c += 32) {
        float v = xr[c + lane];
        s += v;
        ss += v * v;
    }
#pragma unroll
    for (int o = 16; o > 0; o >>= 1) {
        s += __shfl_xor_sync(0xffffffffu, s, o);
        ss += __shfl_xor_sync(0xffffffffu, ss, o);
    }
    if (lane == 0) {
        float m = s * (1.f / 256.f);
        mean[row] = m;
        var[row] = (ss - 256.f * m * m) * (1.f / 255.f);
    }
}

// ---------------- fused flash attention, both branches ----------------
// gridDim = (NB/64, 2); blockIdx.y: 0=channel (dot/16), 1=spatial (SSIM)
// BM=64 rows, BN=64 mem-slots per tile, D=256. 256 threads, 4x4 score micro-tile.
#define SMEM_FLOATS (32 * 68 + 32 * 68 + 64 * 65 + 64 * 256)

__global__ __launch_bounds__(256, 2) void attn(float* __restrict__ OutC) {
    extern __shared__ float smem[];
    float* Qt = smem;                 // [32][68] k-major
    float* Kt = Qt + 32 * 68;         // [32][68] k-major
    float* Pt = Kt + 32 * 68;         // [64(j)][65(row)]
    float* Vs = Pt + 64 * 65;         // [64][256]

    const int tid = threadIdx.x;
    const int tx = tid & 15, ty = tid >> 4;
    const bool spatial = (blockIdx.y != 0);
    const float* Q = spatial ? g_Qf : g_Qc;
    const float* K = spatial ? g_Kf : g_Kc;
    const float* V = spatial ? g_Vf : g_Vc;
    float* O = spatial ? g_OutS : OutC;
    const int rowBase = blockIdx.x * 64;

    float acc[4][16];
#pragma unroll
    for (int i = 0; i < 4; i++)
#pragma unroll
        for (int c = 0; c < 16; c++) acc[i][c] = 0.f;

    float mrow[4], lrow[4], qmr[4], qvr[4];
#pragma unroll
    for (int i = 0; i < 4; i++) { mrow[i] = -1e30f; lrow[i] = 0.f; qmr[i] = 0.f; qvr[i] = 0.f; }
    if (spatial) {
#pragma unroll
        for (int i = 0; i < 4; i++) {
            qmr[i] = g_qm[rowBase + ty * 4 + i];
            qvr[i] = g_qv[rowBase + ty * 4 + i];
        }
    }

    for (int j0 = 0; j0 < MTOT; j0 += 64) {
        float s[4][4];
#pragma unroll
        for (int i = 0; i < 4; i++)
#pragma unroll
            for (int j = 0; j < 4; j++) s[i][j] = 0.f;

        for (int k0 = 0; k0 < 256; k0 += 32) {
            __syncthreads();
#pragma unroll
            for (int u = 0; u < 2; u++) {
                int idx = u * 256 + tid;         // 0..511
                int r = idx >> 3;                // 0..63
                int kk = (idx & 7) * 4;          // 0..28
                float4 q4 = *(const float4*)(Q + (size_t)(rowBase + r) * 256 + k0 + kk);
                float4 k4 = *(const float4*)(K + (size_t)(j0 + r) * 256 + k0 + kk);
                Qt[(kk + 0) * 68 + r] = q4.x; Qt[(kk + 1) * 68 + r] = q4.y;
                Qt[(kk + 2) * 68 + r] = q4.z; Qt[(kk + 3) * 68 + r] = q4.w;
                Kt[(kk + 0) * 68 + r] = k4.x; Kt[(kk + 1) * 68 + r] = k4.y;
                Kt[(kk + 2) * 68 + r] = k4.z; Kt[(kk + 3) * 68 + r] = k4.w;
            }
            __syncthreads();
#pragma unroll
            for (int k = 0; k < 32; k++) {
                float4 a = *(const float4*)&Qt[k * 68 + ty * 4];
                float4 b = *(const float4*)&Kt[k * 68 + tx * 4];
                s[0][0] += a.x * b.x; s[0][1] += a.x * b.y; s[0][2] += a.x * b.z; s[0][3] += a.x * b.w;
                s[1][0] += a.y * b.x; s[1][1] += a.y * b.y; s[1][2] += a.y * b.z; s[1][3] += a.y * b.w;
                s[2][0] += a.z * b.x; s[2][1] += a.z * b.y; s[2][2] += a.z * b.z; s[2][3] += a.z * b.w;
                s[3][0] += a.w * b.x; s[3][1] += a.w * b.y; s[3][2] += a.w * b.z; s[3][3] += a.w * b.w;
            }
        }

        // ---- score transform ----
        if (!spatial) {
#pragma unroll
            for (int i = 0; i < 4; i++)
#pragma unroll
                for (int j = 0; j < 4; j++) s[i][j] *= 0.0625f;  // 1/sqrt(256)
        } else {
            float kmr[4], kvr[4];
#pragma unroll
            for (int j = 0; j < 4; j++) {
                kmr[j] = g_km[j0 + tx * 4 + j];
                kvr[j] = g_kv[j0 + tx * 4 + j];
            }
#pragma unroll
            for (int i = 0; i < 4; i++)
#pragma unroll
                for (int j = 0; j < 4; j++) {
                    float mp  = qmr[i] * kmr[j];
                    float cov = (s[i][j] - 256.f * mp) * (1.f / 255.f);
                    float num = (2.f * mp + 0.01f) * (2.f * cov + 0.03f);
                    float den = (qmr[i] * qmr[i] + kmr[j] * kmr[j] + 0.01f) *
                                (qvr[i] + kvr[j] + 0.03f);
                    s[i][j] = num / (den + 1e-8f);
                }
        }

        // ---- online softmax (rows replicated across the 16-lane tx group) ----
#pragma unroll
        for (int i = 0; i < 4; i++) {
            float tm = fmaxf(fmaxf(s[i][0], s[i][1]), fmaxf(s[i][2], s[i][3]));
#pragma unroll
            for (int o = 8; o > 0; o >>= 1) tm = fmaxf(tm, __shfl_xor_sync(0xffffffffu, tm, o));
            float mnew = fmaxf(mrow[i], tm);
            float scale = __expf(mrow[i] - mnew);
            mrow[i] = mnew;
            float ps = 0.f;
#pragma unroll
            for (int j = 0; j < 4; j++) {
                float p = __expf(s[i][j] - mnew);
                s[i][j] = p;
                ps += p;
            }
#pragma unroll
            for (int o = 8; o > 0; o >>= 1) ps += __shfl_xor_sync(0xffffffffu, ps, o);
            lrow[i] = lrow[i] * scale + ps;
#pragma unroll
            for (int c = 0; c < 16; c++) acc[i][c] *= scale;
#pragma unroll
            for (int j = 0; j < 4; j++) Pt[(tx * 4 + j) * 65 + ty * 4 + i] = s[i][j];
        }

        // ---- load V tile (64x256) ----
#pragma unroll
        for (int u = 0; u < 16; u++) {
            int idx = u * 256 + tid;
            int r = idx >> 6;
            int c = (idx & 63) * 4;
            *(float4*)&Vs[r * 256 + c] = *(const float4*)(V + (size_t)(j0 + r) * 256 + c);
        }
        __syncthreads();

        // ---- O += P @ V ----
#pragma unroll 4
        for (int j = 0; j < 64; j++) {
            float a0 = Pt[j * 65 + ty * 4 + 0];
            float a1 = Pt[j * 65 + ty * 4 + 1];
            float a2 = Pt[j * 65 + ty * 4 + 2];
            float a3 = Pt[j * 65 + ty * 4 + 3];
#pragma unroll
            for (int cc = 0; cc < 4; cc++) {
                float4 v4 = *(const float4*)&Vs[j * 256 + cc * 64 + tx * 4];
                acc[0][cc * 4 + 0] += a0 * v4.x; acc[0][cc * 4 + 1] += a0 * v4.y;
                acc[0][cc * 4 + 2] += a0 * v4.z; acc[0][cc * 4 + 3] += a0 * v4.w;
                acc[1][cc * 4 + 0] += a1 * v4.x; acc[1][cc * 4 + 1] += a1 * v4.y;
                acc[1][cc * 4 + 2] += a1 * v4.z; acc[1][cc * 4 + 3] += a1 * v4.w;
                acc[2][cc * 4 + 0] += a2 * v4.x; acc[2][cc * 4 + 1] += a2 * v4.y;
                acc[2][cc * 4 + 2] += a2 * v4.z; acc[2][cc * 4 + 3] += a2 * v4.w;
                acc[3][cc * 4 + 0] += a3 * v4.x; acc[3][cc * 4 + 1] += a3 * v4.y;
                acc[3][cc * 4 + 2] += a3 * v4.z; acc[3][cc * 4 + 3] += a3 * v4.w;
            }
        }
    }

    // ---- epilogue: out = acc / l ----
#pragma unroll
    for (int i = 0; i < 4; i++) {
        float inv = 1.f / lrow[i];
        size_t r = (size_t)(rowBase + ty * 4 + i);
#pragma unroll
        for (int cc = 0; cc < 4; cc++) {
            float4 o;
            o.x = acc[i][cc * 4 + 0] * inv;
            o.y = acc[i][cc * 4 + 1] * inv;
            o.z = acc[i][cc * 4 + 2] * inv;
            o.w = acc[i][cc * 4 + 3] * inv;
            *(float4*)(O + r * 256 + cc * 64 + tx * 4) = o;
        }
    }
}

// ---------------- out += outS ----------------
__global__ __launch_bounds__(256) void add_out(float* __restrict__ out) {
    int i = (blockIdx.x * 256 + threadIdx.x) * 4;
    float4 a = *(float4*)(out + i);
    const float4 b = *(const float4*)(g_OutS + i);
    a.x += b.x; a.y += b.y; a.z += b.z; a.w += b.w;
    *(float4*)(out + i) = a;
}

// ---------------- launch ----------------
extern "C" void kernel_launch(void* const* d_in, const int* in_sizes, int n_in,
                              void* d_out, int out_size) {
    const float* x    = (const float*)d_in[0];
    const float* chm  = (const float*)d_in[1];
    const float* chwq = (const float*)d_in[2];
    const float* chwk = (const float*)d_in[3];
    const float* chwv = (const float*)d_in[4];
    const float* spm  = (const float*)d_in[5];
    const float* spwq = (const float*)d_in[6];
    const float* spwk = (const float*)d_in[7];
    const float* spwv = (const float*)d_in[8];
    float* out = (float*)d_out;

    // Device-global scratch is referenced directly by symbol inside kernels;
    // we only need raw pointers for gemm outputs. Use static one-time lookup
    // pattern is forbidden (determinism), so use cudaGetSymbolAddress each call
    // ONLY for gemm destinations (non-stream API, capture-safe).
    float *Qc, *Qf, *Kc, *Vc, *Kf, *Vf, *qm, *qv, *km, *kv;
    cudaGetSymbolAddress((void**)&Qc, g_Qc);
    cudaGetSymbolAddress((void**)&Qf, g_Qf);
    cudaGetSymbolAddress((void**)&Kc, g_Kc);
    cudaGetSymbolAddress((void**)&Vc, g_Vc);
    cudaGetSymbolAddress((void**)&Kf, g_Kf);
    cudaGetSymbolAddress((void**)&Vf, g_Vf);
    cudaGetSymbolAddress((void**)&qm, g_qm);
    cudaGetSymbolAddress((void**)&qv, g_qv);
    cudaGetSymbolAddress((void**)&km, g_km);
    cudaGetSymbolAddress((void**)&kv, g_kv);

    const int smemBytes = SMEM_FLOATS * (int)sizeof(float);
    cudaFuncSetAttribute(attn, cudaFuncAttributeMaxDynamicSharedMemorySize, smemBytes);

    dim3 gq(NB / 64, 4), gm(MTOT / 64, 4);
    gemm_nt<<<gq, 256>>>(x, chwq, Qc);
    gemm_nt<<<gq, 256>>>(x, spwq, Qf);
    gemm_nt<<<gm, 256>>>(chm, chwk, Kc);
    gemm_nt<<<gm, 256>>>(chm, chwv, Vc);
    gemm_nt<<<gm, 256>>>(spm, spwk, Kf);
    gemm_nt<<<gm, 256>>>(spm, spwv, Vf);

    row_stats<<<NB / 8, 256>>>(Qf, qm, qv);
    row_stats<<<MTOT / 8, 256>>>(Kf, km, kv);

    attn<<<dim3(NB / 64, 2), 256, smemBytes>>>(out);

    add_out<<<NB * DDIM / 1024, 256>>>(out);
}

// round 4
// speedup vs baseline: 2.2811x; 2.2811x over previous
#include <cuda_runtime.h>
#include <cuda_bf16.h>
#include <cstdint>

#define NB   12544
#define MTOT 2048
#define DDIM 256

// ---------------- scratch ----------------
__device__ __nv_bfloat16 g_Qc_hi[NB * DDIM], g_Qc_lo[NB * DDIM];
__device__ __nv_bfloat16 g_Qf_hi[NB * DDIM], g_Qf_lo[NB * DDIM];
__device__ __nv_bfloat16 g_Kc_hi[MTOT * DDIM], g_Kc_lo[MTOT * DDIM];
__device__ __nv_bfloat16 g_Kf_hi[MTOT * DDIM], g_Kf_lo[MTOT * DDIM];
__device__ __nv_bfloat16 g_Vtc_hi[DDIM * MTOT], g_Vtc_lo[DDIM * MTOT];
__device__ __nv_bfloat16 g_Vtf_hi[DDIM * MTOT], g_Vtf_lo[DDIM * MTOT];
__device__ float g_S0[(size_t)NB * MTOT];
__device__ float g_S1[(size_t)NB * MTOT];
__device__ __nv_bfloat16 g_Ph0[(size_t)NB * MTOT], g_Pl0[(size_t)NB * MTOT];
__device__ __nv_bfloat16 g_Ph1[(size_t)NB * MTOT], g_Pl1[(size_t)NB * MTOT];
__device__ float g_qm[NB], g_qv[NB], g_km[MTOT], g_kv[MTOT];
__device__ float g_OutS[NB * DDIM];

// ---------------- helpers ----------------
__device__ __forceinline__ uint32_t smem_u32(const void* p) {
    uint32_t a;
    asm("{ .reg .u64 t; cvta.to.shared.u64 t, %1; cvt.u32.u64 %0, t; }" : "=r"(a) : "l"(p));
    return a;
}
#define SWZ(o) ((o) ^ (((o) >> 3) & 0x70))

__device__ __forceinline__ void mma16816(float* c, const uint32_t* a, const uint32_t* b) {
    asm volatile(
        "mma.sync.aligned.m16n8k16.row.col.f32.bf16.bf16.f32 "
        "{%0,%1,%2,%3}, {%4,%5,%6,%7}, {%8,%9}, {%0,%1,%2,%3};"
        : "+f"(c[0]), "+f"(c[1]), "+f"(c[2]), "+f"(c[3])
        : "r"(a[0]), "r"(a[1]), "r"(a[2]), "r"(a[3]), "r"(b[0]), "r"(b[1]));
}
__device__ __forceinline__ void ldsm_x4(uint32_t* r, uint32_t addr) {
    asm volatile("ldmatrix.sync.aligned.m8n8.x4.shared.b16 {%0,%1,%2,%3}, [%4];"
                 : "=r"(r[0]), "=r"(r[1]), "=r"(r[2]), "=r"(r[3]) : "r"(addr));
}
__device__ __forceinline__ void ldsm_x2(uint32_t* r, uint32_t addr) {
    asm volatile("ldmatrix.sync.aligned.m8n8.x2.shared.b16 {%0,%1}, [%2];"
                 : "=r"(r[0]), "=r"(r[1]) : "r"(addr));
}

// ---------------- projection GEMM: C = A @ W^T -> bf16 hi/lo ----------------
__global__ __launch_bounds__(256) void gemm_hl(const float* __restrict__ A,
                                               const float* __restrict__ W,
                                               __nv_bfloat16* __restrict__ Ch,
                                               __nv_bfloat16* __restrict__ Cl) {
    __shared__ float As[16][68];
    __shared__ float Ws[16][68];
    const int tid = threadIdx.x;
    const int tx = tid & 15, ty = tid >> 4;
    const int bm = blockIdx.x * 64, bn = blockIdx.y * 64;
    const int lr = tid >> 2, lk = (tid & 3) * 4;

    float acc[4][4];
#pragma unroll
    for (int i = 0; i < 4; i++)
#pragma unroll
        for (int j = 0; j < 4; j++) acc[i][j] = 0.f;

    for (int k0 = 0; k0 < 256; k0 += 16) {
        float4 av = *(const float4*)(A + (size_t)(bm + lr) * 256 + k0 + lk);
        float4 wv = *(const float4*)(W + (size_t)(bn + lr) * 256 + k0 + lk);
        As[lk + 0][lr] = av.x; As[lk + 1][lr] = av.y; As[lk + 2][lr] = av.z; As[lk + 3][lr] = av.w;
        Ws[lk + 0][lr] = wv.x; Ws[lk + 1][lr] = wv.y; Ws[lk + 2][lr] = wv.z; Ws[lk + 3][lr] = wv.w;
        __syncthreads();
#pragma unroll
        for (int k = 0; k < 16; k++) {
            float4 a = *(const float4*)&As[k][ty * 4];
            float4 b = *(const float4*)&Ws[k][tx * 4];
            acc[0][0] += a.x * b.x; acc[0][1] += a.x * b.y; acc[0][2] += a.x * b.z; acc[0][3] += a.x * b.w;
            acc[1][0] += a.y * b.x; acc[1][1] += a.y * b.y; acc[1][2] += a.y * b.z; acc[1][3] += a.y * b.w;
            acc[2][0] += a.z * b.x; acc[2][1] += a.z * b.y; acc[2][2] += a.z * b.z; acc[2][3] += a.z * b.w;
            acc[3][0] += a.w * b.x; acc[3][1] += a.w * b.y; acc[3][2] += a.w * b.z; acc[3][3] += a.w * b.w;
        }
        __syncthreads();
    }
#pragma unroll
    for (int i = 0; i < 4; i++) {
        size_t off = (size_t)(bm + ty * 4 + i) * 256 + bn + tx * 4;
        __nv_bfloat162 h01, h23, l01, l23;
#pragma unroll
        for (int j = 0; j < 4; j++) {
            float a = acc[i][j];
            __nv_bfloat16 h = __float2bfloat16(a);
            __nv_bfloat16 l = __float2bfloat16(a - __bfloat162float(h));
            if (j == 0) { h01.x = h; l01.x = l; }
            if (j == 1) { h01.y = h; l01.y = l; }
            if (j == 2) { h23.x = h; l23.x = l; }
            if (j == 3) { h23.y = h; l23.y = l; }
        }
        *(__nv_bfloat162*)(Ch + off) = h01; *(__nv_bfloat162*)(Ch + off + 2) = h23;
        *(__nv_bfloat162*)(Cl + off) = l01; *(__nv_bfloat162*)(Cl + off + 2) = l23;
    }
}

// ---------------- projection GEMM, transposed hi/lo output [256][2048] ----------------
__global__ __launch_bounds__(256) void gemm_hlT(const float* __restrict__ A,
                                                const float* __restrict__ W,
                                                __nv_bfloat16* __restrict__ Th,
                                                __nv_bfloat16* __restrict__ Tl) {
    __shared__ float As[16][68];
    __shared__ float Ws[16][68];
    const int tid = threadIdx.x;
    const int tx = tid & 15, ty = tid >> 4;
    const int bm = blockIdx.x * 64, bn = blockIdx.y * 64;
    const int lr = tid >> 2, lk = (tid & 3) * 4;

    float acc[4][4];
#pragma unroll
    for (int i = 0; i < 4; i++)
#pragma unroll
        for (int j = 0; j < 4; j++) acc[i][j] = 0.f;

    for (int k0 = 0; k0 < 256; k0 += 16) {
        float4 av = *(const float4*)(A + (size_t)(bm + lr) * 256 + k0 + lk);
        float4 wv = *(const float4*)(W + (size_t)(bn + lr) * 256 + k0 + lk);
        As[lk + 0][lr] = av.x; As[lk + 1][lr] = av.y; As[lk + 2][lr] = av.z; As[lk + 3][lr] = av.w;
        Ws[lk + 0][lr] = wv.x; Ws[lk + 1][lr] = wv.y; Ws[lk + 2][lr] = wv.z; Ws[lk + 3][lr] = wv.w;
        __syncthreads();
#pragma unroll
        for (int k = 0; k < 16; k++) {
            float4 a = *(const float4*)&As[k][ty * 4];
            float4 b = *(const float4*)&Ws[k][tx * 4];
            acc[0][0] += a.x * b.x; acc[0][1] += a.x * b.y; acc[0][2] += a.x * b.z; acc[0][3] += a.x * b.w;
            acc[1][0] += a.y * b.x; acc[1][1] += a.y * b.y; acc[1][2] += a.y * b.z; acc[1][3] += a.y * b.w;
            acc[2][0] += a.z * b.x; acc[2][1] += a.z * b.y; acc[2][2] += a.z * b.z; acc[2][3] += a.z * b.w;
            acc[3][0] += a.w * b.x; acc[3][1] += a.w * b.y; acc[3][2] += a.w * b.z; acc[3][3] += a.w * b.w;
        }
        __syncthreads();
    }
#pragma unroll
    for (int i = 0; i < 4; i++) {
        int row = bm + ty * 4 + i;
#pragma unroll
        for (int j = 0; j < 4; j++) {
            int col = bn + tx * 4 + j;
            float a = acc[i][j];
            __nv_bfloat16 h = __float2bfloat16(a);
            __nv_bfloat16 l = __float2bfloat16(a - __bfloat162float(h));
            Th[(size_t)col * MTOT + row] = h;
            Tl[(size_t)col * MTOT + row] = l;
        }
    }
}

// ---------------- per-row mean/var from hi/lo ----------------
__global__ __launch_bounds__(256) void row_stats_hl(const __nv_bfloat16* __restrict__ Xh,
                                                    const __nv_bfloat16* __restrict__ Xl,
                                                    float* __restrict__ mean,
                                                    float* __restrict__ var) {
    const int row = blockIdx.x * 8 + (threadIdx.x >> 5);
    const int lane = threadIdx.x & 31;
    const size_t base = (size_t)row * 256;
    float s = 0.f, ss = 0.f;
#pragma unroll
    for (int c = 0; c < 256; c += 32) {
        float v = __bfloat162float(Xh[base + c + lane]) + __bfloat162float(Xl[base + c + lane]);
        s += v; ss += v * v;
    }
#pragma unroll
    for (int o = 16; o > 0; o >>= 1) {
        s += __shfl_xor_sync(0xffffffffu, s, o);
        ss += __shfl_xor_sync(0xffffffffu, ss, o);
    }
    if (lane == 0) {
        float m = s * (1.f / 256.f);
        mean[row] = m;
        var[row] = (ss - 256.f * m * m) * (1.f / 255.f);
    }
}

// ---------------- generic split-bf16 MMA GEMM ----------------
// C[M,N] = (Ah+Al)[M,K] @ (Bh+Bl)[N,K]^T  (dropping Al*Bl)
// CTA tile 128x128, 8 warps (4 row x 2 col), warp tile 32x64.
// K consumed in chunks of 64. smem = 4 * 16KB = 64KB.
// mode 0: C *= 1/16 (channel scores). mode 1: SSIM transform. mode 2: plain (PV).
#define OFF_AH 0
#define OFF_AL 16384
#define OFF_BH 32768
#define OFF_BL 49152
#define MM_SMEM 65536

__global__ __launch_bounds__(256, 2) void mma_gemm(
    const __nv_bfloat16* __restrict__ Ah, const __nv_bfloat16* __restrict__ Al,
    const __nv_bfloat16* __restrict__ Bh, const __nv_bfloat16* __restrict__ Bl,
    float* __restrict__ C, int Klen, int ldc, int mode,
    const float* __restrict__ qm, const float* __restrict__ qv,
    const float* __restrict__ km, const float* __restrict__ kv) {
    extern __shared__ char sm[];
    const uint32_t sb = smem_u32(sm);
    const int tid = threadIdx.x;
    const int wid = tid >> 5, lane = tid & 31;
    const int wm = wid & 3, wn = wid >> 2;          // warp row/col
    const int mBase = blockIdx.x * 128;
    const int nBase = blockIdx.y * 128;

    float acc[2][8][4];
#pragma unroll
    for (int rf = 0; rf < 2; rf++)
#pragma unroll
        for (int nt = 0; nt < 8; nt++)
#pragma unroll
            for (int c = 0; c < 4; c++) acc[rf][nt][c] = 0.f;

    // ldmatrix lane addressing (constant per thread)
    const int a_row = wm * 32 + (lane & 15);        // + rf*16
    const int a_kb  = (lane >> 4) * 16;             // bytes within 32B kstep block
    const int b_row = wn * 64 + (lane & 7);         // + nt*8
    const int b_kb  = ((lane >> 3) & 1) * 16;

#pragma unroll 1
    for (int k0 = 0; k0 < Klen; k0 += 64) {
        __syncthreads();
        // load A chunk [128][64] hi/lo and B chunk [128][64] hi/lo
#pragma unroll
        for (int u = 0; u < 4; u++) {
            int idx = u * 256 + tid;
            int r = idx >> 3, g = idx & 7;
            uint32_t sw = SWZ(r * 128 + g * 16);
            size_t ga = (size_t)(mBase + r) * Klen + k0 + g * 8;
            size_t gb = (size_t)(nBase + r) * Klen + k0 + g * 8;
            *(uint4*)(sm + OFF_AH + sw) = *(const uint4*)(Ah + ga);
            *(uint4*)(sm + OFF_AL + sw) = *(const uint4*)(Al + ga);
            *(uint4*)(sm + OFF_BH + sw) = *(const uint4*)(Bh + gb);
            *(uint4*)(sm + OFF_BL + sw) = *(const uint4*)(Bl + gb);
        }
        __syncthreads();

#pragma unroll
        for (int ks = 0; ks < 4; ks++) {
            uint32_t ah[2][4], al[2][4];
#pragma unroll
            for (int rf = 0; rf < 2; rf++) {
                uint32_t off = SWZ((a_row + rf * 16) * 128 + ks * 32 + a_kb);
                ldsm_x4(ah[rf], sb + OFF_AH + off);
                ldsm_x4(al[rf], sb + OFF_AL + off);
            }
#pragma unroll
            for (int nt = 0; nt < 8; nt++) {
                uint32_t off = SWZ((b_row + nt * 8) * 128 + ks * 32 + b_kb);
                uint32_t bh[2], bl[2];
                ldsm_x2(bh, sb + OFF_BH + off);
                ldsm_x2(bl, sb + OFF_BL + off);
#pragma unroll
                for (int rf = 0; rf < 2; rf++) {
                    mma16816(acc[rf][nt], ah[rf], bh);
                    mma16816(acc[rf][nt], ah[rf], bl);
                    mma16816(acc[rf][nt], al[rf], bh);
                }
            }
        }
    }

    // ---- epilogue ----
    const int gID = lane >> 2, tig = lane & 3;
#pragma unroll
    for (int rf = 0; rf < 2; rf++) {
        int r0 = mBase + wm * 32 + rf * 16 + gID;
        int r1 = r0 + 8;
        float qm0 = 0.f, qv0 = 0.f, qm1 = 0.f, qv1 = 0.f;
        if (mode == 1) {
            qm0 = qm[r0]; qv0 = qv[r0];
            qm1 = qm[r1]; qv1 = qv[r1];
        }
#pragma unroll
        for (int nt = 0; nt < 8; nt++) {
            int col = nBase + wn * 64 + nt * 8 + tig * 2;
            float v0 = acc[rf][nt][0], v1 = acc[rf][nt][1];
            float v2 = acc[rf][nt][2], v3 = acc[rf][nt][3];
            if (mode == 0) {
                v0 *= 0.0625f; v1 *= 0.0625f; v2 *= 0.0625f; v3 *= 0.0625f;
            } else if (mode == 1) {
                float km0 = km[col], kv0 = kv[col];
                float km1 = km[col + 1], kv1 = kv[col + 1];
#define SSIM(dot, QM, QV, KM, KV)                                              \
    ({ float mp = (QM) * (KM);                                                 \
       float cov = ((dot) - 256.f * mp) * (1.f / 255.f);                       \
       float num = (2.f * mp + 0.01f) * (2.f * cov + 0.03f);                   \
       float den = ((QM) * (QM) + (KM) * (KM) + 0.01f) * ((QV) + (KV) + 0.03f);\
       num / (den + 1e-8f); })
                v0 = SSIM(v0, qm0, qv0, km0, kv0);
                v1 = SSIM(v1, qm0, qv0, km1, kv1);
                v2 = SSIM(v2, qm1, qv1, km0, kv0);
                v3 = SSIM(v3, qm1, qv1, km1, kv1);
            }
            *(float2*)(C + (size_t)r0 * ldc + col) = make_float2(v0, v1);
            *(float2*)(C + (size_t)r1 * ldc + col) = make_float2(v2, v3);
        }
    }
}

// ---------------- row softmax -> P hi/lo bf16 ----------------
__global__ __launch_bounds__(256) void softmax_rows(const float* __restrict__ S,
                                                    __nv_bfloat16* __restrict__ Ph,
                                                    __nv_bfloat16* __restrict__ Pl) {
    __shared__ float red[8];
    const int tid = threadIdx.x;
    const int wid = tid >> 5, lane = tid & 31;
    const size_t row = blockIdx.x;
    const float4* Sr = (const float4*)(S + row * 2048);
    float4 v0 = Sr[tid];
    float4 v1 = Sr[tid + 256];

    float m = fmaxf(fmaxf(fmaxf(v0.x, v0.y), fmaxf(v0.z, v0.w)),
                    fmaxf(fmaxf(v1.x, v1.y), fmaxf(v1.z, v1.w)));
#pragma unroll
    for (int o = 16; o > 0; o >>= 1) m = fmaxf(m, __shfl_xor_sync(0xffffffffu, m, o));
    if (lane == 0) red[wid] = m;
    __syncthreads();
    m = red[0];
#pragma unroll
    for (int w = 1; w < 8; w++) m = fmaxf(m, red[w]);
    __syncthreads();

    float e[8];
    e[0] = __expf(v0.x - m); e[1] = __expf(v0.y - m); e[2] = __expf(v0.z - m); e[3] = __expf(v0.w - m);
    e[4] = __expf(v1.x - m); e[5] = __expf(v1.y - m); e[6] = __expf(v1.z - m); e[7] = __expf(v1.w - m);
    float s = e[0] + e[1] + e[2] + e[3] + e[4] + e[5] + e[6] + e[7];
#pragma unroll
    for (int o = 16; o > 0; o >>= 1) s += __shfl_xor_sync(0xffffffffu, s, o);
    if (lane == 0) red[wid] = s;
    __syncthreads();
    s = red[0] + red[1] + red[2] + red[3] + red[4] + red[5] + red[6] + red[7];
    float inv = 1.f / s;

    __nv_bfloat16* PhR = Ph + row * 2048;
    __nv_bfloat16* PlR = Pl + row * 2048;
#pragma unroll
    for (int g = 0; g < 2; g++) {
        __nv_bfloat162 h01, h23, l01, l23;
#pragma unroll
        for (int j = 0; j < 4; j++) {
            float p = e[g * 4 + j] * inv;
            __nv_bfloat16 h = __float2bfloat16(p);
            __nv_bfloat16 l = __float2bfloat16(p - __bfloat162float(h));
            if (j == 0) { h01.x = h; l01.x = l; }
            if (j == 1) { h01.y = h; l01.y = l; }
            if (j == 2) { h23.x = h; l23.x = l; }
            if (j == 3) { h23.y = h; l23.y = l; }
        }
        int col = 4 * (tid + g * 256);
        *(__nv_bfloat162*)(PhR + col) = h01; *(__nv_bfloat162*)(PhR + col + 2) = h23;
        *(__nv_bfloat162*)(PlR + col) = l01; *(__nv_bfloat162*)(PlR + col + 2) = l23;
    }
}

// ---------------- out += outS ----------------
__global__ __launch_bounds__(256) void add_out(float* __restrict__ out,
                                               const float* __restrict__ add) {
    int i = (blockIdx.x * 256 + threadIdx.x) * 4;
    float4 a = *(float4*)(out + i);
    float4 b = *(const float4*)(add + i);
    a.x += b.x; a.y += b.y; a.z += b.z; a.w += b.w;
    *(float4*)(out + i) = a;
}

// ---------------- launch ----------------
extern "C" void kernel_launch(void* const* d_in, const int* in_sizes, int n_in,
                              void* d_out, int out_size) {
    const float* x    = (const float*)d_in[0];
    const float* chm  = (const float*)d_in[1];
    const float* chwq = (const float*)d_in[2];
    const float* chwk = (const float*)d_in[3];
    const float* chwv = (const float*)d_in[4];
    const float* spm  = (const float*)d_in[5];
    const float* spwq = (const float*)d_in[6];
    const float* spwk = (const float*)d_in[7];
    const float* spwv = (const float*)d_in[8];
    float* out = (float*)d_out;

    __nv_bfloat16 *Qch, *Qcl, *Qfh, *Qfl, *Kch, *Kcl, *Kfh, *Kfl;
    __nv_bfloat16 *Vtch, *Vtcl, *Vtfh, *Vtfl, *Ph0, *Pl0, *Ph1, *Pl1;
    float *S0, *S1, *qm, *qv, *km, *kv, *outS;
    cudaGetSymbolAddress((void**)&Qch, g_Qc_hi);  cudaGetSymbolAddress((void**)&Qcl, g_Qc_lo);
    cudaGetSymbolAddress((void**)&Qfh, g_Qf_hi);  cudaGetSymbolAddress((void**)&Qfl, g_Qf_lo);
    cudaGetSymbolAddress((void**)&Kch, g_Kc_hi);  cudaGetSymbolAddress((void**)&Kcl, g_Kc_lo);
    cudaGetSymbolAddress((void**)&Kfh, g_Kf_hi);  cudaGetSymbolAddress((void**)&Kfl, g_Kf_lo);
    cudaGetSymbolAddress((void**)&Vtch, g_Vtc_hi); cudaGetSymbolAddress((void**)&Vtcl, g_Vtc_lo);
    cudaGetSymbolAddress((void**)&Vtfh, g_Vtf_hi); cudaGetSymbolAddress((void**)&Vtfl, g_Vtf_lo);
    cudaGetSymbolAddress((void**)&Ph0, g_Ph0);    cudaGetSymbolAddress((void**)&Pl0, g_Pl0);
    cudaGetSymbolAddress((void**)&Ph1, g_Ph1);    cudaGetSymbolAddress((void**)&Pl1, g_Pl1);
    cudaGetSymbolAddress((void**)&S0, g_S0);      cudaGetSymbolAddress((void**)&S1, g_S1);
    cudaGetSymbolAddress((void**)&qm, g_qm);      cudaGetSymbolAddress((void**)&qv, g_qv);
    cudaGetSymbolAddress((void**)&km, g_km);      cudaGetSymbolAddress((void**)&kv, g_kv);
    cudaGetSymbolAddress((void**)&outS, g_OutS);

    cudaFuncSetAttribute(mma_gemm, cudaFuncAttributeMaxDynamicSharedMemorySize, MM_SMEM);

    dim3 gq(NB / 64, 4), gm(MTOT / 64, 4);
    gemm_hl<<<gq, 256>>>(x, chwq, Qch, Qcl);
    gemm_hl<<<gq, 256>>>(x, spwq, Qfh, Qfl);
    gemm_hl<<<gm, 256>>>(chm, chwk, Kch, Kcl);
    gemm_hl<<<gm, 256>>>(spm, spwk, Kfh, Kfl);
    gemm_hlT<<<gm, 256>>>(chm, chwv, Vtch, Vtcl);
    gemm_hlT<<<gm, 256>>>(spm, spwv, Vtfh, Vtfl);

    row_stats_hl<<<NB / 8, 256>>>(Qfh, Qfl, qm, qv);
    row_stats_hl<<<MTOT / 8, 256>>>(Kfh, Kfl, km, kv);

    dim3 gs(NB / 128, MTOT / 128);
    mma_gemm<<<gs, 256, MM_SMEM>>>(Qch, Qcl, Kch, Kcl, S0, 256, 2048, 0, qm, qv, km, kv);
    mma_gemm<<<gs, 256, MM_SMEM>>>(Qfh, Qfl, Kfh, Kfl, S1, 256, 2048, 1, qm, qv, km, kv);

    softmax_rows<<<NB, 256>>>(S0, Ph0, Pl0);
    softmax_rows<<<NB, 256>>>(S1, Ph1, Pl1);

    dim3 gp(NB / 128, DDIM / 128);
    mma_gemm<<<gp, 256, MM_SMEM>>>(Ph0, Pl0, Vtch, Vtcl, out, 2048, 256, 2, qm, qv, km, kv);
    mma_gemm<<<gp, 256, MM_SMEM>>>(Ph1, Pl1, Vtfh, Vtfl, outS, 2048, 256, 2, qm, qv, km, kv);

    add_out<<<NB * DDIM / 1024, 256>>>(out, outS);
}

// round 5
// speedup vs baseline: 2.3942x; 1.0496x over previous
#include <cuda_runtime.h>
#include <cuda_bf16.h>
#include <cstdint>

#define NB   12544
#define MTOT 2048
#define DDIM 256

// ---------------- scratch ----------------
__device__ __nv_bfloat16 g_Qc_hi[NB * DDIM], g_Qc_lo[NB * DDIM];
__device__ __nv_bfloat16 g_Qf_hi[NB * DDIM], g_Qf_lo[NB * DDIM];
__device__ __nv_bfloat16 g_Kc_hi[MTOT * DDIM], g_Kc_lo[MTOT * DDIM];
__device__ __nv_bfloat16 g_Kf_hi[MTOT * DDIM], g_Kf_lo[MTOT * DDIM];
__device__ __nv_bfloat16 g_Vtc_hi[DDIM * MTOT], g_Vtc_lo[DDIM * MTOT];
__device__ __nv_bfloat16 g_Vtf_hi[DDIM * MTOT], g_Vtf_lo[DDIM * MTOT];
__device__ __nv_bfloat16 g_Ph0[(size_t)NB * MTOT], g_Pl0[(size_t)NB * MTOT];
__device__ __nv_bfloat16 g_Ph1[(size_t)NB * MTOT], g_Pl1[(size_t)NB * MTOT];
__device__ float g_psum0[NB * 16], g_psum1[NB * 16];
__device__ float g_linv0[NB], g_linv1[NB];
__device__ float g_qm[NB], g_qv[NB], g_km[MTOT], g_kv[MTOT];
__device__ float g_OutS[NB * DDIM];

// ---------------- helpers ----------------
__device__ __forceinline__ uint32_t smem_u32(const void* p) {
    uint32_t a;
    asm("{ .reg .u64 t; cvta.to.shared.u64 t, %1; cvt.u32.u64 %0, t; }" : "=r"(a) : "l"(p));
    return a;
}
#define SWZ(o) ((o) ^ (((o) >> 3) & 0x70))

__device__ __forceinline__ void mma16816(float* c, const uint32_t* a, const uint32_t* b) {
    asm volatile(
        "mma.sync.aligned.m16n8k16.row.col.f32.bf16.bf16.f32 "
        "{%0,%1,%2,%3}, {%4,%5,%6,%7}, {%8,%9}, {%0,%1,%2,%3};"
        : "+f"(c[0]), "+f"(c[1]), "+f"(c[2]), "+f"(c[3])
        : "r"(a[0]), "r"(a[1]), "r"(a[2]), "r"(a[3]), "r"(b[0]), "r"(b[1]));
}
__device__ __forceinline__ void ldsm_x4(uint32_t* r, uint32_t addr) {
    asm volatile("ldmatrix.sync.aligned.m8n8.x4.shared.b16 {%0,%1,%2,%3}, [%4];"
                 : "=r"(r[0]), "=r"(r[1]), "=r"(r[2]), "=r"(r[3]) : "r"(addr));
}
__device__ __forceinline__ void ldsm_x2(uint32_t* r, uint32_t addr) {
    asm volatile("ldmatrix.sync.aligned.m8n8.x2.shared.b16 {%0,%1}, [%2];"
                 : "=r"(r[0]), "=r"(r[1]) : "r"(addr));
}

// ---------------- projection GEMM: C = A @ W^T -> bf16 hi/lo ----------------
__global__ __launch_bounds__(256) void gemm_hl(const float* __restrict__ A,
                                               const float* __restrict__ W,
                                               __nv_bfloat16* __restrict__ Ch,
                                               __nv_bfloat16* __restrict__ Cl) {
    __shared__ float As[16][68];
    __shared__ float Ws[16][68];
    const int tid = threadIdx.x;
    const int tx = tid & 15, ty = tid >> 4;
    const int bm = blockIdx.x * 64, bn = blockIdx.y * 64;
    const int lr = tid >> 2, lk = (tid & 3) * 4;

    float acc[4][4];
#pragma unroll
    for (int i = 0; i < 4; i++)
#pragma unroll
        for (int j = 0; j < 4; j++) acc[i][j] = 0.f;

    for (int k0 = 0; k0 < 256; k0 += 16) {
        float4 av = *(const float4*)(A + (size_t)(bm + lr) * 256 + k0 + lk);
        float4 wv = *(const float4*)(W + (size_t)(bn + lr) * 256 + k0 + lk);
        As[lk + 0][lr] = av.x; As[lk + 1][lr] = av.y; As[lk + 2][lr] = av.z; As[lk + 3][lr] = av.w;
        Ws[lk + 0][lr] = wv.x; Ws[lk + 1][lr] = wv.y; Ws[lk + 2][lr] = wv.z; Ws[lk + 3][lr] = wv.w;
        __syncthreads();
#pragma unroll
        for (int k = 0; k < 16; k++) {
            float4 a = *(const float4*)&As[k][ty * 4];
            float4 b = *(const float4*)&Ws[k][tx * 4];
            acc[0][0] += a.x * b.x; acc[0][1] += a.x * b.y; acc[0][2] += a.x * b.z; acc[0][3] += a.x * b.w;
            acc[1][0] += a.y * b.x; acc[1][1] += a.y * b.y; acc[1][2] += a.y * b.z; acc[1][3] += a.y * b.w;
            acc[2][0] += a.z * b.x; acc[2][1] += a.z * b.y; acc[2][2] += a.z * b.z; acc[2][3] += a.z * b.w;
            acc[3][0] += a.w * b.x; acc[3][1] += a.w * b.y; acc[3][2] += a.w * b.z; acc[3][3] += a.w * b.w;
        }
        __syncthreads();
    }
#pragma unroll
    for (int i = 0; i < 4; i++) {
        size_t off = (size_t)(bm + ty * 4 + i) * 256 + bn + tx * 4;
        __nv_bfloat162 h01, h23, l01, l23;
#pragma unroll
        for (int j = 0; j < 4; j++) {
            float a = acc[i][j];
            __nv_bfloat16 h = __float2bfloat16(a);
            __nv_bfloat16 l = __float2bfloat16(a - __bfloat162float(h));
            if (j == 0) { h01.x = h; l01.x = l; }
            if (j == 1) { h01.y = h; l01.y = l; }
            if (j == 2) { h23.x = h; l23.x = l; }
            if (j == 3) { h23.y = h; l23.y = l; }
        }
        *(__nv_bfloat162*)(Ch + off) = h01; *(__nv_bfloat162*)(Ch + off + 2) = h23;
        *(__nv_bfloat162*)(Cl + off) = l01; *(__nv_bfloat162*)(Cl + off + 2) = l23;
    }
}

// ---------------- projection GEMM, transposed hi/lo output [256][2048] ----------------
__global__ __launch_bounds__(256) void gemm_hlT(const float* __restrict__ A,
                                                const float* __restrict__ W,
                                                __nv_bfloat16* __restrict__ Th,
                                                __nv_bfloat16* __restrict__ Tl) {
    __shared__ float As[16][68];
    __shared__ float Ws[16][68];
    const int tid = threadIdx.x;
    const int tx = tid & 15, ty = tid >> 4;
    const int bm = blockIdx.x * 64, bn = blockIdx.y * 64;
    const int lr = tid >> 2, lk = (tid & 3) * 4;

    float acc[4][4];
#pragma unroll
    for (int i = 0; i < 4; i++)
#pragma unroll
        for (int j = 0; j < 4; j++) acc[i][j] = 0.f;

    for (int k0 = 0; k0 < 256; k0 += 16) {
        float4 av = *(const float4*)(A + (size_t)(bm + lr) * 256 + k0 + lk);
        float4 wv = *(const float4*)(W + (size_t)(bn + lr) * 256 + k0 + lk);
        As[lk + 0][lr] = av.x; As[lk + 1][lr] = av.y; As[lk + 2][lr] = av.z; As[lk + 3][lr] = av.w;
        Ws[lk + 0][lr] = wv.x; Ws[lk + 1][lr] = wv.y; Ws[lk + 2][lr] = wv.z; Ws[lk + 3][lr] = wv.w;
        __syncthreads();
#pragma unroll
        for (int k = 0; k < 16; k++) {
            float4 a = *(const float4*)&As[k][ty * 4];
            float4 b = *(const float4*)&Ws[k][tx * 4];
            acc[0][0] += a.x * b.x; acc[0][1] += a.x * b.y; acc[0][2] += a.x * b.z; acc[0][3] += a.x * b.w;
            acc[1][0] += a.y * b.x; acc[1][1] += a.y * b.y; acc[1][2] += a.y * b.z; acc[1][3] += a.y * b.w;
            acc[2][0] += a.z * b.x; acc[2][1] += a.z * b.y; acc[2][2] += a.z * b.z; acc[2][3] += a.z * b.w;
            acc[3][0] += a.w * b.x; acc[3][1] += a.w * b.y; acc[3][2] += a.w * b.z; acc[3][3] += a.w * b.w;
        }
        __syncthreads();
    }
#pragma unroll
    for (int i = 0; i < 4; i++) {
        int row = bm + ty * 4 + i;
#pragma unroll
        for (int j = 0; j < 4; j++) {
            int col = bn + tx * 4 + j;
            float a = acc[i][j];
            __nv_bfloat16 h = __float2bfloat16(a);
            __nv_bfloat16 l = __float2bfloat16(a - __bfloat162float(h));
            Th[(size_t)col * MTOT + row] = h;
            Tl[(size_t)col * MTOT + row] = l;
        }
    }
}

// ---------------- per-row mean/var from hi/lo ----------------
__global__ __launch_bounds__(256) void row_stats_hl(const __nv_bfloat16* __restrict__ Xh,
                                                    const __nv_bfloat16* __restrict__ Xl,
                                                    float* __restrict__ mean,
                                                    float* __restrict__ var) {
    const int row = blockIdx.x * 8 + (threadIdx.x >> 5);
    const int lane = threadIdx.x & 31;
    const size_t base = (size_t)row * 256;
    float s = 0.f, ss = 0.f;
#pragma unroll
    for (int c = 0; c < 256; c += 32) {
        float v = __bfloat162float(Xh[base + c + lane]) + __bfloat162float(Xl[base + c + lane]);
        s += v; ss += v * v;
    }
#pragma unroll
    for (int o = 16; o > 0; o >>= 1) {
        s += __shfl_xor_sync(0xffffffffu, s, o);
        ss += __shfl_xor_sync(0xffffffffu, ss, o);
    }
    if (lane == 0) {
        float m = s * (1.f / 256.f);
        mean[row] = m;
        var[row] = (ss - 256.f * m * m) * (1.f / 255.f);
    }
}

// ---------------- generic split-bf16 MMA GEMM ----------------
// mode 0: channel scores -> exp(dot/16) -> P hi/lo + row partial sums
// mode 1: spatial SSIM   -> exp(ssim)   -> P hi/lo + row partial sums
// mode 2: PV             -> C = acc * linv[row]
#define OFF_AH 0
#define OFF_AL 16384
#define OFF_BH 32768
#define OFF_BL 49152
#define MM_SMEM 65536

__global__ __launch_bounds__(256, 2) void mma_gemm(
    const __nv_bfloat16* __restrict__ Ah, const __nv_bfloat16* __restrict__ Al,
    const __nv_bfloat16* __restrict__ Bh, const __nv_bfloat16* __restrict__ Bl,
    float* __restrict__ C,
    __nv_bfloat16* __restrict__ Ph, __nv_bfloat16* __restrict__ Pl,
    float* __restrict__ psum, const float* __restrict__ linv,
    int Klen, int ldc, int mode,
    const float* __restrict__ qm, const float* __restrict__ qv,
    const float* __restrict__ km, const float* __restrict__ kv) {
    extern __shared__ char sm[];
    const uint32_t sb = smem_u32(sm);
    const int tid = threadIdx.x;
    const int wid = tid >> 5, lane = tid & 31;
    const int wm = wid & 3, wn = wid >> 2;
    const int mBase = blockIdx.x * 128;
    const int nBase = blockIdx.y * 128;

    float acc[2][8][4];
#pragma unroll
    for (int rf = 0; rf < 2; rf++)
#pragma unroll
        for (int nt = 0; nt < 8; nt++)
#pragma unroll
            for (int c = 0; c < 4; c++) acc[rf][nt][c] = 0.f;

    const int a_row = wm * 32 + (lane & 15);
    const int a_kb  = (lane >> 4) * 16;
    const int b_row = wn * 64 + (lane & 7);
    const int b_kb  = ((lane >> 3) & 1) * 16;

#pragma unroll 1
    for (int k0 = 0; k0 < Klen; k0 += 64) {
        __syncthreads();
#pragma unroll
        for (int u = 0; u < 4; u++) {
            int idx = u * 256 + tid;
            int r = idx >> 3, g = idx & 7;
            uint32_t sw = SWZ(r * 128 + g * 16);
            size_t ga = (size_t)(mBase + r) * Klen + k0 + g * 8;
            size_t gb = (size_t)(nBase + r) * Klen + k0 + g * 8;
            *(uint4*)(sm + OFF_AH + sw) = *(const uint4*)(Ah + ga);
            *(uint4*)(sm + OFF_AL + sw) = *(const uint4*)(Al + ga);
            *(uint4*)(sm + OFF_BH + sw) = *(const uint4*)(Bh + gb);
            *(uint4*)(sm + OFF_BL + sw) = *(const uint4*)(Bl + gb);
        }
        __syncthreads();

#pragma unroll
        for (int ks = 0; ks < 4; ks++) {
            uint32_t ah[2][4], al[2][4];
#pragma unroll
            for (int rf = 0; rf < 2; rf++) {
                uint32_t off = SWZ((a_row + rf * 16) * 128 + ks * 32 + a_kb);
                ldsm_x4(ah[rf], sb + OFF_AH + off);
                ldsm_x4(al[rf], sb + OFF_AL + off);
            }
#pragma unroll
            for (int nt = 0; nt < 8; nt++) {
                uint32_t off = SWZ((b_row + nt * 8) * 128 + ks * 32 + b_kb);
                uint32_t bh[2], bl[2];
                ldsm_x2(bh, sb + OFF_BH + off);
                ldsm_x2(bl, sb + OFF_BL + off);
#pragma unroll
                for (int rf = 0; rf < 2; rf++) {
                    mma16816(acc[rf][nt], ah[rf], bh);
                    mma16816(acc[rf][nt], ah[rf], bl);
                    mma16816(acc[rf][nt], al[rf], bh);
                }
            }
        }
    }

    // ---- epilogue ----
    const int gID = lane >> 2, tig = lane & 3;

    if (mode == 2) {
#pragma unroll
        for (int rf = 0; rf < 2; rf++) {
            int r0 = mBase + wm * 32 + rf * 16 + gID;
            int r1 = r0 + 8;
            float i0 = linv[r0], i1 = linv[r1];
#pragma unroll
            for (int nt = 0; nt < 8; nt++) {
                int col = nBase + wn * 64 + nt * 8 + tig * 2;
                *(float2*)(C + (size_t)r0 * ldc + col) =
                    make_float2(acc[rf][nt][0] * i0, acc[rf][nt][1] * i0);
                *(float2*)(C + (size_t)r1 * ldc + col) =
                    make_float2(acc[rf][nt][2] * i1, acc[rf][nt][3] * i1);
            }
        }
        return;
    }

    float rs[2][2];
    rs[0][0] = rs[0][1] = rs[1][0] = rs[1][1] = 0.f;

#pragma unroll
    for (int rf = 0; rf < 2; rf++) {
        int r0 = mBase + wm * 32 + rf * 16 + gID;
        int r1 = r0 + 8;
        float qm0 = 0.f, qv0 = 0.f, qm1 = 0.f, qv1 = 0.f;
        if (mode == 1) { qm0 = qm[r0]; qv0 = qv[r0]; qm1 = qm[r1]; qv1 = qv[r1]; }
#pragma unroll
        for (int nt = 0; nt < 8; nt++) {
            int col = nBase + wn * 64 + nt * 8 + tig * 2;
            float v0 = acc[rf][nt][0], v1 = acc[rf][nt][1];
            float v2 = acc[rf][nt][2], v3 = acc[rf][nt][3];
            if (mode == 0) {
                v0 = __expf(v0 * 0.0625f); v1 = __expf(v1 * 0.0625f);
                v2 = __expf(v2 * 0.0625f); v3 = __expf(v3 * 0.0625f);
            } else {
                float km0 = km[col], kv0 = kv[col];
                float km1 = km[col + 1], kv1 = kv[col + 1];
#define SSIM(dot, QM, QV, KM, KV)                                              \
    ({ float mp = (QM) * (KM);                                                 \
       float cov = ((dot) - 256.f * mp) * (1.f / 255.f);                       \
       float num = (2.f * mp + 0.01f) * (2.f * cov + 0.03f);                   \
       float den = ((QM) * (QM) + (KM) * (KM) + 0.01f) * ((QV) + (KV) + 0.03f);\
       num / (den + 1e-8f); })
                v0 = __expf(SSIM(v0, qm0, qv0, km0, kv0));
                v1 = __expf(SSIM(v1, qm0, qv0, km1, kv1));
                v2 = __expf(SSIM(v2, qm1, qv1, km0, kv0));
                v3 = __expf(SSIM(v3, qm1, qv1, km1, kv1));
            }
            rs[rf][0] += v0 + v1;
            rs[rf][1] += v2 + v3;

            __nv_bfloat16 h0 = __float2bfloat16(v0);
            __nv_bfloat16 l0 = __float2bfloat16(v0 - __bfloat162float(h0));
            __nv_bfloat16 h1 = __float2bfloat16(v1);
            __nv_bfloat16 l1 = __float2bfloat16(v1 - __bfloat162float(h1));
            __nv_bfloat16 h2 = __float2bfloat16(v2);
            __nv_bfloat16 l2 = __float2bfloat16(v2 - __bfloat162float(h2));
            __nv_bfloat16 h3 = __float2bfloat16(v3);
            __nv_bfloat16 l3 = __float2bfloat16(v3 - __bfloat162float(h3));
            __nv_bfloat162 hh0; hh0.x = h0; hh0.y = h1;
            __nv_bfloat162 ll0; ll0.x = l0; ll0.y = l1;
            __nv_bfloat162 hh1; hh1.x = h2; hh1.y = h3;
            __nv_bfloat162 ll1; ll1.x = l2; ll1.y = l3;
            *(__nv_bfloat162*)(Ph + (size_t)r0 * 2048 + col) = hh0;
            *(__nv_bfloat162*)(Pl + (size_t)r0 * 2048 + col) = ll0;
            *(__nv_bfloat162*)(Ph + (size_t)r1 * 2048 + col) = hh1;
            *(__nv_bfloat162*)(Pl + (size_t)r1 * 2048 + col) = ll1;
        }
    }

    // reduce row sums across tig lanes (lanes differing in bits 0..1)
#pragma unroll
    for (int rf = 0; rf < 2; rf++)
#pragma unroll
        for (int h = 0; h < 2; h++) {
            rs[rf][h] += __shfl_xor_sync(0xffffffffu, rs[rf][h], 1);
            rs[rf][h] += __shfl_xor_sync(0xffffffffu, rs[rf][h], 2);
        }

    __syncthreads();                 // operand smem no longer needed
    float* rs_sm = (float*)sm;       // [2][128]
    if (tig == 0) {
#pragma unroll
        for (int rf = 0; rf < 2; rf++)
#pragma unroll
            for (int h = 0; h < 2; h++)
                rs_sm[wn * 128 + wm * 32 + rf * 16 + h * 8 + gID] = rs[rf][h];
    }
    __syncthreads();
    if (tid < 128)
        psum[(size_t)(mBase + tid) * 16 + blockIdx.y] = rs_sm[tid] + rs_sm[128 + tid];
}

// ---------------- reduce partial sums -> 1/l ----------------
__global__ __launch_bounds__(256) void reduce_l(const float* __restrict__ psum,
                                                float* __restrict__ linv) {
    int row = blockIdx.x * 256 + threadIdx.x;
    const float* p = psum + (size_t)row * 16;
    float s = 0.f;
#pragma unroll
    for (int i = 0; i < 16; i++) s += p[i];
    linv[row] = 1.f / s;
}

// ---------------- out += outS ----------------
__global__ __launch_bounds__(256) void add_out(float* __restrict__ out,
                                               const float* __restrict__ add) {
    int i = (blockIdx.x * 256 + threadIdx.x) * 4;
    float4 a = *(float4*)(out + i);
    float4 b = *(const float4*)(add + i);
    a.x += b.x; a.y += b.y; a.z += b.z; a.w += b.w;
    *(float4*)(out + i) = a;
}

// ---------------- launch ----------------
extern "C" void kernel_launch(void* const* d_in, const int* in_sizes, int n_in,
                              void* d_out, int out_size) {
    const float* x    = (const float*)d_in[0];
    const float* chm  = (const float*)d_in[1];
    const float* chwq = (const float*)d_in[2];
    const float* chwk = (const float*)d_in[3];
    const float* chwv = (const float*)d_in[4];
    const float* spm  = (const float*)d_in[5];
    const float* spwq = (const float*)d_in[6];
    const float* spwk = (const float*)d_in[7];
    const float* spwv = (const float*)d_in[8];
    float* out = (float*)d_out;

    __nv_bfloat16 *Qch, *Qcl, *Qfh, *Qfl, *Kch, *Kcl, *Kfh, *Kfl;
    __nv_bfloat16 *Vtch, *Vtcl, *Vtfh, *Vtfl, *Ph0, *Pl0, *Ph1, *Pl1;
    float *ps0, *ps1, *li0, *li1, *qm, *qv, *km, *kv, *outS;
    cudaGetSymbolAddress((void**)&Qch, g_Qc_hi);  cudaGetSymbolAddress((void**)&Qcl, g_Qc_lo);
    cudaGetSymbolAddress((void**)&Qfh, g_Qf_hi);  cudaGetSymbolAddress((void**)&Qfl, g_Qf_lo);
    cudaGetSymbolAddress((void**)&Kch, g_Kc_hi);  cudaGetSymbolAddress((void**)&Kcl, g_Kc_lo);
    cudaGetSymbolAddress((void**)&Kfh, g_Kf_hi);  cudaGetSymbolAddress((void**)&Kfl, g_Kf_lo);
    cudaGetSymbolAddress((void**)&Vtch, g_Vtc_hi); cudaGetSymbolAddress((void**)&Vtcl, g_Vtc_lo);
    cudaGetSymbolAddress((void**)&Vtfh, g_Vtf_hi); cudaGetSymbolAddress((void**)&Vtfl, g_Vtf_lo);
    cudaGetSymbolAddress((void**)&Ph0, g_Ph0);    cudaGetSymbolAddress((void**)&Pl0, g_Pl0);
    cudaGetSymbolAddress((void**)&Ph1, g_Ph1);    cudaGetSymbolAddress((void**)&Pl1, g_Pl1);
    cudaGetSymbolAddress((void**)&ps0, g_psum0);  cudaGetSymbolAddress((void**)&ps1, g_psum1);
    cudaGetSymbolAddress((void**)&li0, g_linv0);  cudaGetSymbolAddress((void**)&li1, g_linv1);
    cudaGetSymbolAddress((void**)&qm, g_qm);      cudaGetSymbolAddress((void**)&qv, g_qv);
    cudaGetSymbolAddress((void**)&km, g_km);      cudaGetSymbolAddress((void**)&kv, g_kv);
    cudaGetSymbolAddress((void**)&outS, g_OutS);

    cudaFuncSetAttribute(mma_gemm, cudaFuncAttributeMaxDynamicSharedMemorySize, MM_SMEM);

    dim3 gq(NB / 64, 4), gm(MTOT / 64, 4);
    dim3 gs(NB / 128, MTOT / 128);
    dim3 gp(NB / 128, DDIM / 128);

    // order chosen so ncu -s 5 -c 1 profiles the spatial score MMA kernel
    gemm_hl<<<gq, 256>>>(x, spwq, Qfh, Qfl);                       // 0
    gemm_hl<<<gq, 256>>>(x, chwq, Qch, Qcl);                       // 1
    gemm_hl<<<gm, 256>>>(spm, spwk, Kfh, Kfl);                     // 2
    row_stats_hl<<<NB / 8, 256>>>(Qfh, Qfl, qm, qv);               // 3
    row_stats_hl<<<MTOT / 8, 256>>>(Kfh, Kfl, km, kv);             // 4
    mma_gemm<<<gs, 256, MM_SMEM>>>(Qfh, Qfl, Kfh, Kfl, nullptr,    // 5  (profiled)
                                   Ph1, Pl1, ps1, nullptr, 256, 2048, 1, qm, qv, km, kv);
    gemm_hl<<<gm, 256>>>(chm, chwk, Kch, Kcl);                     // 6
    mma_gemm<<<gs, 256, MM_SMEM>>>(Qch, Qcl, Kch, Kcl, nullptr,    // 7
                                   Ph0, Pl0, ps0, nullptr, 256, 2048, 0, qm, qv, km, kv);
    gemm_hlT<<<gm, 256>>>(chm, chwv, Vtch, Vtcl);                  // 8
    gemm_hlT<<<gm, 256>>>(spm, spwv, Vtfh, Vtfl);                  // 9
    reduce_l<<<NB / 256, 256>>>(ps1, li1);                         // 10
    reduce_l<<<NB / 256, 256>>>(ps0, li0);                         // 11
    mma_gemm<<<gp, 256, MM_SMEM>>>(Ph0, Pl0, Vtch, Vtcl, out,      // 12
                                   nullptr, nullptr, nullptr, li0, 2048, 256, 2, qm, qv, km, kv);
    mma_gemm<<<gp, 256, MM_SMEM>>>(Ph1, Pl1, Vtfh, Vtfl, outS,     // 13
                                   nullptr, nullptr, nullptr, li1, 2048, 256, 2, qm, qv, km, kv);
    add_out<<<NB * DDIM / 1024, 256>>>(out, outS);                 // 14
}

// round 6
// speedup vs baseline: 3.1016x; 1.2955x over previous
#include <cuda_runtime.h>
#include <cuda_bf16.h>
#include <cstdint>

#define NB   12544
#define MTOT 2048
#define DDIM 256

typedef __nv_bfloat16 bf16;

// ---------------- scratch ----------------
__device__ bf16 g_Qc_hi[NB * DDIM], g_Qc_lo[NB * DDIM];
__device__ bf16 g_Qf_hi[NB * DDIM], g_Qf_lo[NB * DDIM];
__device__ bf16 g_Kc_hi[MTOT * DDIM], g_Kc_lo[MTOT * DDIM];
__device__ bf16 g_Kf_hi[MTOT * DDIM], g_Kf_lo[MTOT * DDIM];
__device__ bf16 g_Vtc_hi[DDIM * MTOT], g_Vtc_lo[DDIM * MTOT];
__device__ bf16 g_Vtf_hi[DDIM * MTOT], g_Vtf_lo[DDIM * MTOT];
__device__ bf16 g_Ph0[(size_t)NB * MTOT], g_Pl0[(size_t)NB * MTOT];
__device__ bf16 g_Ph1[(size_t)NB * MTOT], g_Pl1[(size_t)NB * MTOT];
__device__ float g_psum0[NB * 16], g_psum1[NB * 16];
__device__ float g_linv0[NB], g_linv1[NB];
__device__ float g_qm[NB], g_qv[NB], g_km[MTOT], g_kv[MTOT];
__device__ float g_OutS[NB * DDIM];

// ---------------- helpers ----------------
__device__ __forceinline__ uint32_t smem_u32(const void* p) {
    uint32_t a;
    asm("{ .reg .u64 t; cvta.to.shared.u64 t, %1; cvt.u32.u64 %0, t; }" : "=r"(a) : "l"(p));
    return a;
}
#define SWZ(o) ((o) ^ (((o) >> 3) & 0x70))

__device__ __forceinline__ void mma16816(float* c, const uint32_t* a, const uint32_t* b) {
    asm volatile(
        "mma.sync.aligned.m16n8k16.row.col.f32.bf16.bf16.f32 "
        "{%0,%1,%2,%3}, {%4,%5,%6,%7}, {%8,%9}, {%0,%1,%2,%3};"
        : "+f"(c[0]), "+f"(c[1]), "+f"(c[2]), "+f"(c[3])
        : "r"(a[0]), "r"(a[1]), "r"(a[2]), "r"(a[3]), "r"(b[0]), "r"(b[1]));
}
__device__ __forceinline__ void ldsm_x4(uint32_t* r, uint32_t addr) {
    asm volatile("ldmatrix.sync.aligned.m8n8.x4.shared.b16 {%0,%1,%2,%3}, [%4];"
                 : "=r"(r[0]), "=r"(r[1]), "=r"(r[2]), "=r"(r[3]) : "r"(addr));
}
__device__ __forceinline__ void ldsm_x2(uint32_t* r, uint32_t addr) {
    asm volatile("ldmatrix.sync.aligned.m8n8.x2.shared.b16 {%0,%1}, [%2];"
                 : "=r"(r[0]), "=r"(r[1]) : "r"(addr));
}
__device__ __forceinline__ void cp16(uint32_t dst, const void* src) {
    asm volatile("cp.async.cg.shared.global [%0], [%1], 16;" :: "r"(dst), "l"(src));
}
#define CP_COMMIT() asm volatile("cp.async.commit_group;" ::: "memory")
#define CP_WAIT1()  asm volatile("cp.async.wait_group 1;" ::: "memory")

// packed tile addressing: 128 logical rows x 64 bytes -> 64 smem rows x 128B
__device__ __forceinline__ uint32_t toff(int row, int cb) {
    return SWZ((uint32_t)((row & 63) * 128 + ((row >> 6) << 6) + cb));
}

// ---------------- merged projection GEMMs ----------------
struct ProjPtrs {
    const float* A[6];
    const float* W[6];
    bf16* Oh[6];
    bf16* Ol[6];
    int nx[6];
    int trans[6];
};

__global__ __launch_bounds__(256) void proj_all(ProjPtrs p) {
    const int z = blockIdx.z;
    if ((int)blockIdx.x >= p.nx[z]) return;
    const float* __restrict__ A = p.A[z];
    const float* __restrict__ W = p.W[z];
    bf16* __restrict__ Oh = p.Oh[z];
    bf16* __restrict__ Ol = p.Ol[z];
    const int transposed = p.trans[z];

    __shared__ float As[16][68];
    __shared__ float Ws[16][68];
    const int tid = threadIdx.x;
    const int tx = tid & 15, ty = tid >> 4;
    const int bm = blockIdx.x * 64, bn = blockIdx.y * 64;
    const int lr = tid >> 2, lk = (tid & 3) * 4;

    float acc[4][4];
#pragma unroll
    for (int i = 0; i < 4; i++)
#pragma unroll
        for (int j = 0; j < 4; j++) acc[i][j] = 0.f;

    for (int k0 = 0; k0 < 256; k0 += 16) {
        float4 av = *(const float4*)(A + (size_t)(bm + lr) * 256 + k0 + lk);
        float4 wv = *(const float4*)(W + (size_t)(bn + lr) * 256 + k0 + lk);
        As[lk + 0][lr] = av.x; As[lk + 1][lr] = av.y; As[lk + 2][lr] = av.z; As[lk + 3][lr] = av.w;
        Ws[lk + 0][lr] = wv.x; Ws[lk + 1][lr] = wv.y; Ws[lk + 2][lr] = wv.z; Ws[lk + 3][lr] = wv.w;
        __syncthreads();
#pragma unroll
        for (int k = 0; k < 16; k++) {
            float4 a = *(const float4*)&As[k][ty * 4];
            float4 b = *(const float4*)&Ws[k][tx * 4];
            acc[0][0] += a.x * b.x; acc[0][1] += a.x * b.y; acc[0][2] += a.x * b.z; acc[0][3] += a.x * b.w;
            acc[1][0] += a.y * b.x; acc[1][1] += a.y * b.y; acc[1][2] += a.y * b.z; acc[1][3] += a.y * b.w;
            acc[2][0] += a.z * b.x; acc[2][1] += a.z * b.y; acc[2][2] += a.z * b.z; acc[2][3] += a.z * b.w;
            acc[3][0] += a.w * b.x; acc[3][1] += a.w * b.y; acc[3][2] += a.w * b.z; acc[3][3] += a.w * b.w;
        }
        __syncthreads();
    }
    if (!transposed) {
#pragma unroll
        for (int i = 0; i < 4; i++) {
            size_t off = (size_t)(bm + ty * 4 + i) * 256 + bn + tx * 4;
#pragma unroll
            for (int j = 0; j < 4; j++) {
                float a = acc[i][j];
                bf16 h = __float2bfloat16(a);
                bf16 l = __float2bfloat16(a - __bfloat162float(h));
                Oh[off + j] = h;
                Ol[off + j] = l;
            }
        }
    } else {
#pragma unroll
        for (int i = 0; i < 4; i++) {
            int row = bm + ty * 4 + i;
#pragma unroll
            for (int j = 0; j < 4; j++) {
                int col = bn + tx * 4 + j;
                float a = acc[i][j];
                bf16 h = __float2bfloat16(a);
                bf16 l = __float2bfloat16(a - __bfloat162float(h));
                Oh[(size_t)col * MTOT + row] = h;
                Ol[(size_t)col * MTOT + row] = l;
            }
        }
    }
}

// ---------------- merged row stats ----------------
__global__ __launch_bounds__(256) void row_stats2(
    const bf16* __restrict__ Qh, const bf16* __restrict__ Ql,
    const bf16* __restrict__ Kh, const bf16* __restrict__ Kl,
    float* __restrict__ qm, float* __restrict__ qv,
    float* __restrict__ km, float* __restrict__ kv) {
    int row = blockIdx.x * 8 + (threadIdx.x >> 5);
    const int lane = threadIdx.x & 31;
    const bf16 *Xh, *Xl;
    float *mean, *var;
    if (row < NB) { Xh = Qh; Xl = Ql; mean = qm; var = qv; }
    else { row -= NB; Xh = Kh; Xl = Kl; mean = km; var = kv; }
    const size_t base = (size_t)row * 256;
    float s = 0.f, ss = 0.f;
#pragma unroll
    for (int c = 0; c < 256; c += 32) {
        float v = __bfloat162float(Xh[base + c + lane]) + __bfloat162float(Xl[base + c + lane]);
        s += v; ss += v * v;
    }
#pragma unroll
    for (int o = 16; o > 0; o >>= 1) {
        s += __shfl_xor_sync(0xffffffffu, s, o);
        ss += __shfl_xor_sync(0xffffffffu, ss, o);
    }
    if (lane == 0) {
        float m = s * (1.f / 256.f);
        mean[row] = m;
        var[row] = (ss - 256.f * m * m) * (1.f / 255.f);
    }
}

// ---------------- pipelined split-bf16 MMA GEMM (merged branches via z) ----------------
// scoreKernel=1: z=0 channel exp(dot/16), z=1 spatial exp(SSIM) -> P hi/lo + psum
// scoreKernel=0: PV, C = acc * linv[row]
struct MMArgs {
    const bf16 *Ah[2], *Al[2], *Bh[2], *Bl[2];
    float* C[2];
    bf16 *Ph[2], *Pl[2];
    float* psum[2];
    const float* linv[2];
    const float *qm, *qv, *km, *kv;
    int Klen, ldc, scoreKernel;
};

#define STG_BYTES 32768
#define MM_SMEM (3 * STG_BYTES)

__global__ __launch_bounds__(256, 2) void mma_gemm(MMArgs g) {
    extern __shared__ char sm[];
    const uint32_t sb = smem_u32(sm);
    const int z = blockIdx.z;
    const bf16* __restrict__ Ah = g.Ah[z];
    const bf16* __restrict__ Al = g.Al[z];
    const bf16* __restrict__ Bh = g.Bh[z];
    const bf16* __restrict__ Bl = g.Bl[z];
    const int Klen = g.Klen;
    const int tid = threadIdx.x;
    const int wid = tid >> 5, lane = tid & 31;
    const int wm = wid & 3, wn = wid >> 2;
    const int mBase = blockIdx.x * 128;
    const int nBase = blockIdx.y * 128;

    float acc[2][8][4];
#pragma unroll
    for (int rf = 0; rf < 2; rf++)
#pragma unroll
        for (int nt = 0; nt < 8; nt++)
#pragma unroll
            for (int c = 0; c < 4; c++) acc[rf][nt][c] = 0.f;

    const int a_row = wm * 32 + (lane & 15);
    const int a_kb  = (lane >> 4) * 16;
    const int b_row = wn * 64 + (lane & 7);
    const int b_kb  = ((lane >> 3) & 1) * 16;

    // per-thread load coords: 2 rows x 1 16B chunk per array per stage
    const int lr0 = tid >> 2;            // 0..63
    const int lg  = (tid & 3);           // 0..3 -> 16B chunk
    // rows lr0 and lr0+64

    const int nIter = Klen >> 5;
    auto issue = [&](int buf, int k0) {
        uint32_t base = sb + buf * STG_BYTES;
#pragma unroll
        for (int h = 0; h < 2; h++) {
            int r = lr0 + h * 64;
            uint32_t off = toff(r, lg * 16);
            size_t ga = (size_t)(mBase + r) * Klen + k0 + lg * 8;
            size_t gb = (size_t)(nBase + r) * Klen + k0 + lg * 8;
            cp16(base + off,         Ah + ga);
            cp16(base + 8192 + off,  Al + ga);
            cp16(base + 16384 + off, Bh + gb);
            cp16(base + 24576 + off, Bl + gb);
        }
    };

    issue(0, 0); CP_COMMIT();
    issue(1, 32); CP_COMMIT();

    int buf = 0;
    for (int it = 0; it < nIter; it++) {
        CP_WAIT1();
        __syncthreads();
        if (it + 2 < nIter) issue((it + 2) % 3, (it + 2) * 32);
        CP_COMMIT();

        const uint32_t sbase = sb + buf * STG_BYTES;
#pragma unroll
        for (int ks = 0; ks < 2; ks++) {
            uint32_t ah[2][4], al[2][4];
#pragma unroll
            for (int rf = 0; rf < 2; rf++) {
                uint32_t off = toff(a_row + rf * 16, ks * 32 + a_kb);
                ldsm_x4(ah[rf], sbase + off);
                ldsm_x4(al[rf], sbase + 8192 + off);
            }
#pragma unroll
            for (int nt = 0; nt < 8; nt++) {
                uint32_t off = toff(b_row + nt * 8, ks * 32 + b_kb);
                uint32_t bh[2], bl[2];
                ldsm_x2(bh, sbase + 16384 + off);
                ldsm_x2(bl, sbase + 24576 + off);
#pragma unroll
                for (int rf = 0; rf < 2; rf++) {
                    mma16816(acc[rf][nt], ah[rf], bh);
                    mma16816(acc[rf][nt], ah[rf], bl);
                    mma16816(acc[rf][nt], al[rf], bh);
                }
            }
        }
        buf++; if (buf == 3) buf = 0;
    }

    // ---- epilogue ----
    const int gID = lane >> 2, tig = lane & 3;

    if (!g.scoreKernel) {
        float* __restrict__ C = g.C[z];
        const float* __restrict__ linv = g.linv[z];
        const int ldc = g.ldc;
#pragma unroll
        for (int rf = 0; rf < 2; rf++) {
            int r0 = mBase + wm * 32 + rf * 16 + gID;
            int r1 = r0 + 8;
            float i0 = linv[r0], i1 = linv[r1];
#pragma unroll
            for (int nt = 0; nt < 8; nt++) {
                int col = nBase + wn * 64 + nt * 8 + tig * 2;
                *(float2*)(C + (size_t)r0 * ldc + col) =
                    make_float2(acc[rf][nt][0] * i0, acc[rf][nt][1] * i0);
                *(float2*)(C + (size_t)r1 * ldc + col) =
                    make_float2(acc[rf][nt][2] * i1, acc[rf][nt][3] * i1);
            }
        }
        return;
    }

    bf16* __restrict__ Ph = g.Ph[z];
    bf16* __restrict__ Pl = g.Pl[z];
    const int mode = (z == 0) ? 0 : 1;
    float rs[2][2];
    rs[0][0] = rs[0][1] = rs[1][0] = rs[1][1] = 0.f;

#pragma unroll
    for (int rf = 0; rf < 2; rf++) {
        int r0 = mBase + wm * 32 + rf * 16 + gID;
        int r1 = r0 + 8;
        float qm0 = 0.f, qv0 = 0.f, qm1 = 0.f, qv1 = 0.f;
        if (mode == 1) { qm0 = g.qm[r0]; qv0 = g.qv[r0]; qm1 = g.qm[r1]; qv1 = g.qv[r1]; }
#pragma unroll
        for (int nt = 0; nt < 8; nt++) {
            int col = nBase + wn * 64 + nt * 8 + tig * 2;
            float v0 = acc[rf][nt][0], v1 = acc[rf][nt][1];
            float v2 = acc[rf][nt][2], v3 = acc[rf][nt][3];
            if (mode == 0) {
                v0 = __expf(v0 * 0.0625f); v1 = __expf(v1 * 0.0625f);
                v2 = __expf(v2 * 0.0625f); v3 = __expf(v3 * 0.0625f);
            } else {
                float km0 = g.km[col], kv0 = g.kv[col];
                float km1 = g.km[col + 1], kv1 = g.kv[col + 1];
#define SSIM(dot, QM, QV, KM, KV)                                              \
    ({ float mp = (QM) * (KM);                                                 \
       float cov = ((dot) - 256.f * mp) * (1.f / 255.f);                       \
       float num = (2.f * mp + 0.01f) * (2.f * cov + 0.03f);                   \
       float den = ((QM) * (QM) + (KM) * (KM) + 0.01f) * ((QV) + (KV) + 0.03f);\
       num / (den + 1e-8f); })
                v0 = __expf(SSIM(v0, qm0, qv0, km0, kv0));
                v1 = __expf(SSIM(v1, qm0, qv0, km1, kv1));
                v2 = __expf(SSIM(v2, qm1, qv1, km0, kv0));
                v3 = __expf(SSIM(v3, qm1, qv1, km1, kv1));
            }
            rs[rf][0] += v0 + v1;
            rs[rf][1] += v2 + v3;

            bf16 h0 = __float2bfloat16(v0);
            bf16 l0 = __float2bfloat16(v0 - __bfloat162float(h0));
            bf16 h1 = __float2bfloat16(v1);
            bf16 l1 = __float2bfloat16(v1 - __bfloat162float(h1));
            bf16 h2 = __float2bfloat16(v2);
            bf16 l2 = __float2bfloat16(v2 - __bfloat162float(h2));
            bf16 h3 = __float2bfloat16(v3);
            bf16 l3 = __float2bfloat16(v3 - __bfloat162float(h3));
            __nv_bfloat162 hh0; hh0.x = h0; hh0.y = h1;
            __nv_bfloat162 ll0; ll0.x = l0; ll0.y = l1;
            __nv_bfloat162 hh1; hh1.x = h2; hh1.y = h3;
            __nv_bfloat162 ll1; ll1.x = l2; ll1.y = l3;
            *(__nv_bfloat162*)(Ph + (size_t)r0 * 2048 + col) = hh0;
            *(__nv_bfloat162*)(Pl + (size_t)r0 * 2048 + col) = ll0;
            *(__nv_bfloat162*)(Ph + (size_t)r1 * 2048 + col) = hh1;
            *(__nv_bfloat162*)(Pl + (size_t)r1 * 2048 + col) = ll1;
        }
    }

#pragma unroll
    for (int rf = 0; rf < 2; rf++)
#pragma unroll
        for (int h = 0; h < 2; h++) {
            rs[rf][h] += __shfl_xor_sync(0xffffffffu, rs[rf][h], 1);
            rs[rf][h] += __shfl_xor_sync(0xffffffffu, rs[rf][h], 2);
        }

    __syncthreads();
    float* rs_sm = (float*)sm;
    if (tig == 0) {
#pragma unroll
        for (int rf = 0; rf < 2; rf++)
#pragma unroll
            for (int h = 0; h < 2; h++)
                rs_sm[wn * 128 + wm * 32 + rf * 16 + h * 8 + gID] = rs[rf][h];
    }
    __syncthreads();
    if (tid < 128)
        g.psum[z][(size_t)(mBase + tid) * 16 + blockIdx.y] = rs_sm[tid] + rs_sm[128 + tid];
}

// ---------------- reduce partial sums -> 1/l (both branches) ----------------
__global__ __launch_bounds__(256) void reduce_l2(const float* __restrict__ ps0,
                                                 const float* __restrict__ ps1,
                                                 float* __restrict__ li0,
                                                 float* __restrict__ li1) {
    int row = blockIdx.x * 256 + threadIdx.x;
    const float* p = (blockIdx.y == 0 ? ps0 : ps1) + (size_t)row * 16;
    float s = 0.f;
#pragma unroll
    for (int i = 0; i < 16; i++) s += p[i];
    (blockIdx.y == 0 ? li0 : li1)[row] = 1.f / s;
}

// ---------------- out += outS ----------------
__global__ __launch_bounds__(256) void add_out(float* __restrict__ out,
                                               const float* __restrict__ add) {
    int i = (blockIdx.x * 256 + threadIdx.x) * 4;
    float4 a = *(float4*)(out + i);
    float4 b = *(const float4*)(add + i);
    a.x += b.x; a.y += b.y; a.z += b.z; a.w += b.w;
    *(float4*)(out + i) = a;
}

// ---------------- launch ----------------
extern "C" void kernel_launch(void* const* d_in, const int* in_sizes, int n_in,
                              void* d_out, int out_size) {
    const float* x    = (const float*)d_in[0];
    const float* chm  = (const float*)d_in[1];
    const float* chwq = (const float*)d_in[2];
    const float* chwk = (const float*)d_in[3];
    const float* chwv = (const float*)d_in[4];
    const float* spm  = (const float*)d_in[5];
    const float* spwq = (const float*)d_in[6];
    const float* spwk = (const float*)d_in[7];
    const float* spwv = (const float*)d_in[8];
    float* out = (float*)d_out;

    bf16 *Qch, *Qcl, *Qfh, *Qfl, *Kch, *Kcl, *Kfh, *Kfl;
    bf16 *Vtch, *Vtcl, *Vtfh, *Vtfl, *Ph0, *Pl0, *Ph1, *Pl1;
    float *ps0, *ps1, *li0, *li1, *qm, *qv, *km, *kv, *outS;
    cudaGetSymbolAddress((void**)&Qch, g_Qc_hi);  cudaGetSymbolAddress((void**)&Qcl, g_Qc_lo);
    cudaGetSymbolAddress((void**)&Qfh, g_Qf_hi);  cudaGetSymbolAddress((void**)&Qfl, g_Qf_lo);
    cudaGetSymbolAddress((void**)&Kch, g_Kc_hi);  cudaGetSymbolAddress((void**)&Kcl, g_Kc_lo);
    cudaGetSymbolAddress((void**)&Kfh, g_Kf_hi);  cudaGetSymbolAddress((void**)&Kfl, g_Kf_lo);
    cudaGetSymbolAddress((void**)&Vtch, g_Vtc_hi); cudaGetSymbolAddress((void**)&Vtcl, g_Vtc_lo);
    cudaGetSymbolAddress((void**)&Vtfh, g_Vtf_hi); cudaGetSymbolAddress((void**)&Vtfl, g_Vtf_lo);
    cudaGetSymbolAddress((void**)&Ph0, g_Ph0);    cudaGetSymbolAddress((void**)&Pl0, g_Pl0);
    cudaGetSymbolAddress((void**)&Ph1, g_Ph1);    cudaGetSymbolAddress((void**)&Pl1, g_Pl1);
    cudaGetSymbolAddress((void**)&ps0, g_psum0);  cudaGetSymbolAddress((void**)&ps1, g_psum1);
    cudaGetSymbolAddress((void**)&li0, g_linv0);  cudaGetSymbolAddress((void**)&li1, g_linv1);
    cudaGetSymbolAddress((void**)&qm, g_qm);      cudaGetSymbolAddress((void**)&qv, g_qv);
    cudaGetSymbolAddress((void**)&km, g_km);      cudaGetSymbolAddress((void**)&kv, g_kv);
    cudaGetSymbolAddress((void**)&outS, g_OutS);

    cudaFuncSetAttribute(mma_gemm, cudaFuncAttributeMaxDynamicSharedMemorySize, MM_SMEM);

    // 0: merged projections
    ProjPtrs pp;
    pp.A[0] = x;   pp.W[0] = spwq; pp.Oh[0] = Qfh;  pp.Ol[0] = Qfl;  pp.nx[0] = NB / 64;   pp.trans[0] = 0;
    pp.A[1] = x;   pp.W[1] = chwq; pp.Oh[1] = Qch;  pp.Ol[1] = Qcl;  pp.nx[1] = NB / 64;   pp.trans[1] = 0;
    pp.A[2] = spm; pp.W[2] = spwk; pp.Oh[2] = Kfh;  pp.Ol[2] = Kfl;  pp.nx[2] = MTOT / 64; pp.trans[2] = 0;
    pp.A[3] = chm; pp.W[3] = chwk; pp.Oh[3] = Kch;  pp.Ol[3] = Kcl;  pp.nx[3] = MTOT / 64; pp.trans[3] = 0;
    pp.A[4] = chm; pp.W[4] = chwv; pp.Oh[4] = Vtch; pp.Ol[4] = Vtcl; pp.nx[4] = MTOT / 64; pp.trans[4] = 1;
    pp.A[5] = spm; pp.W[5] = spwv; pp.Oh[5] = Vtfh; pp.Ol[5] = Vtfl; pp.nx[5] = MTOT / 64; pp.trans[5] = 1;
    proj_all<<<dim3(NB / 64, 4, 6), 256>>>(pp);

    // 1: merged row stats
    row_stats2<<<(NB + MTOT) / 8, 256>>>(Qfh, Qfl, Kfh, Kfl, qm, qv, km, kv);

    // 2: merged score GEMMs
    MMArgs sa;
    sa.Ah[0] = Qch; sa.Al[0] = Qcl; sa.Bh[0] = Kch; sa.Bl[0] = Kcl;
    sa.Ah[1] = Qfh; sa.Al[1] = Qfl; sa.Bh[1] = Kfh; sa.Bl[1] = Kfl;
    sa.C[0] = sa.C[1] = nullptr;
    sa.Ph[0] = Ph0; sa.Pl[0] = Pl0; sa.Ph[1] = Ph1; sa.Pl[1] = Pl1;
    sa.psum[0] = ps0; sa.psum[1] = ps1;
    sa.linv[0] = sa.linv[1] = nullptr;
    sa.qm = qm; sa.qv = qv; sa.km = km; sa.kv = kv;
    sa.Klen = 256; sa.ldc = 0; sa.scoreKernel = 1;
    mma_gemm<<<dim3(NB / 128, MTOT / 128, 2), 256, MM_SMEM>>>(sa);

    // 3: reduce
    reduce_l2<<<dim3(NB / 256, 2), 256>>>(ps0, ps1, li0, li1);

    // 4: merged PV GEMMs
    MMArgs pa;
    pa.Ah[0] = Ph0; pa.Al[0] = Pl0; pa.Bh[0] = Vtch; pa.Bl[0] = Vtcl;
    pa.Ah[1] = Ph1; pa.Al[1] = Pl1; pa.Bh[1] = Vtfh; pa.Bl[1] = Vtfl;
    pa.C[0] = out; pa.C[1] = outS;
    pa.Ph[0] = pa.Ph[1] = nullptr; pa.Pl[0] = pa.Pl[1] = nullptr;
    pa.psum[0] = pa.psum[1] = nullptr;
    pa.linv[0] = li0; pa.linv[1] = li1;
    pa.qm = qm; pa.qv = qv; pa.km = km; pa.kv = kv;
    pa.Klen = 2048; pa.ldc = 256; pa.scoreKernel = 0;
    mma_gemm<<<dim3(NB / 128, DDIM / 128, 2), 256, MM_SMEM>>>(pa);

    // 5: combine
    add_out<<<NB * DDIM / 1024, 256>>>(out, outS);
}

// round 7
// speedup vs baseline: 3.8490x; 1.2410x over previous
#include <cuda_runtime.h>
#include <cuda_bf16.h>
#include <cstdint>

#define NB   12544
#define MTOT 2048
#define DDIM 256

typedef __nv_bfloat16 bf16;

// ---------------- scratch ----------------
__device__ bf16 g_x_hi[NB * DDIM], g_x_lo[NB * DDIM];
__device__ bf16 g_cm_hi[MTOT * DDIM], g_cm_lo[MTOT * DDIM];
__device__ bf16 g_sm_hi[MTOT * DDIM], g_sm_lo[MTOT * DDIM];
__device__ bf16 g_w_hi[6 * DDIM * DDIM], g_w_lo[6 * DDIM * DDIM];
__device__ bf16 g_Qc_hi[NB * DDIM], g_Qc_lo[NB * DDIM];
__device__ bf16 g_Qf_hi[NB * DDIM], g_Qf_lo[NB * DDIM];
__device__ bf16 g_Kc_hi[MTOT * DDIM], g_Kc_lo[MTOT * DDIM];
__device__ bf16 g_Kf_hi[MTOT * DDIM], g_Kf_lo[MTOT * DDIM];
__device__ bf16 g_Vtc_hi[DDIM * MTOT], g_Vtc_lo[DDIM * MTOT];
__device__ bf16 g_Vtf_hi[DDIM * MTOT], g_Vtf_lo[DDIM * MTOT];
__device__ bf16 g_Ph0[(size_t)NB * MTOT], g_Pl0[(size_t)NB * MTOT];
__device__ bf16 g_Ph1[(size_t)NB * MTOT], g_Pl1[(size_t)NB * MTOT];
__device__ float g_psum0[NB * 16], g_psum1[NB * 16];
__device__ float g_linv0[NB], g_linv1[NB];
__device__ float g_qm[NB], g_qv[NB], g_km[MTOT], g_kv[MTOT];
__device__ float g_OutS[NB * DDIM];

// ---------------- helpers ----------------
__device__ __forceinline__ uint32_t smem_u32(const void* p) {
    uint32_t a;
    asm("{ .reg .u64 t; cvta.to.shared.u64 t, %1; cvt.u32.u64 %0, t; }" : "=r"(a) : "l"(p));
    return a;
}
#define SWZ(o) ((o) ^ (((o) >> 3) & 0x70))

__device__ __forceinline__ void mma16816(float* c, const uint32_t* a, const uint32_t* b) {
    asm volatile(
        "mma.sync.aligned.m16n8k16.row.col.f32.bf16.bf16.f32 "
        "{%0,%1,%2,%3}, {%4,%5,%6,%7}, {%8,%9}, {%0,%1,%2,%3};"
        : "+f"(c[0]), "+f"(c[1]), "+f"(c[2]), "+f"(c[3])
        : "r"(a[0]), "r"(a[1]), "r"(a[2]), "r"(a[3]), "r"(b[0]), "r"(b[1]));
}
__device__ __forceinline__ void ldsm_x4(uint32_t* r, uint32_t addr) {
    asm volatile("ldmatrix.sync.aligned.m8n8.x4.shared.b16 {%0,%1,%2,%3}, [%4];"
                 : "=r"(r[0]), "=r"(r[1]), "=r"(r[2]), "=r"(r[3]) : "r"(addr));
}
__device__ __forceinline__ void cp16(uint32_t dst, const void* src) {
    asm volatile("cp.async.cg.shared.global [%0], [%1], 16;" :: "r"(dst), "l"(src));
}
#define CP_COMMIT() asm volatile("cp.async.commit_group;" ::: "memory")
#define CP_WAIT1()  asm volatile("cp.async.wait_group 1;" ::: "memory")

// packed tile addressing: 128 logical rows x 64 bytes -> 64 smem rows x 128B
__device__ __forceinline__ uint32_t toff(int row, int cb) {
    return SWZ((uint32_t)((row & 63) * 128 + ((row >> 6) << 6) + cb));
}
__device__ __forceinline__ void split1(float a, bf16& h, bf16& l) {
    h = __float2bfloat16(a);
    l = __float2bfloat16(a - __bfloat162float(h));
}

#define STG_BYTES 32768
#define MM_SMEM (3 * STG_BYTES)

// ---------------- fp32 -> bf16 hi/lo conversion (9 arrays) ----------------
struct SplitArgs {
    const float* src[9];
    bf16 *h[9], *l[9];
    int nblk[9];
};
__global__ __launch_bounds__(256) void split_all(SplitArgs a) {
    int bx = blockIdx.x, z = 0;
    while (bx >= a.nblk[z]) { bx -= a.nblk[z]; z++; }
    size_t i = ((size_t)bx * 256 + threadIdx.x) * 4;
    float4 v = *(const float4*)(a.src[z] + i);
    bf16 h0, l0, h1, l1, h2, l2, h3, l3;
    split1(v.x, h0, l0); split1(v.y, h1, l1);
    split1(v.z, h2, l2); split1(v.w, h3, l3);
    __nv_bfloat162 ha; ha.x = h0; ha.y = h1;
    __nv_bfloat162 hb; hb.x = h2; hb.y = h3;
    __nv_bfloat162 la; la.x = l0; la.y = l1;
    __nv_bfloat162 lb; lb.x = l2; lb.y = l3;
    *(__nv_bfloat162*)(a.h[z] + i) = ha; *(__nv_bfloat162*)(a.h[z] + i + 2) = hb;
    *(__nv_bfloat162*)(a.l[z] + i) = la; *(__nv_bfloat162*)(a.l[z] + i + 2) = lb;
}

// ---------------- mainloop macro (shared by proj / score / pv) ----------------
// defines acc + runs full K loop. Expects: sb, tid, wid, lane, wm, wn, mBase, nBase,
// pointers Ah, Al, Bh, Bl, Klen.
#define MMA_MAINLOOP()                                                          \
    float acc[2][8][4];                                                         \
    _Pragma("unroll")                                                           \
    for (int rf = 0; rf < 2; rf++)                                              \
        _Pragma("unroll")                                                       \
        for (int nt = 0; nt < 8; nt++)                                          \
            _Pragma("unroll")                                                   \
            for (int c = 0; c < 4; c++) acc[rf][nt][c] = 0.f;                   \
    const int a_row = wm * 32 + (lane & 15);                                    \
    const int a_kb  = (lane >> 4) * 16;                                         \
    const int b_row = wn * 64 + ((lane >> 4) << 3) + (lane & 7);                \
    const int b_kb  = ((lane >> 3) & 1) * 16;                                   \
    const int lr0 = tid >> 2;                                                   \
    const int lg  = (tid & 3);                                                  \
    const int nIter = Klen >> 5;                                                \
    auto issue = [&](int buf, int k0) {                                         \
        uint32_t base = sb + buf * STG_BYTES;                                   \
        _Pragma("unroll")                                                       \
        for (int h = 0; h < 2; h++) {                                           \
            int r = lr0 + h * 64;                                               \
            uint32_t off = toff(r, lg * 16);                                    \
            size_t ga = (size_t)(mBase + r) * Klen + k0 + lg * 8;               \
            size_t gb = (size_t)(nBase + r) * Klen + k0 + lg * 8;               \
            cp16(base + off,         Ah + ga);                                  \
            cp16(base + 8192 + off,  Al + ga);                                  \
            cp16(base + 16384 + off, Bh + gb);                                  \
            cp16(base + 24576 + off, Bl + gb);                                  \
        }                                                                       \
    };                                                                          \
    issue(0, 0); CP_COMMIT();                                                   \
    issue(1, 32); CP_COMMIT();                                                  \
    int buf = 0;                                                                \
    for (int it = 0; it < nIter; it++) {                                        \
        CP_WAIT1();                                                             \
        __syncthreads();                                                        \
        if (it + 2 < nIter) issue((it + 2) % 3, (it + 2) * 32);                 \
        CP_COMMIT();                                                            \
        const uint32_t sbase = sb + buf * STG_BYTES;                            \
        _Pragma("unroll")                                                       \
        for (int ks = 0; ks < 2; ks++) {                                        \
            uint32_t ah[2][4], al[2][4];                                        \
            _Pragma("unroll")                                                   \
            for (int rf = 0; rf < 2; rf++) {                                    \
                uint32_t off = toff(a_row + rf * 16, ks * 32 + a_kb);           \
                ldsm_x4(ah[rf], sbase + off);                                   \
                ldsm_x4(al[rf], sbase + 8192 + off);                            \
            }                                                                   \
            _Pragma("unroll")                                                   \
            for (int ntp = 0; ntp < 4; ntp++) {                                 \
                uint32_t off = toff(b_row + ntp * 16, ks * 32 + b_kb);          \
                uint32_t bh4[4], bl4[4];                                        \
                ldsm_x4(bh4, sbase + 16384 + off);                              \
                ldsm_x4(bl4, sbase + 24576 + off);                              \
                _Pragma("unroll")                                               \
                for (int rf = 0; rf < 2; rf++) {                                \
                    mma16816(acc[rf][2 * ntp],     ah[rf], bh4);                \
                    mma16816(acc[rf][2 * ntp],     ah[rf], bl4);                \
                    mma16816(acc[rf][2 * ntp],     al[rf], bh4);                \
                    mma16816(acc[rf][2 * ntp + 1], ah[rf], bh4 + 2);            \
                    mma16816(acc[rf][2 * ntp + 1], ah[rf], bl4 + 2);            \
                    mma16816(acc[rf][2 * ntp + 1], al[rf], bh4 + 2);            \
                }                                                               \
            }                                                                   \
        }                                                                       \
        buf++; if (buf == 3) buf = 0;                                           \
    }

// ---------------- projection GEMMs via MMA ----------------
struct ProjM {
    const bf16 *A_h[6], *A_l[6], *B_h[6], *B_l[6];
    bf16 *Oh[6], *Ol[6];
    int mx[6], trans[6];
};
__global__ __launch_bounds__(256, 2) void mma_proj(ProjM p) {
    extern __shared__ char sm[];
    const int z = blockIdx.z;
    if ((int)blockIdx.x >= p.mx[z]) return;
    const uint32_t sb = smem_u32(sm);
    const bf16* __restrict__ Ah = p.A_h[z];
    const bf16* __restrict__ Al = p.A_l[z];
    const bf16* __restrict__ Bh = p.B_h[z];
    const bf16* __restrict__ Bl = p.B_l[z];
    const int Klen = 256;
    const int tid = threadIdx.x;
    const int wid = tid >> 5, lane = tid & 31;
    const int wm = wid & 3, wn = wid >> 2;
    const int mBase = blockIdx.x * 128;
    const int nBase = blockIdx.y * 128;

    MMA_MAINLOOP();

    const int gID = lane >> 2, tig = lane & 3;
    bf16* __restrict__ Oh = p.Oh[z];
    bf16* __restrict__ Ol = p.Ol[z];

    if (p.trans[z]) {
#pragma unroll
        for (int rf = 0; rf < 2; rf++) {
            int r0 = mBase + wm * 32 + rf * 16 + gID;
#pragma unroll
            for (int nt = 0; nt < 8; nt++) {
                int col = nBase + wn * 64 + nt * 8 + tig * 2;
#pragma unroll
                for (int c = 0; c < 4; c++) {
                    int row = r0 + (c >> 1) * 8;
                    int cc = col + (c & 1);
                    bf16 h, l;
                    split1(acc[rf][nt][c], h, l);
                    Oh[(size_t)cc * MTOT + row] = h;
                    Ol[(size_t)cc * MTOT + row] = l;
                }
            }
        }
        return;
    }

    // staged coalesced store
    __syncthreads();
    char* smHi = sm;
    char* smLo = sm + 32768;
#pragma unroll
    for (int rf = 0; rf < 2; rf++) {
#pragma unroll
        for (int nt = 0; nt < 8; nt++) {
            int chunk = wn * 8 + nt;
#pragma unroll
            for (int half = 0; half < 2; half++) {
                int rl = wm * 32 + rf * 16 + half * 8 + gID;
                bf16 h0, l0, h1, l1;
                split1(acc[rf][nt][half * 2 + 0], h0, l0);
                split1(acc[rf][nt][half * 2 + 1], h1, l1);
                __nv_bfloat162 hh; hh.x = h0; hh.y = h1;
                __nv_bfloat162 ll; ll.x = l0; ll.y = l1;
                uint32_t addr = rl * 256 + ((chunk ^ (rl & 15)) << 4) + tig * 4;
                *(__nv_bfloat162*)(smHi + addr) = hh;
                *(__nv_bfloat162*)(smLo + addr) = ll;
            }
        }
    }
    __syncthreads();
#pragma unroll
    for (int it = 0; it < 8; it++) {
        int idx = it * 256 + tid;
        int r = idx >> 4, c = idx & 15;
        uint32_t src = r * 256 + ((c ^ (r & 15)) << 4);
        size_t dst = (size_t)(mBase + r) * 256 + nBase + c * 8;
        *(uint4*)(Oh + dst) = *(uint4*)(smHi + src);
        *(uint4*)(Ol + dst) = *(uint4*)(smLo + src);
    }
}

// ---------------- merged row stats ----------------
__global__ __launch_bounds__(256) void row_stats2(
    const bf16* __restrict__ Qh, const bf16* __restrict__ Ql,
    const bf16* __restrict__ Kh, const bf16* __restrict__ Kl,
    float* __restrict__ qm, float* __restrict__ qv,
    float* __restrict__ km, float* __restrict__ kv) {
    int row = blockIdx.x * 8 + (threadIdx.x >> 5);
    const int lane = threadIdx.x & 31;
    const bf16 *Xh, *Xl;
    float *mean, *var;
    if (row < NB) { Xh = Qh; Xl = Ql; mean = qm; var = qv; }
    else { row -= NB; Xh = Kh; Xl = Kl; mean = km; var = kv; }
    const size_t base = (size_t)row * 256;
    float s = 0.f, ss = 0.f;
#pragma unroll
    for (int c = 0; c < 256; c += 32) {
        float v = __bfloat162float(Xh[base + c + lane]) + __bfloat162float(Xl[base + c + lane]);
        s += v; ss += v * v;
    }
#pragma unroll
    for (int o = 16; o > 0; o >>= 1) {
        s += __shfl_xor_sync(0xffffffffu, s, o);
        ss += __shfl_xor_sync(0xffffffffu, ss, o);
    }
    if (lane == 0) {
        float m = s * (1.f / 256.f);
        mean[row] = m;
        var[row] = (ss - 256.f * m * m) * (1.f / 255.f);
    }
}

// ---------------- score / PV MMA GEMM ----------------
struct MMArgs {
    const bf16 *A_h[2], *A_l[2], *B_h[2], *B_l[2];
    float* C[2];
    bf16 *Ph[2], *Pl[2];
    float* psum[2];
    const float* linv[2];
    const float *qm, *qv, *km, *kv;
    int Klen, ldc, scoreKernel;
};

__global__ __launch_bounds__(256, 2) void mma_gemm(MMArgs g) {
    extern __shared__ char sm[];
    const uint32_t sb = smem_u32(sm);
    const int z = blockIdx.z;
    const bf16* __restrict__ Ah = g.A_h[z];
    const bf16* __restrict__ Al = g.A_l[z];
    const bf16* __restrict__ Bh = g.B_h[z];
    const bf16* __restrict__ Bl = g.B_l[z];
    const int Klen = g.Klen;
    const int tid = threadIdx.x;
    const int wid = tid >> 5, lane = tid & 31;
    const int wm = wid & 3, wn = wid >> 2;
    const int mBase = blockIdx.x * 128;
    const int nBase = blockIdx.y * 128;

    MMA_MAINLOOP();

    const int gID = lane >> 2, tig = lane & 3;

    if (!g.scoreKernel) {
        float* __restrict__ C = g.C[z];
        const float* __restrict__ linv = g.linv[z];
        const int ldc = g.ldc;
#pragma unroll
        for (int rf = 0; rf < 2; rf++) {
            int r0 = mBase + wm * 32 + rf * 16 + gID;
            int r1 = r0 + 8;
            float i0 = linv[r0], i1 = linv[r1];
#pragma unroll
            for (int nt = 0; nt < 8; nt++) {
                int col = nBase + wn * 64 + nt * 8 + tig * 2;
                *(float2*)(C + (size_t)r0 * ldc + col) =
                    make_float2(acc[rf][nt][0] * i0, acc[rf][nt][1] * i0);
                *(float2*)(C + (size_t)r1 * ldc + col) =
                    make_float2(acc[rf][nt][2] * i1, acc[rf][nt][3] * i1);
            }
        }
        return;
    }

    // ---- score epilogue: transform -> exp -> split -> staged store + row sums
    const int mode = (z == 0) ? 0 : 1;
    char* smHi = sm;
    char* smLo = sm + 32768;
    float* rs_sm = (float*)(sm + 65536);
    float rs[2][2];
    rs[0][0] = rs[0][1] = rs[1][0] = rs[1][1] = 0.f;

    __syncthreads();
#pragma unroll
    for (int rf = 0; rf < 2; rf++) {
        int r0 = mBase + wm * 32 + rf * 16 + gID;
        int r1 = r0 + 8;
        float qm0 = 0.f, qv0 = 0.f, qm1 = 0.f, qv1 = 0.f;
        if (mode == 1) { qm0 = g.qm[r0]; qv0 = g.qv[r0]; qm1 = g.qm[r1]; qv1 = g.qv[r1]; }
#pragma unroll
        for (int nt = 0; nt < 8; nt++) {
            int col = nBase + wn * 64 + nt * 8 + tig * 2;
            float v0 = acc[rf][nt][0], v1 = acc[rf][nt][1];
            float v2 = acc[rf][nt][2], v3 = acc[rf][nt][3];
            if (mode == 0) {
                v0 = __expf(v0 * 0.0625f); v1 = __expf(v1 * 0.0625f);
                v2 = __expf(v2 * 0.0625f); v3 = __expf(v3 * 0.0625f);
            } else {
                float km0 = g.km[col], kv0 = g.kv[col];
                float km1 = g.km[col + 1], kv1 = g.kv[col + 1];
#define SSIM(dot, QM, QV, KM, KV)                                              \
    ({ float mp = (QM) * (KM);                                                 \
       float cov = ((dot) - 256.f * mp) * (1.f / 255.f);                       \
       float num = (2.f * mp + 0.01f) * (2.f * cov + 0.03f);                   \
       float den = ((QM) * (QM) + (KM) * (KM) + 0.01f) * ((QV) + (KV) + 0.03f);\
       num / (den + 1e-8f); })
                v0 = __expf(SSIM(v0, qm0, qv0, km0, kv0));
                v1 = __expf(SSIM(v1, qm0, qv0, km1, kv1));
                v2 = __expf(SSIM(v2, qm1, qv1, km0, kv0));
                v3 = __expf(SSIM(v3, qm1, qv1, km1, kv1));
            }
            rs[rf][0] += v0 + v1;
            rs[rf][1] += v2 + v3;

            int chunk = wn * 8 + nt;
            int rl0 = wm * 32 + rf * 16 + gID;
            int rl1 = rl0 + 8;
            bf16 h0, l0, h1, l1, h2, l2, h3, l3;
            split1(v0, h0, l0); split1(v1, h1, l1);
            split1(v2, h2, l2); split1(v3, h3, l3);
            __nv_bfloat162 hh0; hh0.x = h0; hh0.y = h1;
            __nv_bfloat162 ll0; ll0.x = l0; ll0.y = l1;
            __nv_bfloat162 hh1; hh1.x = h2; hh1.y = h3;
            __nv_bfloat162 ll1; ll1.x = l2; ll1.y = l3;
            uint32_t a0 = rl0 * 256 + ((chunk ^ (rl0 & 15)) << 4) + tig * 4;
            uint32_t a1 = rl1 * 256 + ((chunk ^ (rl1 & 15)) << 4) + tig * 4;
            *(__nv_bfloat162*)(smHi + a0) = hh0;
            *(__nv_bfloat162*)(smLo + a0) = ll0;
            *(__nv_bfloat162*)(smHi + a1) = hh1;
            *(__nv_bfloat162*)(smLo + a1) = ll1;
        }
    }

#pragma unroll
    for (int rf = 0; rf < 2; rf++)
#pragma unroll
        for (int h = 0; h < 2; h++) {
            rs[rf][h] += __shfl_xor_sync(0xffffffffu, rs[rf][h], 1);
            rs[rf][h] += __shfl_xor_sync(0xffffffffu, rs[rf][h], 2);
        }
    __syncthreads();
    if (tig == 0) {
#pragma unroll
        for (int rf = 0; rf < 2; rf++)
#pragma unroll
            for (int h = 0; h < 2; h++)
                rs_sm[wn * 128 + wm * 32 + rf * 16 + h * 8 + gID] = rs[rf][h];
    }
    __syncthreads();

    bf16* __restrict__ Ph = g.Ph[z];
    bf16* __restrict__ Pl = g.Pl[z];
#pragma unroll
    for (int it = 0; it < 8; it++) {
        int idx = it * 256 + tid;
        int r = idx >> 4, c = idx & 15;
        uint32_t src = r * 256 + ((c ^ (r & 15)) << 4);
        size_t dst = (size_t)(mBase + r) * 2048 + nBase + c * 8;
        *(uint4*)(Ph + dst) = *(uint4*)(smHi + src);
        *(uint4*)(Pl + dst) = *(uint4*)(smLo + src);
    }
    if (tid < 128)
        g.psum[z][(size_t)(mBase + tid) * 16 + blockIdx.y] = rs_sm[tid] + rs_sm[128 + tid];
}

// ---------------- reduce partial sums -> 1/l ----------------
__global__ __launch_bounds__(256) void reduce_l2(const float* __restrict__ ps0,
                                                 const float* __restrict__ ps1,
                                                 float* __restrict__ li0,
                                                 float* __restrict__ li1) {
    int row = blockIdx.x * 256 + threadIdx.x;
    const float* p = (blockIdx.y == 0 ? ps0 : ps1) + (size_t)row * 16;
    float s = 0.f;
#pragma unroll
    for (int i = 0; i < 16; i++) s += p[i];
    (blockIdx.y == 0 ? li0 : li1)[row] = 1.f / s;
}

// ---------------- out += outS ----------------
__global__ __launch_bounds__(256) void add_out(float* __restrict__ out,
                                               const float* __restrict__ add) {
    int i = (blockIdx.x * 256 + threadIdx.x) * 4;
    float4 a = *(float4*)(out + i);
    float4 b = *(const float4*)(add + i);
    a.x += b.x; a.y += b.y; a.z += b.z; a.w += b.w;
    *(float4*)(out + i) = a;
}

// ---------------- launch ----------------
extern "C" void kernel_launch(void* const* d_in, const int* in_sizes, int n_in,
                              void* d_out, int out_size) {
    const float* x    = (const float*)d_in[0];
    const float* chm  = (const float*)d_in[1];
    const float* chwq = (const float*)d_in[2];
    const float* chwk = (const float*)d_in[3];
    const float* chwv = (const float*)d_in[4];
    const float* spm  = (const float*)d_in[5];
    const float* spwq = (const float*)d_in[6];
    const float* spwk = (const float*)d_in[7];
    const float* spwv = (const float*)d_in[8];
    float* out = (float*)d_out;

    bf16 *xh, *xl, *cmh, *cml, *smh, *sml, *wh, *wl;
    bf16 *Qch, *Qcl, *Qfh, *Qfl, *Kch, *Kcl, *Kfh, *Kfl;
    bf16 *Vtch, *Vtcl, *Vtfh, *Vtfl, *Ph0, *Pl0, *Ph1, *Pl1;
    float *ps0, *ps1, *li0, *li1, *qm, *qv, *km, *kv, *outS;
    cudaGetSymbolAddress((void**)&xh, g_x_hi);    cudaGetSymbolAddress((void**)&xl, g_x_lo);
    cudaGetSymbolAddress((void**)&cmh, g_cm_hi);  cudaGetSymbolAddress((void**)&cml, g_cm_lo);
    cudaGetSymbolAddress((void**)&smh, g_sm_hi);  cudaGetSymbolAddress((void**)&sml, g_sm_lo);
    cudaGetSymbolAddress((void**)&wh, g_w_hi);    cudaGetSymbolAddress((void**)&wl, g_w_lo);
    cudaGetSymbolAddress((void**)&Qch, g_Qc_hi);  cudaGetSymbolAddress((void**)&Qcl, g_Qc_lo);
    cudaGetSymbolAddress((void**)&Qfh, g_Qf_hi);  cudaGetSymbolAddress((void**)&Qfl, g_Qf_lo);
    cudaGetSymbolAddress((void**)&Kch, g_Kc_hi);  cudaGetSymbolAddress((void**)&Kcl, g_Kc_lo);
    cudaGetSymbolAddress((void**)&Kfh, g_Kf_hi);  cudaGetSymbolAddress((void**)&Kfl, g_Kf_lo);
    cudaGetSymbolAddress((void**)&Vtch, g_Vtc_hi); cudaGetSymbolAddress((void**)&Vtcl, g_Vtc_lo);
    cudaGetSymbolAddress((void**)&Vtfh, g_Vtf_hi); cudaGetSymbolAddress((void**)&Vtfl, g_Vtf_lo);
    cudaGetSymbolAddress((void**)&Ph0, g_Ph0);    cudaGetSymbolAddress((void**)&Pl0, g_Pl0);
    cudaGetSymbolAddress((void**)&Ph1, g_Ph1);    cudaGetSymbolAddress((void**)&Pl1, g_Pl1);
    cudaGetSymbolAddress((void**)&ps0, g_psum0);  cudaGetSymbolAddress((void**)&ps1, g_psum1);
    cudaGetSymbolAddress((void**)&li0, g_linv0);  cudaGetSymbolAddress((void**)&li1, g_linv1);
    cudaGetSymbolAddress((void**)&qm, g_qm);      cudaGetSymbolAddress((void**)&qv, g_qv);
    cudaGetSymbolAddress((void**)&km, g_km);      cudaGetSymbolAddress((void**)&kv, g_kv);
    cudaGetSymbolAddress((void**)&outS, g_OutS);

    cudaFuncSetAttribute(mma_gemm, cudaFuncAttributeMaxDynamicSharedMemorySize, MM_SMEM);
    cudaFuncSetAttribute(mma_proj, cudaFuncAttributeMaxDynamicSharedMemorySize, MM_SMEM);

    // 0: fp32 -> bf16 hi/lo for x, chm, spm, 6 weights
    const int WSZ = DDIM * DDIM;
    SplitArgs sp;
    sp.src[0] = x;    sp.h[0] = xh;           sp.l[0] = xl;           sp.nblk[0] = NB * DDIM / 1024;
    sp.src[1] = chm;  sp.h[1] = cmh;          sp.l[1] = cml;          sp.nblk[1] = MTOT * DDIM / 1024;
    sp.src[2] = spm;  sp.h[2] = smh;          sp.l[2] = sml;          sp.nblk[2] = MTOT * DDIM / 1024;
    sp.src[3] = spwq; sp.h[3] = wh + 0 * WSZ; sp.l[3] = wl + 0 * WSZ; sp.nblk[3] = WSZ / 1024;
    sp.src[4] = chwq; sp.h[4] = wh + 1 * WSZ; sp.l[4] = wl + 1 * WSZ; sp.nblk[4] = WSZ / 1024;
    sp.src[5] = spwk; sp.h[5] = wh + 2 * WSZ; sp.l[5] = wl + 2 * WSZ; sp.nblk[5] = WSZ / 1024;
    sp.src[6] = chwk; sp.h[6] = wh + 3 * WSZ; sp.l[6] = wl + 3 * WSZ; sp.nblk[6] = WSZ / 1024;
    sp.src[7] = chwv; sp.h[7] = wh + 4 * WSZ; sp.l[7] = wl + 4 * WSZ; sp.nblk[7] = WSZ / 1024;
    sp.src[8] = spwv; sp.h[8] = wh + 5 * WSZ; sp.l[8] = wl + 5 * WSZ; sp.nblk[8] = WSZ / 1024;
    int totBlk = 0;
    for (int i = 0; i < 9; i++) totBlk += sp.nblk[i];
    split_all<<<totBlk, 256>>>(sp);

    // 1: projections via MMA
    ProjM pm;
    pm.A_h[0] = xh;  pm.A_l[0] = xl;  pm.B_h[0] = wh + 0 * WSZ; pm.B_l[0] = wl + 0 * WSZ;
    pm.Oh[0] = Qfh;  pm.Ol[0] = Qfl;  pm.mx[0] = NB / 128;      pm.trans[0] = 0;
    pm.A_h[1] = xh;  pm.A_l[1] = xl;  pm.B_h[1] = wh + 1 * WSZ; pm.B_l[1] = wl + 1 * WSZ;
    pm.Oh[1] = Qch;  pm.Ol[1] = Qcl;  pm.mx[1] = NB / 128;      pm.trans[1] = 0;
    pm.A_h[2] = smh; pm.A_l[2] = sml; pm.B_h[2] = wh + 2 * WSZ; pm.B_l[2] = wl + 2 * WSZ;
    pm.Oh[2] = Kfh;  pm.Ol[2] = Kfl;  pm.mx[2] = MTOT / 128;    pm.trans[2] = 0;
    pm.A_h[3] = cmh; pm.A_l[3] = cml; pm.B_h[3] = wh + 3 * WSZ; pm.B_l[3] = wl + 3 * WSZ;
    pm.Oh[3] = Kch;  pm.Ol[3] = Kcl;  pm.mx[3] = MTOT / 128;    pm.trans[3] = 0;
    pm.A_h[4] = cmh; pm.A_l[4] = cml; pm.B_h[4] = wh + 4 * WSZ; pm.B_l[4] = wl + 4 * WSZ;
    pm.Oh[4] = Vtch; pm.Ol[4] = Vtcl; pm.mx[4] = MTOT / 128;    pm.trans[4] = 1;
    pm.A_h[5] = smh; pm.A_l[5] = sml; pm.B_h[5] = wh + 5 * WSZ; pm.B_l[5] = wl + 5 * WSZ;
    pm.Oh[5] = Vtfh; pm.Ol[5] = Vtfl; pm.mx[5] = MTOT / 128;    pm.trans[5] = 1;
    mma_proj<<<dim3(NB / 128, 2, 6), 256, MM_SMEM>>>(pm);

    // 2: row stats
    row_stats2<<<(NB + MTOT) / 8, 256>>>(Qfh, Qfl, Kfh, Kfl, qm, qv, km, kv);

    // 3: score GEMMs  (profiled: launch index 3)
    MMArgs sa;
    sa.A_h[0] = Qch; sa.A_l[0] = Qcl; sa.B_h[0] = Kch; sa.B_l[0] = Kcl;
    sa.A_h[1] = Qfh; sa.A_l[1] = Qfl; sa.B_h[1] = Kfh; sa.B_l[1] = Kfl;
    sa.C[0] = sa.C[1] = nullptr;
    sa.Ph[0] = Ph0; sa.Pl[0] = Pl0; sa.Ph[1] = Ph1; sa.Pl[1] = Pl1;
    sa.psum[0] = ps0; sa.psum[1] = ps1;
    sa.linv[0] = sa.linv[1] = nullptr;
    sa.qm = qm; sa.qv = qv; sa.km = km; sa.kv = kv;
    sa.Klen = 256; sa.ldc = 0; sa.scoreKernel = 1;
    mma_gemm<<<dim3(NB / 128, MTOT / 128, 2), 256, MM_SMEM>>>(sa);

    // 4: reduce
    reduce_l2<<<dim3(NB / 256, 2), 256>>>(ps0, ps1, li0, li1);

    // 5: PV GEMMs
    MMArgs pa;
    pa.A_h[0] = Ph0; pa.A_l[0] = Pl0; pa.B_h[0] = Vtch; pa.B_l[0] = Vtcl;
    pa.A_h[1] = Ph1; pa.A_l[1] = Pl1; pa.B_h[1] = Vtfh; pa.B_l[1] = Vtfl;
    pa.C[0] = out; pa.C[1] = outS;
    pa.Ph[0] = pa.Ph[1] = nullptr; pa.Pl[0] = pa.Pl[1] = nullptr;
    pa.psum[0] = pa.psum[1] = nullptr;
    pa.linv[0] = li0; pa.linv[1] = li1;
    pa.qm = qm; pa.qv = qv; pa.km = km; pa.kv = kv;
    pa.Klen = 2048; pa.ldc = 256; pa.scoreKernel = 0;
    mma_gemm<<<dim3(NB / 128, DDIM / 128, 2), 256, MM_SMEM>>>(pa);

    // 6: combine
    add_out<<<NB * DDIM / 1024, 256>>>(out, outS);
}

// round 9
// speedup vs baseline: 5.2513x; 1.3643x over previous
#include <cuda_runtime.h>
#include <cuda_bf16.h>
#include <cuda_fp16.h>
#include <cstdint>

#define NB   12544
#define MTOT 2048
#define DDIM 256

typedef __nv_bfloat16 bf16;

// ---------------- scratch ----------------
__device__ __align__(16) bf16 g_x_hi[NB * DDIM], g_x_lo[NB * DDIM];
__device__ __align__(16) bf16 g_cm_hi[MTOT * DDIM], g_cm_lo[MTOT * DDIM];
__device__ __align__(16) bf16 g_sm_hi[MTOT * DDIM], g_sm_lo[MTOT * DDIM];
__device__ __align__(16) bf16 g_w_hi[6 * DDIM * DDIM], g_w_lo[6 * DDIM * DDIM];
__device__ __align__(16) bf16 g_Qc_hi[NB * DDIM], g_Qc_lo[NB * DDIM];
__device__ __align__(16) bf16 g_Qf_hi[NB * DDIM], g_Qf_lo[NB * DDIM];
__device__ __align__(16) bf16 g_Kc_hi[MTOT * DDIM], g_Kc_lo[MTOT * DDIM];
__device__ __align__(16) bf16 g_Kf_hi[MTOT * DDIM], g_Kf_lo[MTOT * DDIM];
__device__ __align__(16) __half g_Vtc[DDIM * MTOT];
__device__ __align__(16) __half g_Vtf[DDIM * MTOT];
__device__ __align__(16) __half g_P0[(size_t)NB * MTOT];
__device__ __align__(16) __half g_P1[(size_t)NB * MTOT];
__device__ float g_psum0[NB * 16], g_psum1[NB * 16];
__device__ float g_linv0[NB], g_linv1[NB];
__device__ float g_qm[NB], g_qv[NB], g_km[MTOT], g_kv[MTOT];
__device__ float g_OutS[NB * DDIM];

// ---------------- helpers ----------------
__device__ __forceinline__ uint32_t smem_u32(const void* p) {
    uint32_t a;
    asm("{ .reg .u64 t; cvta.to.shared.u64 t, %1; cvt.u32.u64 %0, t; }" : "=r"(a) : "l"(p));
    return a;
}
#define SWZ(o) ((o) ^ (((o) >> 3) & 0x70))

__device__ __forceinline__ void mma16816(float* c, const uint32_t* a, const uint32_t* b) {
    asm volatile(
        "mma.sync.aligned.m16n8k16.row.col.f32.bf16.bf16.f32 "
        "{%0,%1,%2,%3}, {%4,%5,%6,%7}, {%8,%9}, {%0,%1,%2,%3};"
        : "+f"(c[0]), "+f"(c[1]), "+f"(c[2]), "+f"(c[3])
        : "r"(a[0]), "r"(a[1]), "r"(a[2]), "r"(a[3]), "r"(b[0]), "r"(b[1]));
}
__device__ __forceinline__ void mma16816h(float* c, const uint32_t* a, const uint32_t* b) {
    asm volatile(
        "mma.sync.aligned.m16n8k16.row.col.f32.f16.f16.f32 "
        "{%0,%1,%2,%3}, {%4,%5,%6,%7}, {%8,%9}, {%0,%1,%2,%3};"
        : "+f"(c[0]), "+f"(c[1]), "+f"(c[2]), "+f"(c[3])
        : "r"(a[0]), "r"(a[1]), "r"(a[2]), "r"(a[3]), "r"(b[0]), "r"(b[1]));
}
__device__ __forceinline__ void ldsm_x4(uint32_t* r, uint32_t addr) {
    asm volatile("ldmatrix.sync.aligned.m8n8.x4.shared.b16 {%0,%1,%2,%3}, [%4];"
                 : "=r"(r[0]), "=r"(r[1]), "=r"(r[2]), "=r"(r[3]) : "r"(addr));
}
__device__ __forceinline__ void cp16(uint32_t dst, const void* src) {
    asm volatile("cp.async.cg.shared.global [%0], [%1], 16;" :: "r"(dst), "l"(src));
}
#define CP_COMMIT() asm volatile("cp.async.commit_group;" ::: "memory")
#define CP_WAIT1()  asm volatile("cp.async.wait_group 1;" ::: "memory")

// packed tile addressing: 128 logical rows x 64 bytes -> 64 smem rows x 128B
__device__ __forceinline__ uint32_t toff(int row, int cb) {
    return SWZ((uint32_t)((row & 63) * 128 + ((row >> 6) << 6) + cb));
}
__device__ __forceinline__ void split1(float a, bf16& h, bf16& l) {
    h = __float2bfloat16(a);
    l = __float2bfloat16(a - __bfloat162float(h));
}

#define STG_BYTES 32768
#define MM_SMEM (3 * STG_BYTES)
#define PV_STG 16384
#define PV_SMEM (3 * PV_STG)

// ---------------- fp32 -> bf16 hi/lo conversion (9 arrays) ----------------
struct SplitArgs {
    const float* src[9];
    bf16 *h[9], *l[9];
    int nblk[9];
};
__global__ __launch_bounds__(256) void split_all(SplitArgs a) {
    int bx = blockIdx.x, z = 0;
    while (bx >= a.nblk[z]) { bx -= a.nblk[z]; z++; }
    size_t i = ((size_t)bx * 256 + threadIdx.x) * 4;
    float4 v = *(const float4*)(a.src[z] + i);
    bf16 h0, l0, h1, l1, h2, l2, h3, l3;
    split1(v.x, h0, l0); split1(v.y, h1, l1);
    split1(v.z, h2, l2); split1(v.w, h3, l3);
    __nv_bfloat162 ha; ha.x = h0; ha.y = h1;
    __nv_bfloat162 hb; hb.x = h2; hb.y = h3;
    __nv_bfloat162 la; la.x = l0; la.y = l1;
    __nv_bfloat162 lb; lb.x = l2; lb.y = l3;
    *(__nv_bfloat162*)(a.h[z] + i) = ha; *(__nv_bfloat162*)(a.h[z] + i + 2) = hb;
    *(__nv_bfloat162*)(a.l[z] + i) = la; *(__nv_bfloat162*)(a.l[z] + i + 2) = lb;
}

// ---------------- split-bf16 3-product mainloop ----------------
#define MMA_MAINLOOP()                                                          \
    float acc[2][8][4];                                                         \
    _Pragma("unroll")                                                           \
    for (int rf = 0; rf < 2; rf++)                                              \
        _Pragma("unroll")                                                       \
        for (int nt = 0; nt < 8; nt++)                                          \
            _Pragma("unroll")                                                   \
            for (int c = 0; c < 4; c++) acc[rf][nt][c] = 0.f;                   \
    const int a_row = wm * 32 + (lane & 15);                                    \
    const int a_kb  = (lane >> 4) * 16;                                         \
    const int b_row = wn * 64 + ((lane >> 4) << 3) + (lane & 7);                \
    const int b_kb  = ((lane >> 3) & 1) * 16;                                   \
    const int lr0 = tid >> 2;                                                   \
    const int lg  = (tid & 3);                                                  \
    const int nIter = Klen >> 5;                                                \
    auto issue = [&](int buf, int k0) {                                         \
        uint32_t base = sb + buf * STG_BYTES;                                   \
        _Pragma("unroll")                                                       \
        for (int h = 0; h < 2; h++) {                                           \
            int r = lr0 + h * 64;                                               \
            uint32_t off = toff(r, lg * 16);                                    \
            size_t ga = (size_t)(mBase + r) * Klen + k0 + lg * 8;               \
            size_t gb = (size_t)(nBase + r) * Klen + k0 + lg * 8;               \
            cp16(base + off,         Ah + ga);                                  \
            cp16(base + 8192 + off,  Al + ga);                                  \
            cp16(base + 16384 + off, Bh + gb);                                  \
            cp16(base + 24576 + off, Bl + gb);                                  \
        }                                                                       \
    };                                                                          \
    issue(0, 0); CP_COMMIT();                                                   \
    issue(1, 32); CP_COMMIT();                                                  \
    int buf = 0;                                                                \
    for (int it = 0; it < nIter; it++) {                                        \
        CP_WAIT1();                                                             \
        __syncthreads();                                                        \
        if (it + 2 < nIter) issue((it + 2) % 3, (it + 2) * 32);                 \
        CP_COMMIT();                                                            \
        const uint32_t sbase = sb + buf * STG_BYTES;                            \
        _Pragma("unroll")                                                       \
        for (int ks = 0; ks < 2; ks++) {                                        \
            uint32_t ah[2][4], al[2][4];                                        \
            _Pragma("unroll")                                                   \
            for (int rf = 0; rf < 2; rf++) {                                    \
                uint32_t off = toff(a_row + rf * 16, ks * 32 + a_kb);           \
                ldsm_x4(ah[rf], sbase + off);                                   \
                ldsm_x4(al[rf], sbase + 8192 + off);                            \
            }                                                                   \
            _Pragma("unroll")                                                   \
            for (int ntp = 0; ntp < 4; ntp++) {                                 \
                uint32_t off = toff(b_row + ntp * 16, ks * 32 + b_kb);          \
                uint32_t bh4[4], bl4[4];                                        \
                ldsm_x4(bh4, sbase + 16384 + off);                              \
                ldsm_x4(bl4, sbase + 24576 + off);                              \
                _Pragma("unroll")                                               \
                for (int rf = 0; rf < 2; rf++) {                                \
                    mma16816(acc[rf][2 * ntp],     ah[rf], bh4);                \
                    mma16816(acc[rf][2 * ntp],     ah[rf], bl4);                \
                    mma16816(acc[rf][2 * ntp],     al[rf], bh4);                \
                    mma16816(acc[rf][2 * ntp + 1], ah[rf], bh4 + 2);            \
                    mma16816(acc[rf][2 * ntp + 1], ah[rf], bl4 + 2);            \
                    mma16816(acc[rf][2 * ntp + 1], al[rf], bh4 + 2);            \
                }                                                               \
            }                                                                   \
        }                                                                       \
        buf++; if (buf == 3) buf = 0;                                           \
    }

// ---------------- projection GEMMs via MMA ----------------
struct ProjM {
    const bf16 *A_h[6], *A_l[6], *B_h[6], *B_l[6];
    bf16 *Oh[6], *Ol[6];
    __half* OT[6];
    int mx[6], trans[6];
};
__global__ __launch_bounds__(256, 2) void mma_proj(ProjM p) {
    extern __shared__ char sm[];
    const int z = blockIdx.z;
    if ((int)blockIdx.x >= p.mx[z]) return;
    const uint32_t sb = smem_u32(sm);
    const bf16* __restrict__ Ah = p.A_h[z];
    const bf16* __restrict__ Al = p.A_l[z];
    const bf16* __restrict__ Bh = p.B_h[z];
    const bf16* __restrict__ Bl = p.B_l[z];
    const int Klen = 256;
    const int tid = threadIdx.x;
    const int wid = tid >> 5, lane = tid & 31;
    const int wm = wid & 3, wn = wid >> 2;
    const int mBase = blockIdx.x * 128;
    const int nBase = blockIdx.y * 128;

    MMA_MAINLOOP();

    const int gID = lane >> 2, tig = lane & 3;

    if (p.trans[z]) {
        __half* __restrict__ OT = p.OT[z];
#pragma unroll
        for (int rf = 0; rf < 2; rf++) {
            int r0 = mBase + wm * 32 + rf * 16 + gID;
#pragma unroll
            for (int nt = 0; nt < 8; nt++) {
                int col = nBase + wn * 64 + nt * 8 + tig * 2;
#pragma unroll
                for (int c = 0; c < 4; c++) {
                    int row = r0 + (c >> 1) * 8;
                    int cc = col + (c & 1);
                    OT[(size_t)cc * MTOT + row] = __float2half(acc[rf][nt][c]);
                }
            }
        }
        return;
    }

    // staged coalesced bf16 hi/lo store
    __syncthreads();
    char* smHi = sm;
    char* smLo = sm + 32768;
    bf16* __restrict__ Oh = p.Oh[z];
    bf16* __restrict__ Ol = p.Ol[z];
#pragma unroll
    for (int rf = 0; rf < 2; rf++) {
#pragma unroll
        for (int nt = 0; nt < 8; nt++) {
            int chunk = wn * 8 + nt;
#pragma unroll
            for (int half = 0; half < 2; half++) {
                int rl = wm * 32 + rf * 16 + half * 8 + gID;
                bf16 h0, l0, h1, l1;
                split1(acc[rf][nt][half * 2 + 0], h0, l0);
                split1(acc[rf][nt][half * 2 + 1], h1, l1);
                __nv_bfloat162 hh; hh.x = h0; hh.y = h1;
                __nv_bfloat162 ll; ll.x = l0; ll.y = l1;
                uint32_t addr = rl * 256 + ((chunk ^ (rl & 15)) << 4) + tig * 4;
                *(__nv_bfloat162*)(smHi + addr) = hh;
                *(__nv_bfloat162*)(smLo + addr) = ll;
            }
        }
    }
    __syncthreads();
#pragma unroll
    for (int it = 0; it < 8; it++) {
        int idx = it * 256 + tid;
        int r = idx >> 4, c = idx & 15;
        uint32_t src = r * 256 + ((c ^ (r & 15)) << 4);
        size_t dst = (size_t)(mBase + r) * 256 + nBase + c * 8;
        *(uint4*)(Oh + dst) = *(uint4*)(smHi + src);
        *(uint4*)(Ol + dst) = *(uint4*)(smLo + src);
    }
}

// ---------------- merged row stats ----------------
__global__ __launch_bounds__(256) void row_stats2(
    const bf16* __restrict__ Qh, const bf16* __restrict__ Ql,
    const bf16* __restrict__ Kh, const bf16* __restrict__ Kl,
    float* __restrict__ qm, float* __restrict__ qv,
    float* __restrict__ km, float* __restrict__ kv) {
    int row = blockIdx.x * 8 + (threadIdx.x >> 5);
    const int lane = threadIdx.x & 31;
    const bf16 *Xh, *Xl;
    float *mean, *var;
    if (row < NB) { Xh = Qh; Xl = Ql; mean = qm; var = qv; }
    else { row -= NB; Xh = Kh; Xl = Kl; mean = km; var = kv; }
    const size_t base = (size_t)row * 256;
    float s = 0.f, ss = 0.f;
#pragma unroll
    for (int c = 0; c < 256; c += 32) {
        float v = __bfloat162float(Xh[base + c + lane]) + __bfloat162float(Xl[base + c + lane]);
        s += v; ss += v * v;
    }
#pragma unroll
    for (int o = 16; o > 0; o >>= 1) {
        s += __shfl_xor_sync(0xffffffffu, s, o);
        ss += __shfl_xor_sync(0xffffffffu, ss, o);
    }
    if (lane == 0) {
        float m = s * (1.f / 256.f);
        mean[row] = m;
        var[row] = (ss - 256.f * m * m) * (1.f / 255.f);
    }
}

// ---------------- score MMA GEMM (3-product bf16, fp16 P out) ----------------
struct MMArgs {
    const bf16 *A_h[2], *A_l[2], *B_h[2], *B_l[2];
    __half* P[2];
    float* psum[2];
    const float *qm, *qv, *km, *kv;
};

__global__ __launch_bounds__(256, 2) void mma_gemm(MMArgs g) {
    extern __shared__ char sm[];
    const uint32_t sb = smem_u32(sm);
    const int z = blockIdx.z;
    const bf16* __restrict__ Ah = g.A_h[z];
    const bf16* __restrict__ Al = g.A_l[z];
    const bf16* __restrict__ Bh = g.B_h[z];
    const bf16* __restrict__ Bl = g.B_l[z];
    const int Klen = 256;
    const int tid = threadIdx.x;
    const int wid = tid >> 5, lane = tid & 31;
    const int wm = wid & 3, wn = wid >> 2;
    const int mBase = blockIdx.x * 128;
    const int nBase = blockIdx.y * 128;

    MMA_MAINLOOP();

    const int gID = lane >> 2, tig = lane & 3;
    const int mode = (z == 0) ? 0 : 1;
    char* smP = sm;
    float* rs_sm = (float*)(sm + 32768);
    float rs[2][2];
    rs[0][0] = rs[0][1] = rs[1][0] = rs[1][1] = 0.f;

    __syncthreads();
#pragma unroll
    for (int rf = 0; rf < 2; rf++) {
        int r0 = mBase + wm * 32 + rf * 16 + gID;
        int r1 = r0 + 8;
        float qm0 = 0.f, qv0 = 0.f, qm1 = 0.f, qv1 = 0.f;
        if (mode == 1) { qm0 = g.qm[r0]; qv0 = g.qv[r0]; qm1 = g.qm[r1]; qv1 = g.qv[r1]; }
#pragma unroll
        for (int nt = 0; nt < 8; nt++) {
            int col = nBase + wn * 64 + nt * 8 + tig * 2;
            float v0 = acc[rf][nt][0], v1 = acc[rf][nt][1];
            float v2 = acc[rf][nt][2], v3 = acc[rf][nt][3];
            if (mode == 0) {
                v0 = __expf(v0 * 0.0625f); v1 = __expf(v1 * 0.0625f);
                v2 = __expf(v2 * 0.0625f); v3 = __expf(v3 * 0.0625f);
            } else {
                float km0 = g.km[col], kv0 = g.kv[col];
                float km1 = g.km[col + 1], kv1 = g.kv[col + 1];
#define SSIM(dot, QM, QV, KM, KV)                                              \
    ({ float mp = (QM) * (KM);                                                 \
       float cov = ((dot) - 256.f * mp) * (1.f / 255.f);                       \
       float num = (2.f * mp + 0.01f) * (2.f * cov + 0.03f);                   \
       float den = ((QM) * (QM) + (KM) * (KM) + 0.01f) * ((QV) + (KV) + 0.03f);\
       num / (den + 1e-8f); })
                v0 = __expf(SSIM(v0, qm0, qv0, km0, kv0));
                v1 = __expf(SSIM(v1, qm0, qv0, km1, kv1));
                v2 = __expf(SSIM(v2, qm1, qv1, km0, kv0));
                v3 = __expf(SSIM(v3, qm1, qv1, km1, kv1));
            }
            rs[rf][0] += v0 + v1;
            rs[rf][1] += v2 + v3;

            int chunk = wn * 8 + nt;
            int rl0 = wm * 32 + rf * 16 + gID;
            int rl1 = rl0 + 8;
            __half2 p0; p0.x = __float2half(v0); p0.y = __float2half(v1);
            __half2 p1; p1.x = __float2half(v2); p1.y = __float2half(v3);
            uint32_t a0 = rl0 * 256 + ((chunk ^ (rl0 & 15)) << 4) + tig * 4;
            uint32_t a1 = rl1 * 256 + ((chunk ^ (rl1 & 15)) << 4) + tig * 4;
            *(__half2*)(smP + a0) = p0;
            *(__half2*)(smP + a1) = p1;
        }
    }

#pragma unroll
    for (int rf = 0; rf < 2; rf++)
#pragma unroll
        for (int h = 0; h < 2; h++) {
            rs[rf][h] += __shfl_xor_sync(0xffffffffu, rs[rf][h], 1);
            rs[rf][h] += __shfl_xor_sync(0xffffffffu, rs[rf][h], 2);
        }
    __syncthreads();
    if (tig == 0) {
#pragma unroll
        for (int rf = 0; rf < 2; rf++)
#pragma unroll
            for (int h = 0; h < 2; h++)
                rs_sm[wn * 128 + wm * 32 + rf * 16 + h * 8 + gID] = rs[rf][h];
    }
    __syncthreads();

    __half* __restrict__ P = g.P[z];
#pragma unroll
    for (int it = 0; it < 8; it++) {
        int idx = it * 256 + tid;
        int r = idx >> 4, c = idx & 15;
        uint32_t src = r * 256 + ((c ^ (r & 15)) << 4);
        size_t dst = (size_t)(mBase + r) * 2048 + nBase + c * 8;
        *(uint4*)(P + dst) = *(uint4*)(smP + src);
    }
    if (tid < 128)
        g.psum[z][(size_t)(mBase + tid) * 16 + blockIdx.y] = rs_sm[tid] + rs_sm[128 + tid];
}

// ---------------- PV GEMM: single-product fp16 ----------------
struct PVArgs {
    const __half *A[2], *B[2];
    float* C[2];
    const float* linv[2];
};

__global__ __launch_bounds__(256, 2) void pv_gemm(PVArgs g) {
    extern __shared__ char sm[];
    const uint32_t sb = smem_u32(sm);
    const int z = blockIdx.z;
    const __half* __restrict__ A = g.A[z];
    const __half* __restrict__ B = g.B[z];
    const int Klen = 2048;
    const int tid = threadIdx.x;
    const int wid = tid >> 5, lane = tid & 31;
    const int wm = wid & 3, wn = wid >> 2;
    const int mBase = blockIdx.x * 128;
    const int nBase = blockIdx.y * 128;

    float acc[2][8][4];
#pragma unroll
    for (int rf = 0; rf < 2; rf++)
#pragma unroll
        for (int nt = 0; nt < 8; nt++)
#pragma unroll
            for (int c = 0; c < 4; c++) acc[rf][nt][c] = 0.f;

    const int a_row = wm * 32 + (lane & 15);
    const int a_kb  = (lane >> 4) * 16;
    const int b_row = wn * 64 + ((lane >> 4) << 3) + (lane & 7);
    const int b_kb  = ((lane >> 3) & 1) * 16;
    const int lr0 = tid >> 2;
    const int lg  = (tid & 3);
    const int nIter = Klen >> 5;

    auto issue = [&](int buf, int k0) {
        uint32_t base = sb + buf * PV_STG;
#pragma unroll
        for (int h = 0; h < 2; h++) {
            int r = lr0 + h * 64;
            uint32_t off = toff(r, lg * 16);
            size_t ga = (size_t)(mBase + r) * Klen + k0 + lg * 8;
            size_t gb = (size_t)(nBase + r) * Klen + k0 + lg * 8;
            cp16(base + off,        A + ga);
            cp16(base + 8192 + off, B + gb);
        }
    };

    issue(0, 0); CP_COMMIT();
    issue(1, 32); CP_COMMIT();

    int buf = 0;
    for (int it = 0; it < nIter; it++) {
        CP_WAIT1();
        __syncthreads();
        if (it + 2 < nIter) issue((it + 2) % 3, (it + 2) * 32);
        CP_COMMIT();

        const uint32_t sbase = sb + buf * PV_STG;
#pragma unroll
        for (int ks = 0; ks < 2; ks++) {
            uint32_t af[2][4];
#pragma unroll
            for (int rf = 0; rf < 2; rf++)
                ldsm_x4(af[rf], sbase + toff(a_row + rf * 16, ks * 32 + a_kb));
#pragma unroll
            for (int ntp = 0; ntp < 4; ntp++) {
                uint32_t bf4[4];
                ldsm_x4(bf4, sbase + 8192 + toff(b_row + ntp * 16, ks * 32 + b_kb));
#pragma unroll
                for (int rf = 0; rf < 2; rf++) {
                    mma16816h(acc[rf][2 * ntp],     af[rf], bf4);
                    mma16816h(acc[rf][2 * ntp + 1], af[rf], bf4 + 2);
                }
            }
        }
        buf++; if (buf == 3) buf = 0;
    }

    const int gID = lane >> 2, tig = lane & 3;
    float* __restrict__ C = g.C[z];
    const float* __restrict__ linv = g.linv[z];
#pragma unroll
    for (int rf = 0; rf < 2; rf++) {
        int r0 = mBase + wm * 32 + rf * 16 + gID;
        int r1 = r0 + 8;
        float i0 = linv[r0], i1 = linv[r1];
#pragma unroll
        for (int nt = 0; nt < 8; nt++) {
            int col = nBase + wn * 64 + nt * 8 + tig * 2;
            *(float2*)(C + (size_t)r0 * 256 + col) =
                make_float2(acc[rf][nt][0] * i0, acc[rf][nt][1] * i0);
            *(float2*)(C + (size_t)r1 * 256 + col) =
                make_float2(acc[rf][nt][2] * i1, acc[rf][nt][3] * i1);
        }
    }
}

// ---------------- reduce partial sums -> 1/l ----------------
__global__ __launch_bounds__(256) void reduce_l2(const float* __restrict__ ps0,
                                                 const float* __restrict__ ps1,
                                                 float* __restrict__ li0,
                                                 float* __restrict__ li1) {
    int row = blockIdx.x * 256 + threadIdx.x;
    const float* p = (blockIdx.y == 0 ? ps0 : ps1) + (size_t)row * 16;
    float s = 0.f;
#pragma unroll
    for (int i = 0; i < 16; i++) s += p[i];
    (blockIdx.y == 0 ? li0 : li1)[row] = 1.f / s;
}

// ---------------- out += outS ----------------
__global__ __launch_bounds__(256) void add_out(float* __restrict__ out,
                                               const float* __restrict__ add) {
    int i = (blockIdx.x * 256 + threadIdx.x) * 4;
    float4 a = *(float4*)(out + i);
    float4 b = *(const float4*)(add + i);
    a.x += b.x; a.y += b.y; a.z += b.z; a.w += b.w;
    *(float4*)(out + i) = a;
}

// ---------------- launch ----------------
extern "C" void kernel_launch(void* const* d_in, const int* in_sizes, int n_in,
                              void* d_out, int out_size) {
    const float* x    = (const float*)d_in[0];
    const float* chm  = (const float*)d_in[1];
    const float* chwq = (const float*)d_in[2];
    const float* chwk = (const float*)d_in[3];
    const float* chwv = (const float*)d_in[4];
    const float* spm  = (const float*)d_in[5];
    const float* spwq = (const float*)d_in[6];
    const float* spwk = (const float*)d_in[7];
    const float* spwv = (const float*)d_in[8];
    float* out = (float*)d_out;

    bf16 *xh, *xl, *cmh, *cml, *smh, *sml, *wh, *wl;
    bf16 *Qch, *Qcl, *Qfh, *Qfl, *Kch, *Kcl, *Kfh, *Kfl;
    __half *Vtc, *Vtf, *P0, *P1;
    float *ps0, *ps1, *li0, *li1, *qm, *qv, *km, *kv, *outS;
    cudaGetSymbolAddress((void**)&xh, g_x_hi);    cudaGetSymbolAddress((void**)&xl, g_x_lo);
    cudaGetSymbolAddress((void**)&cmh, g_cm_hi);  cudaGetSymbolAddress((void**)&cml, g_cm_lo);
    cudaGetSymbolAddress((void**)&smh, g_sm_hi);  cudaGetSymbolAddress((void**)&sml, g_sm_lo);
    cudaGetSymbolAddress((void**)&wh, g_w_hi);    cudaGetSymbolAddress((void**)&wl, g_w_lo);
    cudaGetSymbolAddress((void**)&Qch, g_Qc_hi);  cudaGetSymbolAddress((void**)&Qcl, g_Qc_lo);
    cudaGetSymbolAddress((void**)&Qfh, g_Qf_hi);  cudaGetSymbolAddress((void**)&Qfl, g_Qf_lo);
    cudaGetSymbolAddress((void**)&Kch, g_Kc_hi);  cudaGetSymbolAddress((void**)&Kcl, g_Kc_lo);
    cudaGetSymbolAddress((void**)&Kfh, g_Kf_hi);  cudaGetSymbolAddress((void**)&Kfl, g_Kf_lo);
    cudaGetSymbolAddress((void**)&Vtc, g_Vtc);    cudaGetSymbolAddress((void**)&Vtf, g_Vtf);
    cudaGetSymbolAddress((void**)&P0, g_P0);      cudaGetSymbolAddress((void**)&P1, g_P1);
    cudaGetSymbolAddress((void**)&ps0, g_psum0);  cudaGetSymbolAddress((void**)&ps1, g_psum1);
    cudaGetSymbolAddress((void**)&li0, g_linv0);  cudaGetSymbolAddress((void**)&li1, g_linv1);
    cudaGetSymbolAddress((void**)&qm, g_qm);      cudaGetSymbolAddress((void**)&qv, g_qv);
    cudaGetSymbolAddress((void**)&km, g_km);      cudaGetSymbolAddress((void**)&kv, g_kv);
    cudaGetSymbolAddress((void**)&outS, g_OutS);

    cudaFuncSetAttribute(mma_gemm, cudaFuncAttributeMaxDynamicSharedMemorySize, MM_SMEM);
    cudaFuncSetAttribute(mma_proj, cudaFuncAttributeMaxDynamicSharedMemorySize, MM_SMEM);
    cudaFuncSetAttribute(pv_gemm, cudaFuncAttributeMaxDynamicSharedMemorySize, PV_SMEM);

    // 0: fp32 -> bf16 hi/lo
    const int WSZ = DDIM * DDIM;
    SplitArgs sp;
    sp.src[0] = x;    sp.h[0] = xh;           sp.l[0] = xl;           sp.nblk[0] = NB * DDIM / 1024;
    sp.src[1] = chm;  sp.h[1] = cmh;          sp.l[1] = cml;          sp.nblk[1] = MTOT * DDIM / 1024;
    sp.src[2] = spm;  sp.h[2] = smh;          sp.l[2] = sml;          sp.nblk[2] = MTOT * DDIM / 1024;
    sp.src[3] = spwq; sp.h[3] = wh + 0 * WSZ; sp.l[3] = wl + 0 * WSZ; sp.nblk[3] = WSZ / 1024;
    sp.src[4] = chwq; sp.h[4] = wh + 1 * WSZ; sp.l[4] = wl + 1 * WSZ; sp.nblk[4] = WSZ / 1024;
    sp.src[5] = spwk; sp.h[5] = wh + 2 * WSZ; sp.l[5] = wl + 2 * WSZ; sp.nblk[5] = WSZ / 1024;
    sp.src[6] = chwk; sp.h[6] = wh + 3 * WSZ; sp.l[6] = wl + 3 * WSZ; sp.nblk[6] = WSZ / 1024;
    sp.src[7] = chwv; sp.h[7] = wh + 4 * WSZ; sp.l[7] = wl + 4 * WSZ; sp.nblk[7] = WSZ / 1024;
    sp.src[8] = spwv; sp.h[8] = wh + 5 * WSZ; sp.l[8] = wl + 5 * WSZ; sp.nblk[8] = WSZ / 1024;
    int totBlk = 0;
    for (int i = 0; i < 9; i++) totBlk += sp.nblk[i];
    split_all<<<totBlk, 256>>>(sp);

    // 1: projections
    ProjM pm;
    for (int i = 0; i < 6; i++) pm.OT[i] = nullptr;
    pm.A_h[0] = xh;  pm.A_l[0] = xl;  pm.B_h[0] = wh + 0 * WSZ; pm.B_l[0] = wl + 0 * WSZ;
    pm.Oh[0] = Qfh;  pm.Ol[0] = Qfl;  pm.mx[0] = NB / 128;      pm.trans[0] = 0;
    pm.A_h[1] = xh;  pm.A_l[1] = xl;  pm.B_h[1] = wh + 1 * WSZ; pm.B_l[1] = wl + 1 * WSZ;
    pm.Oh[1] = Qch;  pm.Ol[1] = Qcl;  pm.mx[1] = NB / 128;      pm.trans[1] = 0;
    pm.A_h[2] = smh; pm.A_l[2] = sml; pm.B_h[2] = wh + 2 * WSZ; pm.B_l[2] = wl + 2 * WSZ;
    pm.Oh[2] = Kfh;  pm.Ol[2] = Kfl;  pm.mx[2] = MTOT / 128;    pm.trans[2] = 0;
    pm.A_h[3] = cmh; pm.A_l[3] = cml; pm.B_h[3] = wh + 3 * WSZ; pm.B_l[3] = wl + 3 * WSZ;
    pm.Oh[3] = Kch;  pm.Ol[3] = Kcl;  pm.mx[3] = MTOT / 128;    pm.trans[3] = 0;
    pm.A_h[4] = cmh; pm.A_l[4] = cml; pm.B_h[4] = wh + 4 * WSZ; pm.B_l[4] = wl + 4 * WSZ;
    pm.Oh[4] = nullptr; pm.Ol[4] = nullptr; pm.OT[4] = Vtc; pm.mx[4] = MTOT / 128; pm.trans[4] = 1;
    pm.A_h[5] = smh; pm.A_l[5] = sml; pm.B_h[5] = wh + 5 * WSZ; pm.B_l[5] = wl + 5 * WSZ;
    pm.Oh[5] = nullptr; pm.Ol[5] = nullptr; pm.OT[5] = Vtf; pm.mx[5] = MTOT / 128; pm.trans[5] = 1;
    mma_proj<<<dim3(NB / 128, 2, 6), 256, MM_SMEM>>>(pm);

    // 2: row stats
    row_stats2<<<(NB + MTOT) / 8, 256>>>(Qfh, Qfl, Kfh, Kfl, qm, qv, km, kv);

    // 3: score GEMMs (profiled)
    MMArgs sa;
    sa.A_h[0] = Qch; sa.A_l[0] = Qcl; sa.B_h[0] = Kch; sa.B_l[0] = Kcl;
    sa.A_h[1] = Qfh; sa.A_l[1] = Qfl; sa.B_h[1] = Kfh; sa.B_l[1] = Kfl;
    sa.P[0] = P0; sa.P[1] = P1;
    sa.psum[0] = ps0; sa.psum[1] = ps1;
    sa.qm = qm; sa.qv = qv; sa.km = km; sa.kv = kv;
    mma_gemm<<<dim3(NB / 128, MTOT / 128, 2), 256, MM_SMEM>>>(sa);

    // 4: reduce
    reduce_l2<<<dim3(NB / 256, 2), 256>>>(ps0, ps1, li0, li1);

    // 5: PV GEMMs (fp16 single product)
    PVArgs pa;
    pa.A[0] = P0; pa.B[0] = Vtc; pa.C[0] = out;  pa.linv[0] = li0;
    pa.A[1] = P1; pa.B[1] = Vtf; pa.C[1] = outS; pa.linv[1] = li1;
    pv_gemm<<<dim3(NB / 128, DDIM / 128, 2), 256, PV_SMEM>>>(pa);

    // 6: combine
    add_out<<<NB * DDIM / 1024, 256>>>(out, outS);
}

// round 10
// speedup vs baseline: 6.1055x; 1.1627x over previous
#include <cuda_runtime.h>
#include <cuda_fp16.h>
#include <cstdint>

#define NB   12544
#define MTOT 2048
#define DDIM 256

typedef __half h16;

// ---------------- scratch ----------------
__device__ __align__(16) h16 g_x_hi[NB * DDIM], g_x_lo[NB * DDIM];
__device__ __align__(16) h16 g_cm_hi[MTOT * DDIM], g_cm_lo[MTOT * DDIM];
__device__ __align__(16) h16 g_sm_hi[MTOT * DDIM], g_sm_lo[MTOT * DDIM];
__device__ __align__(16) h16 g_w_hi[6 * DDIM * DDIM], g_w_lo[6 * DDIM * DDIM];
__device__ __align__(16) h16 g_Qc_hi[NB * DDIM], g_Qc_lo[NB * DDIM];
__device__ __align__(16) h16 g_Qf_hi[NB * DDIM], g_Qf_lo[NB * DDIM];
__device__ __align__(16) h16 g_Kc_hi[MTOT * DDIM], g_Kc_lo[MTOT * DDIM];
__device__ __align__(16) h16 g_Kf_hi[MTOT * DDIM], g_Kf_lo[MTOT * DDIM];
__device__ __align__(16) h16 g_Vtc[DDIM * MTOT];
__device__ __align__(16) h16 g_Vtf[DDIM * MTOT];
__device__ __align__(16) h16 g_P0[(size_t)NB * MTOT];
__device__ __align__(16) h16 g_P1[(size_t)NB * MTOT];
__device__ float g_psum0[NB * 16], g_psum1[NB * 16];
__device__ float g_linv0[NB], g_linv1[NB];
__device__ float g_qm[NB], g_qv[NB], g_km[MTOT], g_kv[MTOT];
__device__ float g_OutS[NB * DDIM];

// ---------------- helpers ----------------
__device__ __forceinline__ uint32_t smem_u32(const void* p) {
    uint32_t a;
    asm("{ .reg .u64 t; cvta.to.shared.u64 t, %1; cvt.u32.u64 %0, t; }" : "=r"(a) : "l"(p));
    return a;
}
#define SWZ(o) ((o) ^ (((o) >> 3) & 0x70))

__device__ __forceinline__ void mma16816h(float* c, const uint32_t* a, const uint32_t* b) {
    asm volatile(
        "mma.sync.aligned.m16n8k16.row.col.f32.f16.f16.f32 "
        "{%0,%1,%2,%3}, {%4,%5,%6,%7}, {%8,%9}, {%0,%1,%2,%3};"
        : "+f"(c[0]), "+f"(c[1]), "+f"(c[2]), "+f"(c[3])
        : "r"(a[0]), "r"(a[1]), "r"(a[2]), "r"(a[3]), "r"(b[0]), "r"(b[1]));
}
__device__ __forceinline__ void ldsm_x4(uint32_t* r, uint32_t addr) {
    asm volatile("ldmatrix.sync.aligned.m8n8.x4.shared.b16 {%0,%1,%2,%3}, [%4];"
                 : "=r"(r[0]), "=r"(r[1]), "=r"(r[2]), "=r"(r[3]) : "r"(addr));
}
__device__ __forceinline__ void cp16(uint32_t dst, const void* src) {
    asm volatile("cp.async.cg.shared.global [%0], [%1], 16;" :: "r"(dst), "l"(src));
}
#define CP_COMMIT() asm volatile("cp.async.commit_group;" ::: "memory")
#define CP_WAIT1()  asm volatile("cp.async.wait_group 1;" ::: "memory")

// packed tile addressing: 128 logical rows x 64 bytes -> 64 smem rows x 128B
__device__ __forceinline__ uint32_t toff(int row, int cb) {
    return SWZ((uint32_t)((row & 63) * 128 + ((row >> 6) << 6) + cb));
}
__device__ __forceinline__ void split1(float a, h16& h, h16& l) {
    h = __float2half(a);
    l = __float2half(a - __half2float(h));
}

#define STG_BYTES 32768
#define MM_SMEM (3 * STG_BYTES)
#define SC_STG 24576
#define SC_SMEM (3 * SC_STG)
#define PV_STG 16384
#define PV_SMEM (3 * PV_STG)

// ---------------- fp32 -> fp16 hi/lo conversion (9 arrays) ----------------
struct SplitArgs {
    const float* src[9];
    h16 *h[9], *l[9];
    int nblk[9];
};
__global__ __launch_bounds__(256) void split_all(SplitArgs a) {
    int bx = blockIdx.x, z = 0;
    while (bx >= a.nblk[z]) { bx -= a.nblk[z]; z++; }
    size_t i = ((size_t)bx * 256 + threadIdx.x) * 4;
    float4 v = *(const float4*)(a.src[z] + i);
    h16 h0, l0, h1, l1, h2, l2, h3, l3;
    split1(v.x, h0, l0); split1(v.y, h1, l1);
    split1(v.z, h2, l2); split1(v.w, h3, l3);
    __half2 ha; ha.x = h0; ha.y = h1;
    __half2 hb; hb.x = h2; hb.y = h3;
    __half2 la; la.x = l0; la.y = l1;
    __half2 lb; lb.x = l2; lb.y = l3;
    *(__half2*)(a.h[z] + i) = ha; *(__half2*)(a.h[z] + i + 2) = hb;
    *(__half2*)(a.l[z] + i) = la; *(__half2*)(a.l[z] + i + 2) = lb;
}

// ---------------- fp16-split 3-product mainloop (projections) ----------------
#define MMA_MAINLOOP3()                                                         \
    float acc[2][8][4];                                                         \
    _Pragma("unroll")                                                           \
    for (int rf = 0; rf < 2; rf++)                                              \
        _Pragma("unroll")                                                       \
        for (int nt = 0; nt < 8; nt++)                                          \
            _Pragma("unroll")                                                   \
            for (int c = 0; c < 4; c++) acc[rf][nt][c] = 0.f;                   \
    const int a_row = wm * 32 + (lane & 15);                                    \
    const int a_kb  = (lane >> 4) * 16;                                         \
    const int b_row = wn * 64 + ((lane >> 4) << 3) + (lane & 7);                \
    const int b_kb  = ((lane >> 3) & 1) * 16;                                   \
    const int lr0 = tid >> 2;                                                   \
    const int lg  = (tid & 3);                                                  \
    const int nIter = Klen >> 5;                                                \
    auto issue = [&](int buf, int k0) {                                         \
        uint32_t base = sb + buf * STG_BYTES;                                   \
        _Pragma("unroll")                                                       \
        for (int h = 0; h < 2; h++) {                                           \
            int r = lr0 + h * 64;                                               \
            uint32_t off = toff(r, lg * 16);                                    \
            size_t ga = (size_t)(mBase + r) * Klen + k0 + lg * 8;               \
            size_t gb = (size_t)(nBase + r) * Klen + k0 + lg * 8;               \
            cp16(base + off,         Ah + ga);                                  \
            cp16(base + 8192 + off,  Al + ga);                                  \
            cp16(base + 16384 + off, Bh + gb);                                  \
            cp16(base + 24576 + off, Bl + gb);                                  \
        }                                                                       \
    };                                                                          \
    issue(0, 0); CP_COMMIT();                                                   \
    issue(1, 32); CP_COMMIT();                                                  \
    int buf = 0;                                                                \
    for (int it = 0; it < nIter; it++) {                                        \
        CP_WAIT1();                                                             \
        __syncthreads();                                                        \
        if (it + 2 < nIter) issue((it + 2) % 3, (it + 2) * 32);                 \
        CP_COMMIT();                                                            \
        const uint32_t sbase = sb + buf * STG_BYTES;                            \
        _Pragma("unroll")                                                       \
        for (int ks = 0; ks < 2; ks++) {                                        \
            uint32_t ah[2][4], al[2][4];                                        \
            _Pragma("unroll")                                                   \
            for (int rf = 0; rf < 2; rf++) {                                    \
                uint32_t off = toff(a_row + rf * 16, ks * 32 + a_kb);           \
                ldsm_x4(ah[rf], sbase + off);                                   \
                ldsm_x4(al[rf], sbase + 8192 + off);                            \
            }                                                                   \
            _Pragma("unroll")                                                   \
            for (int ntp = 0; ntp < 4; ntp++) {                                 \
                uint32_t off = toff(b_row + ntp * 16, ks * 32 + b_kb);          \
                uint32_t bh4[4], bl4[4];                                        \
                ldsm_x4(bh4, sbase + 16384 + off);                              \
                ldsm_x4(bl4, sbase + 24576 + off);                              \
                _Pragma("unroll")                                               \
                for (int rf = 0; rf < 2; rf++) {                                \
                    mma16816h(acc[rf][2 * ntp],     ah[rf], bh4);               \
                    mma16816h(acc[rf][2 * ntp],     ah[rf], bl4);               \
                    mma16816h(acc[rf][2 * ntp],     al[rf], bh4);               \
                    mma16816h(acc[rf][2 * ntp + 1], ah[rf], bh4 + 2);           \
                    mma16816h(acc[rf][2 * ntp + 1], ah[rf], bl4 + 2);           \
                    mma16816h(acc[rf][2 * ntp + 1], al[rf], bh4 + 2);           \
                }                                                               \
            }                                                                   \
        }                                                                       \
        buf++; if (buf == 3) buf = 0;                                           \
    }

// ---------------- projection GEMMs via MMA ----------------
struct ProjM {
    const h16 *A_h[6], *A_l[6], *B_h[6], *B_l[6];
    h16 *Oh[6], *Ol[6];
    h16* OT[6];
    int mx[6], trans[6];
};
__global__ __launch_bounds__(256, 2) void mma_proj(ProjM p) {
    extern __shared__ char sm[];
    const int z = blockIdx.z;
    if ((int)blockIdx.x >= p.mx[z]) return;
    const uint32_t sb = smem_u32(sm);
    const h16* __restrict__ Ah = p.A_h[z];
    const h16* __restrict__ Al = p.A_l[z];
    const h16* __restrict__ Bh = p.B_h[z];
    const h16* __restrict__ Bl = p.B_l[z];
    const int Klen = 256;
    const int tid = threadIdx.x;
    const int wid = tid >> 5, lane = tid & 31;
    const int wm = wid & 3, wn = wid >> 2;
    const int mBase = blockIdx.x * 128;
    const int nBase = blockIdx.y * 128;

    MMA_MAINLOOP3();

    const int gID = lane >> 2, tig = lane & 3;

    if (p.trans[z]) {
        h16* __restrict__ OT = p.OT[z];
#pragma unroll
        for (int rf = 0; rf < 2; rf++) {
            int r0 = mBase + wm * 32 + rf * 16 + gID;
#pragma unroll
            for (int nt = 0; nt < 8; nt++) {
                int col = nBase + wn * 64 + nt * 8 + tig * 2;
#pragma unroll
                for (int c = 0; c < 4; c++) {
                    int row = r0 + (c >> 1) * 8;
                    int cc = col + (c & 1);
                    OT[(size_t)cc * MTOT + row] = __float2half(acc[rf][nt][c]);
                }
            }
        }
        return;
    }

    // staged coalesced fp16 hi/lo store
    __syncthreads();
    char* smHi = sm;
    char* smLo = sm + 32768;
    h16* __restrict__ Oh = p.Oh[z];
    h16* __restrict__ Ol = p.Ol[z];
#pragma unroll
    for (int rf = 0; rf < 2; rf++) {
#pragma unroll
        for (int nt = 0; nt < 8; nt++) {
            int chunk = wn * 8 + nt;
#pragma unroll
            for (int half = 0; half < 2; half++) {
                int rl = wm * 32 + rf * 16 + half * 8 + gID;
                h16 h0, l0, h1, l1;
                split1(acc[rf][nt][half * 2 + 0], h0, l0);
                split1(acc[rf][nt][half * 2 + 1], h1, l1);
                __half2 hh; hh.x = h0; hh.y = h1;
                __half2 ll; ll.x = l0; ll.y = l1;
                uint32_t addr = rl * 256 + ((chunk ^ (rl & 15)) << 4) + tig * 4;
                *(__half2*)(smHi + addr) = hh;
                *(__half2*)(smLo + addr) = ll;
            }
        }
    }
    __syncthreads();
#pragma unroll
    for (int it = 0; it < 8; it++) {
        int idx = it * 256 + tid;
        int r = idx >> 4, c = idx & 15;
        uint32_t src = r * 256 + ((c ^ (r & 15)) << 4);
        size_t dst = (size_t)(mBase + r) * 256 + nBase + c * 8;
        *(uint4*)(Oh + dst) = *(uint4*)(smHi + src);
        *(uint4*)(Ol + dst) = *(uint4*)(smLo + src);
    }
}

// ---------------- merged row stats ----------------
__global__ __launch_bounds__(256) void row_stats2(
    const h16* __restrict__ Qh, const h16* __restrict__ Ql,
    const h16* __restrict__ Kh, const h16* __restrict__ Kl,
    float* __restrict__ qm, float* __restrict__ qv,
    float* __restrict__ km, float* __restrict__ kv) {
    int row = blockIdx.x * 8 + (threadIdx.x >> 5);
    const int lane = threadIdx.x & 31;
    const h16 *Xh, *Xl;
    float *mean, *var;
    if (row < NB) { Xh = Qh; Xl = Ql; mean = qm; var = qv; }
    else { row -= NB; Xh = Kh; Xl = Kl; mean = km; var = kv; }
    const size_t base = (size_t)row * 256;
    float s = 0.f, ss = 0.f;
#pragma unroll
    for (int c = 0; c < 256; c += 32) {
        float v = __half2float(Xh[base + c + lane]) + __half2float(Xl[base + c + lane]);
        s += v; ss += v * v;
    }
#pragma unroll
    for (int o = 16; o > 0; o >>= 1) {
        s += __shfl_xor_sync(0xffffffffu, s, o);
        ss += __shfl_xor_sync(0xffffffffu, ss, o);
    }
    if (lane == 0) {
        float m = s * (1.f / 256.f);
        mean[row] = m;
        var[row] = (ss - 256.f * m * m) * (1.f / 255.f);
    }
}

// ---------------- score MMA GEMM: 2-product fp16 (qh*kh + qh*kl) ----------------
struct MMArgs {
    const h16 *A_h[2], *B_h[2], *B_l[2];
    h16* P[2];
    float* psum[2];
    const float *qm, *qv, *km, *kv;
};

__global__ __launch_bounds__(256, 2) void mma_gemm(MMArgs g) {
    extern __shared__ char sm[];
    const uint32_t sb = smem_u32(sm);
    const int z = blockIdx.z;
    const h16* __restrict__ Ah = g.A_h[z];
    const h16* __restrict__ Bh = g.B_h[z];
    const h16* __restrict__ Bl = g.B_l[z];
    const int Klen = 256;
    const int tid = threadIdx.x;
    const int wid = tid >> 5, lane = tid & 31;
    const int wm = wid & 3, wn = wid >> 2;
    const int mBase = blockIdx.x * 128;
    const int nBase = blockIdx.y * 128;

    float acc[2][8][4];
#pragma unroll
    for (int rf = 0; rf < 2; rf++)
#pragma unroll
        for (int nt = 0; nt < 8; nt++)
#pragma unroll
            for (int c = 0; c < 4; c++) acc[rf][nt][c] = 0.f;

    const int a_row = wm * 32 + (lane & 15);
    const int a_kb  = (lane >> 4) * 16;
    const int b_row = wn * 64 + ((lane >> 4) << 3) + (lane & 7);
    const int b_kb  = ((lane >> 3) & 1) * 16;
    const int lr0 = tid >> 2;
    const int lg  = (tid & 3);
    const int nIter = Klen >> 5;

    auto issue = [&](int buf, int k0) {
        uint32_t base = sb + buf * SC_STG;
#pragma unroll
        for (int h = 0; h < 2; h++) {
            int r = lr0 + h * 64;
            uint32_t off = toff(r, lg * 16);
            size_t ga = (size_t)(mBase + r) * Klen + k0 + lg * 8;
            size_t gb = (size_t)(nBase + r) * Klen + k0 + lg * 8;
            cp16(base + off,         Ah + ga);
            cp16(base + 8192 + off,  Bh + gb);
            cp16(base + 16384 + off, Bl + gb);
        }
    };

    issue(0, 0); CP_COMMIT();
    issue(1, 32); CP_COMMIT();

    int buf = 0;
    for (int it = 0; it < nIter; it++) {
        CP_WAIT1();
        __syncthreads();
        if (it + 2 < nIter) issue((it + 2) % 3, (it + 2) * 32);
        CP_COMMIT();

        const uint32_t sbase = sb + buf * SC_STG;
#pragma unroll
        for (int ks = 0; ks < 2; ks++) {
            uint32_t ah[2][4];
#pragma unroll
            for (int rf = 0; rf < 2; rf++)
                ldsm_x4(ah[rf], sbase + toff(a_row + rf * 16, ks * 32 + a_kb));
#pragma unroll
            for (int ntp = 0; ntp < 4; ntp++) {
                uint32_t off = toff(b_row + ntp * 16, ks * 32 + b_kb);
                uint32_t bh4[4], bl4[4];
                ldsm_x4(bh4, sbase + 8192 + off);
                ldsm_x4(bl4, sbase + 16384 + off);
#pragma unroll
                for (int rf = 0; rf < 2; rf++) {
                    mma16816h(acc[rf][2 * ntp],     ah[rf], bh4);
                    mma16816h(acc[rf][2 * ntp],     ah[rf], bl4);
                    mma16816h(acc[rf][2 * ntp + 1], ah[rf], bh4 + 2);
                    mma16816h(acc[rf][2 * ntp + 1], ah[rf], bl4 + 2);
                }
            }
        }
        buf++; if (buf == 3) buf = 0;
    }

    const int gID = lane >> 2, tig = lane & 3;
    const int mode = (z == 0) ? 0 : 1;
    char* smP = sm;
    float* rs_sm = (float*)(sm + 32768);
    float rs[2][2];
    rs[0][0] = rs[0][1] = rs[1][0] = rs[1][1] = 0.f;

    __syncthreads();
#pragma unroll
    for (int rf = 0; rf < 2; rf++) {
        int r0 = mBase + wm * 32 + rf * 16 + gID;
        int r1 = r0 + 8;
        float qm0 = 0.f, qv0 = 0.f, qm1 = 0.f, qv1 = 0.f;
        if (mode == 1) { qm0 = g.qm[r0]; qv0 = g.qv[r0]; qm1 = g.qm[r1]; qv1 = g.qv[r1]; }
#pragma unroll
        for (int nt = 0; nt < 8; nt++) {
            int col = nBase + wn * 64 + nt * 8 + tig * 2;
            float v0 = acc[rf][nt][0], v1 = acc[rf][nt][1];
            float v2 = acc[rf][nt][2], v3 = acc[rf][nt][3];
            if (mode == 0) {
                v0 = __expf(v0 * 0.0625f); v1 = __expf(v1 * 0.0625f);
                v2 = __expf(v2 * 0.0625f); v3 = __expf(v3 * 0.0625f);
            } else {
                float km0 = g.km[col], kv0 = g.kv[col];
                float km1 = g.km[col + 1], kv1 = g.kv[col + 1];
#define SSIM(dot, QM, QV, KM, KV)                                              \
    ({ float mp = (QM) * (KM);                                                 \
       float cov = ((dot) - 256.f * mp) * (1.f / 255.f);                       \
       float num = (2.f * mp + 0.01f) * (2.f * cov + 0.03f);                   \
       float den = ((QM) * (QM) + (KM) * (KM) + 0.01f) * ((QV) + (KV) + 0.03f);\
       num / (den + 1e-8f); })
                v0 = __expf(SSIM(v0, qm0, qv0, km0, kv0));
                v1 = __expf(SSIM(v1, qm0, qv0, km1, kv1));
                v2 = __expf(SSIM(v2, qm1, qv1, km0, kv0));
                v3 = __expf(SSIM(v3, qm1, qv1, km1, kv1));
            }
            rs[rf][0] += v0 + v1;
            rs[rf][1] += v2 + v3;

            int chunk = wn * 8 + nt;
            int rl0 = wm * 32 + rf * 16 + gID;
            int rl1 = rl0 + 8;
            __half2 p0; p0.x = __float2half(v0); p0.y = __float2half(v1);
            __half2 p1; p1.x = __float2half(v2); p1.y = __float2half(v3);
            uint32_t a0 = rl0 * 256 + ((chunk ^ (rl0 & 15)) << 4) + tig * 4;
            uint32_t a1 = rl1 * 256 + ((chunk ^ (rl1 & 15)) << 4) + tig * 4;
            *(__half2*)(smP + a0) = p0;
            *(__half2*)(smP + a1) = p1;
        }
    }

#pragma unroll
    for (int rf = 0; rf < 2; rf++)
#pragma unroll
        for (int h = 0; h < 2; h++) {
            rs[rf][h] += __shfl_xor_sync(0xffffffffu, rs[rf][h], 1);
            rs[rf][h] += __shfl_xor_sync(0xffffffffu, rs[rf][h], 2);
        }
    __syncthreads();
    if (tig == 0) {
#pragma unroll
        for (int rf = 0; rf < 2; rf++)
#pragma unroll
            for (int h = 0; h < 2; h++)
                rs_sm[wn * 128 + wm * 32 + rf * 16 + h * 8 + gID] = rs[rf][h];
    }
    __syncthreads();

    h16* __restrict__ P = g.P[z];
#pragma unroll
    for (int it = 0; it < 8; it++) {
        int idx = it * 256 + tid;
        int r = idx >> 4, c = idx & 15;
        uint32_t src = r * 256 + ((c ^ (r & 15)) << 4);
        size_t dst = (size_t)(mBase + r) * 2048 + nBase + c * 8;
        *(uint4*)(P + dst) = *(uint4*)(smP + src);
    }
    if (tid < 128)
        g.psum[z][(size_t)(mBase + tid) * 16 + blockIdx.y] = rs_sm[tid] + rs_sm[128 + tid];
}

// ---------------- PV GEMM: single-product fp16 ----------------
struct PVArgs {
    const h16 *A[2], *B[2];
    float* C[2];
    const float* linv[2];
};

__global__ __launch_bounds__(256, 2) void pv_gemm(PVArgs g) {
    extern __shared__ char sm[];
    const uint32_t sb = smem_u32(sm);
    const int z = blockIdx.z;
    const h16* __restrict__ A = g.A[z];
    const h16* __restrict__ B = g.B[z];
    const int Klen = 2048;
    const int tid = threadIdx.x;
    const int wid = tid >> 5, lane = tid & 31;
    const int wm = wid & 3, wn = wid >> 2;
    const int mBase = blockIdx.x * 128;
    const int nBase = blockIdx.y * 128;

    float acc[2][8][4];
#pragma unroll
    for (int rf = 0; rf < 2; rf++)
#pragma unroll
        for (int nt = 0; nt < 8; nt++)
#pragma unroll
            for (int c = 0; c < 4; c++) acc[rf][nt][c] = 0.f;

    const int a_row = wm * 32 + (lane & 15);
    const int a_kb  = (lane >> 4) * 16;
    const int b_row = wn * 64 + ((lane >> 4) << 3) + (lane & 7);
    const int b_kb  = ((lane >> 3) & 1) * 16;
    const int lr0 = tid >> 2;
    const int lg  = (tid & 3);
    const int nIter = Klen >> 5;

    auto issue = [&](int buf, int k0) {
        uint32_t base = sb + buf * PV_STG;
#pragma unroll
        for (int h = 0; h < 2; h++) {
            int r = lr0 + h * 64;
            uint32_t off = toff(r, lg * 16);
            size_t ga = (size_t)(mBase + r) * Klen + k0 + lg * 8;
            size_t gb = (size_t)(nBase + r) * Klen + k0 + lg * 8;
            cp16(base + off,        A + ga);
            cp16(base + 8192 + off, B + gb);
        }
    };

    issue(0, 0); CP_COMMIT();
    issue(1, 32); CP_COMMIT();

    int buf = 0;
    for (int it = 0; it < nIter; it++) {
        CP_WAIT1();
        __syncthreads();
        if (it + 2 < nIter) issue((it + 2) % 3, (it + 2) * 32);
        CP_COMMIT();

        const uint32_t sbase = sb + buf * PV_STG;
#pragma unroll
        for (int ks = 0; ks < 2; ks++) {
            uint32_t af[2][4];
#pragma unroll
            for (int rf = 0; rf < 2; rf++)
                ldsm_x4(af[rf], sbase + toff(a_row + rf * 16, ks * 32 + a_kb));
#pragma unroll
            for (int ntp = 0; ntp < 4; ntp++) {
                uint32_t bf4[4];
                ldsm_x4(bf4, sbase + 8192 + toff(b_row + ntp * 16, ks * 32 + b_kb));
#pragma unroll
                for (int rf = 0; rf < 2; rf++) {
                    mma16816h(acc[rf][2 * ntp],     af[rf], bf4);
                    mma16816h(acc[rf][2 * ntp + 1], af[rf], bf4 + 2);
                }
            }
        }
        buf++; if (buf == 3) buf = 0;
    }

    const int gID = lane >> 2, tig = lane & 3;
    float* __restrict__ C = g.C[z];
    const float* __restrict__ linv = g.linv[z];
#pragma unroll
    for (int rf = 0; rf < 2; rf++) {
        int r0 = mBase + wm * 32 + rf * 16 + gID;
        int r1 = r0 + 8;
        float i0 = linv[r0], i1 = linv[r1];
#pragma unroll
        for (int nt = 0; nt < 8; nt++) {
            int col = nBase + wn * 64 + nt * 8 + tig * 2;
            *(float2*)(C + (size_t)r0 * 256 + col) =
                make_float2(acc[rf][nt][0] * i0, acc[rf][nt][1] * i0);
            *(float2*)(C + (size_t)r1 * 256 + col) =
                make_float2(acc[rf][nt][2] * i1, acc[rf][nt][3] * i1);
        }
    }
}

// ---------------- reduce partial sums -> 1/l ----------------
__global__ __launch_bounds__(256) void reduce_l2(const float* __restrict__ ps0,
                                                 const float* __restrict__ ps1,
                                                 float* __restrict__ li0,
                                                 float* __restrict__ li1) {
    int row = blockIdx.x * 256 + threadIdx.x;
    const float* p = (blockIdx.y == 0 ? ps0 : ps1) + (size_t)row * 16;
    float s = 0.f;
#pragma unroll
    for (int i = 0; i < 16; i++) s += p[i];
    (blockIdx.y == 0 ? li0 : li1)[row] = 1.f / s;
}

// ---------------- out += outS ----------------
__global__ __launch_bounds__(256) void add_out(float* __restrict__ out,
                                               const float* __restrict__ add) {
    int i = (blockIdx.x * 256 + threadIdx.x) * 4;
    float4 a = *(float4*)(out + i);
    float4 b = *(const float4*)(add + i);
    a.x += b.x; a.y += b.y; a.z += b.z; a.w += b.w;
    *(float4*)(out + i) = a;
}

// ---------------- launch ----------------
extern "C" void kernel_launch(void* const* d_in, const int* in_sizes, int n_in,
                              void* d_out, int out_size) {
    const float* x    = (const float*)d_in[0];
    const float* chm  = (const float*)d_in[1];
    const float* chwq = (const float*)d_in[2];
    const float* chwk = (const float*)d_in[3];
    const float* chwv = (const float*)d_in[4];
    const float* spm  = (const float*)d_in[5];
    const float* spwq = (const float*)d_in[6];
    const float* spwk = (const float*)d_in[7];
    const float* spwv = (const float*)d_in[8];
    float* out = (float*)d_out;

    h16 *xh, *xl, *cmh, *cml, *smh, *sml, *wh, *wl;
    h16 *Qch, *Qcl, *Qfh, *Qfl, *Kch, *Kcl, *Kfh, *Kfl;
    h16 *Vtc, *Vtf, *P0, *P1;
    float *ps0, *ps1, *li0, *li1, *qm, *qv, *km, *kv, *outS;
    cudaGetSymbolAddress((void**)&xh, g_x_hi);    cudaGetSymbolAddress((void**)&xl, g_x_lo);
    cudaGetSymbolAddress((void**)&cmh, g_cm_hi);  cudaGetSymbolAddress((void**)&cml, g_cm_lo);
    cudaGetSymbolAddress((void**)&smh, g_sm_hi);  cudaGetSymbolAddress((void**)&sml, g_sm_lo);
    cudaGetSymbolAddress((void**)&wh, g_w_hi);    cudaGetSymbolAddress((void**)&wl, g_w_lo);
    cudaGetSymbolAddress((void**)&Qch, g_Qc_hi);  cudaGetSymbolAddress((void**)&Qcl, g_Qc_lo);
    cudaGetSymbolAddress((void**)&Qfh, g_Qf_hi);  cudaGetSymbolAddress((void**)&Qfl, g_Qf_lo);
    cudaGetSymbolAddress((void**)&Kch, g_Kc_hi);  cudaGetSymbolAddress((void**)&Kcl, g_Kc_lo);
    cudaGetSymbolAddress((void**)&Kfh, g_Kf_hi);  cudaGetSymbolAddress((void**)&Kfl, g_Kf_lo);
    cudaGetSymbolAddress((void**)&Vtc, g_Vtc);    cudaGetSymbolAddress((void**)&Vtf, g_Vtf);
    cudaGetSymbolAddress((void**)&P0, g_P0);      cudaGetSymbolAddress((void**)&P1, g_P1);
    cudaGetSymbolAddress((void**)&ps0, g_psum0);  cudaGetSymbolAddress((void**)&ps1, g_psum1);
    cudaGetSymbolAddress((void**)&li0, g_linv0);  cudaGetSymbolAddress((void**)&li1, g_linv1);
    cudaGetSymbolAddress((void**)&qm, g_qm);      cudaGetSymbolAddress((void**)&qv, g_qv);
    cudaGetSymbolAddress((void**)&km, g_km);      cudaGetSymbolAddress((void**)&kv, g_kv);
    cudaGetSymbolAddress((void**)&outS, g_OutS);

    cudaFuncSetAttribute(mma_gemm, cudaFuncAttributeMaxDynamicSharedMemorySize, SC_SMEM);
    cudaFuncSetAttribute(mma_proj, cudaFuncAttributeMaxDynamicSharedMemorySize, MM_SMEM);
    cudaFuncSetAttribute(pv_gemm, cudaFuncAttributeMaxDynamicSharedMemorySize, PV_SMEM);

    // 0: fp32 -> fp16 hi/lo
    const int WSZ = DDIM * DDIM;
    SplitArgs sp;
    sp.src[0] = x;    sp.h[0] = xh;           sp.l[0] = xl;           sp.nblk[0] = NB * DDIM / 1024;
    sp.src[1] = chm;  sp.h[1] = cmh;          sp.l[1] = cml;          sp.nblk[1] = MTOT * DDIM / 1024;
    sp.src[2] = spm;  sp.h[2] = smh;          sp.l[2] = sml;          sp.nblk[2] = MTOT * DDIM / 1024;
    sp.src[3] = spwq; sp.h[3] = wh + 0 * WSZ; sp.l[3] = wl + 0 * WSZ; sp.nblk[3] = WSZ / 1024;
    sp.src[4] = chwq; sp.h[4] = wh + 1 * WSZ; sp.l[4] = wl + 1 * WSZ; sp.nblk[4] = WSZ / 1024;
    sp.src[5] = spwk; sp.h[5] = wh + 2 * WSZ; sp.l[5] = wl + 2 * WSZ; sp.nblk[5] = WSZ / 1024;
    sp.src[6] = chwk; sp.h[6] = wh + 3 * WSZ; sp.l[6] = wl + 3 * WSZ; sp.nblk[6] = WSZ / 1024;
    sp.src[7] = chwv; sp.h[7] = wh + 4 * WSZ; sp.l[7] = wl + 4 * WSZ; sp.nblk[7] = WSZ / 1024;
    sp.src[8] = spwv; sp.h[8] = wh + 5 * WSZ; sp.l[8] = wl + 5 * WSZ; sp.nblk[8] = WSZ / 1024;
    int totBlk = 0;
    for (int i = 0; i < 9; i++) totBlk += sp.nblk[i];
    split_all<<<totBlk, 256>>>(sp);

    // 1: projections
    ProjM pm;
    for (int i = 0; i < 6; i++) pm.OT[i] = nullptr;
    pm.A_h[0] = xh;  pm.A_l[0] = xl;  pm.B_h[0] = wh + 0 * WSZ; pm.B_l[0] = wl + 0 * WSZ;
    pm.Oh[0] = Qfh;  pm.Ol[0] = Qfl;  pm.mx[0] = NB / 128;      pm.trans[0] = 0;
    pm.A_h[1] = xh;  pm.A_l[1] = xl;  pm.B_h[1] = wh + 1 * WSZ; pm.B_l[1] = wl + 1 * WSZ;
    pm.Oh[1] = Qch;  pm.Ol[1] = Qcl;  pm.mx[1] = NB / 128;      pm.trans[1] = 0;
    pm.A_h[2] = smh; pm.A_l[2] = sml; pm.B_h[2] = wh + 2 * WSZ; pm.B_l[2] = wl + 2 * WSZ;
    pm.Oh[2] = Kfh;  pm.Ol[2] = Kfl;  pm.mx[2] = MTOT / 128;    pm.trans[2] = 0;
    pm.A_h[3] = cmh; pm.A_l[3] = cml; pm.B_h[3] = wh + 3 * WSZ; pm.B_l[3] = wl + 3 * WSZ;
    pm.Oh[3] = Kch;  pm.Ol[3] = Kcl;  pm.mx[3] = MTOT / 128;    pm.trans[3] = 0;
    pm.A_h[4] = cmh; pm.A_l[4] = cml; pm.B_h[4] = wh + 4 * WSZ; pm.B_l[4] = wl + 4 * WSZ;
    pm.Oh[4] = nullptr; pm.Ol[4] = nullptr; pm.OT[4] = Vtc; pm.mx[4] = MTOT / 128; pm.trans[4] = 1;
    pm.A_h[5] = smh; pm.A_l[5] = sml; pm.B_h[5] = wh + 5 * WSZ; pm.B_l[5] = wl + 5 * WSZ;
    pm.Oh[5] = nullptr; pm.Ol[5] = nullptr; pm.OT[5] = Vtf; pm.mx[5] = MTOT / 128; pm.trans[5] = 1;
    mma_proj<<<dim3(NB / 128, 2, 6), 256, MM_SMEM>>>(pm);

    // 2: row stats
    row_stats2<<<(NB + MTOT) / 8, 256>>>(Qfh, Qfl, Kfh, Kfl, qm, qv, km, kv);

    // 3: score GEMMs (profiled)
    MMArgs sa;
    sa.A_h[0] = Qch; sa.B_h[0] = Kch; sa.B_l[0] = Kcl;
    sa.A_h[1] = Qfh; sa.B_h[1] = Kfh; sa.B_l[1] = Kfl;
    sa.P[0] = P0; sa.P[1] = P1;
    sa.psum[0] = ps0; sa.psum[1] = ps1;
    sa.qm = qm; sa.qv = qv; sa.km = km; sa.kv = kv;
    mma_gemm<<<dim3(NB / 128, MTOT / 128, 2), 256, SC_SMEM>>>(sa);

    // 4: reduce
    reduce_l2<<<dim3(NB / 256, 2), 256>>>(ps0, ps1, li0, li1);

    // 5: PV GEMMs
    PVArgs pa;
    pa.A[0] = P0; pa.B[0] = Vtc; pa.C[0] = out;  pa.linv[0] = li0;
    pa.A[1] = P1; pa.B[1] = Vtf; pa.C[1] = outS; pa.linv[1] = li1;
    pv_gemm<<<dim3(NB / 128, DDIM / 128, 2), 256, PV_SMEM>>>(pa);

    // 6: combine
    add_out<<<NB * DDIM / 1024, 256>>>(out, outS);
}

// round 11
// speedup vs baseline: 7.5479x; 1.2363x over previous
#include <cuda_runtime.h>
#include <cuda_fp16.h>
#include <cstdint>

#define NB   12544
#define MTOT 2048
#define DDIM 256

typedef __half h16;

// ---------------- scratch ----------------
__device__ __align__(16) h16 g_x_hi[NB * DDIM], g_x_lo[NB * DDIM];
__device__ __align__(16) h16 g_cm_hi[MTOT * DDIM], g_cm_lo[MTOT * DDIM];
__device__ __align__(16) h16 g_sm_hi[MTOT * DDIM], g_sm_lo[MTOT * DDIM];
__device__ __align__(16) h16 g_w_hi[6 * DDIM * DDIM], g_w_lo[6 * DDIM * DDIM];
__device__ __align__(16) h16 g_Qc[NB * DDIM];
__device__ __align__(16) h16 g_Qf[NB * DDIM];
__device__ __align__(16) h16 g_Kc[MTOT * DDIM];
__device__ __align__(16) h16 g_Kf[MTOT * DDIM];
__device__ __align__(16) h16 g_Vtc[DDIM * MTOT];
__device__ __align__(16) h16 g_Vtf[DDIM * MTOT];
__device__ __align__(16) h16 g_P0[(size_t)NB * MTOT];
__device__ __align__(16) h16 g_P1[(size_t)NB * MTOT];
__device__ float g_psum0[NB * 16], g_psum1[NB * 16];
__device__ float g_linv0[NB], g_linv1[NB];
__device__ float g_qm[NB], g_qv[NB], g_km[MTOT], g_kv[MTOT];
__device__ float g_OutS[NB * DDIM];

// ---------------- helpers ----------------
__device__ __forceinline__ uint32_t smem_u32(const void* p) {
    uint32_t a;
    asm("{ .reg .u64 t; cvta.to.shared.u64 t, %1; cvt.u32.u64 %0, t; }" : "=r"(a) : "l"(p));
    return a;
}
#define SWZ(o) ((o) ^ (((o) >> 3) & 0x70))

__device__ __forceinline__ void mma16816h(float* c, const uint32_t* a, const uint32_t* b) {
    asm volatile(
        "mma.sync.aligned.m16n8k16.row.col.f32.f16.f16.f32 "
        "{%0,%1,%2,%3}, {%4,%5,%6,%7}, {%8,%9}, {%0,%1,%2,%3};"
        : "+f"(c[0]), "+f"(c[1]), "+f"(c[2]), "+f"(c[3])
        : "r"(a[0]), "r"(a[1]), "r"(a[2]), "r"(a[3]), "r"(b[0]), "r"(b[1]));
}
__device__ __forceinline__ void ldsm_x4(uint32_t* r, uint32_t addr) {
    asm volatile("ldmatrix.sync.aligned.m8n8.x4.shared.b16 {%0,%1,%2,%3}, [%4];"
                 : "=r"(r[0]), "=r"(r[1]), "=r"(r[2]), "=r"(r[3]) : "r"(addr));
}
__device__ __forceinline__ void cp16(uint32_t dst, const void* src) {
    asm volatile("cp.async.cg.shared.global [%0], [%1], 16;" :: "r"(dst), "l"(src));
}
#define CP_COMMIT() asm volatile("cp.async.commit_group;" ::: "memory")
#define CP_WAIT1()  asm volatile("cp.async.wait_group 1;" ::: "memory")

// packed tile addressing: 128 logical rows x 64 bytes -> 64 smem rows x 128B
__device__ __forceinline__ uint32_t toff(int row, int cb) {
    return SWZ((uint32_t)((row & 63) * 128 + ((row >> 6) << 6) + cb));
}
__device__ __forceinline__ void split1(float a, h16& h, h16& l) {
    h = __float2half(a);
    l = __float2half(a - __half2float(h));
}

#define STG_BYTES 32768
#define MM_SMEM (3 * STG_BYTES)
#define GV_STG 16384
#define GV_SMEM (3 * GV_STG)

// ---------------- fp32 -> fp16 hi/lo conversion (9 arrays) ----------------
struct SplitArgs {
    const float* src[9];
    h16 *h[9], *l[9];
    int nblk[9];
};
__global__ __launch_bounds__(256) void split_all(SplitArgs a) {
    int bx = blockIdx.x, z = 0;
    while (bx >= a.nblk[z]) { bx -= a.nblk[z]; z++; }
    size_t i = ((size_t)bx * 256 + threadIdx.x) * 4;
    float4 v = *(const float4*)(a.src[z] + i);
    h16 h0, l0, h1, l1, h2, l2, h3, l3;
    split1(v.x, h0, l0); split1(v.y, h1, l1);
    split1(v.z, h2, l2); split1(v.w, h3, l3);
    __half2 ha; ha.x = h0; ha.y = h1;
    __half2 hb; hb.x = h2; hb.y = h3;
    __half2 la; la.x = l0; la.y = l1;
    __half2 lb; lb.x = l2; lb.y = l3;
    *(__half2*)(a.h[z] + i) = ha; *(__half2*)(a.h[z] + i + 2) = hb;
    *(__half2*)(a.l[z] + i) = la; *(__half2*)(a.l[z] + i + 2) = lb;
}

// ---------------- fp16-split 3-product mainloop (projections) ----------------
#define MMA_MAINLOOP3()                                                         \
    float acc[2][8][4];                                                         \
    _Pragma("unroll")                                                           \
    for (int rf = 0; rf < 2; rf++)                                              \
        _Pragma("unroll")                                                       \
        for (int nt = 0; nt < 8; nt++)                                          \
            _Pragma("unroll")                                                   \
            for (int c = 0; c < 4; c++) acc[rf][nt][c] = 0.f;                   \
    const int a_row = wm * 32 + (lane & 15);                                    \
    const int a_kb  = (lane >> 4) * 16;                                         \
    const int b_row = wn * 64 + ((lane >> 4) << 3) + (lane & 7);                \
    const int b_kb  = ((lane >> 3) & 1) * 16;                                   \
    const int lr0 = tid >> 2;                                                   \
    const int lg  = (tid & 3);                                                  \
    const int nIter = Klen >> 5;                                                \
    auto issue = [&](int buf, int k0) {                                         \
        uint32_t base = sb + buf * STG_BYTES;                                   \
        _Pragma("unroll")                                                       \
        for (int h = 0; h < 2; h++) {                                           \
            int r = lr0 + h * 64;                                               \
            uint32_t off = toff(r, lg * 16);                                    \
            size_t ga = (size_t)(mBase + r) * Klen + k0 + lg * 8;               \
            size_t gb = (size_t)(nBase + r) * Klen + k0 + lg * 8;               \
            cp16(base + off,         Ah + ga);                                  \
            cp16(base + 8192 + off,  Al + ga);                                  \
            cp16(base + 16384 + off, Bh + gb);                                  \
            cp16(base + 24576 + off, Bl + gb);                                  \
        }                                                                       \
    };                                                                          \
    issue(0, 0); CP_COMMIT();                                                   \
    issue(1, 32); CP_COMMIT();                                                  \
    int buf = 0;                                                                \
    for (int it = 0; it < nIter; it++) {                                        \
        CP_WAIT1();                                                             \
        __syncthreads();                                                        \
        if (it + 2 < nIter) issue((it + 2) % 3, (it + 2) * 32);                 \
        CP_COMMIT();                                                            \
        const uint32_t sbase = sb + buf * STG_BYTES;                            \
        _Pragma("unroll")                                                       \
        for (int ks = 0; ks < 2; ks++) {                                        \
            uint32_t ah[2][4], al[2][4];                                        \
            _Pragma("unroll")                                                   \
            for (int rf = 0; rf < 2; rf++) {                                    \
                uint32_t off = toff(a_row + rf * 16, ks * 32 + a_kb);           \
                ldsm_x4(ah[rf], sbase + off);                                   \
                ldsm_x4(al[rf], sbase + 8192 + off);                            \
            }                                                                   \
            _Pragma("unroll")                                                   \
            for (int ntp = 0; ntp < 4; ntp++) {                                 \
                uint32_t off = toff(b_row + ntp * 16, ks * 32 + b_kb);          \
                uint32_t bh4[4], bl4[4];                                        \
                ldsm_x4(bh4, sbase + 16384 + off);                              \
                ldsm_x4(bl4, sbase + 24576 + off);                              \
                _Pragma("unroll")                                               \
                for (int rf = 0; rf < 2; rf++) {                                \
                    mma16816h(acc[rf][2 * ntp],     ah[rf], bh4);               \
                    mma16816h(acc[rf][2 * ntp],     ah[rf], bl4);               \
                    mma16816h(acc[rf][2 * ntp],     al[rf], bh4);               \
                    mma16816h(acc[rf][2 * ntp + 1], ah[rf], bh4 + 2);           \
                    mma16816h(acc[rf][2 * ntp + 1], ah[rf], bl4 + 2);           \
                    mma16816h(acc[rf][2 * ntp + 1], al[rf], bh4 + 2);           \
                }                                                               \
            }                                                                   \
        }                                                                       \
        buf++; if (buf == 3) buf = 0;                                           \
    }

// ---------------- projection GEMMs via MMA (fp16 single-array outputs) ----------------
struct ProjM {
    const h16 *A_h[6], *A_l[6], *B_h[6], *B_l[6];
    h16* O[6];
    int mx[6], trans[6];
};
__global__ __launch_bounds__(256, 2) void mma_proj(ProjM p) {
    extern __shared__ char sm[];
    const int z = blockIdx.z;
    if ((int)blockIdx.x >= p.mx[z]) return;
    const uint32_t sb = smem_u32(sm);
    const h16* __restrict__ Ah = p.A_h[z];
    const h16* __restrict__ Al = p.A_l[z];
    const h16* __restrict__ Bh = p.B_h[z];
    const h16* __restrict__ Bl = p.B_l[z];
    const int Klen = 256;
    const int tid = threadIdx.x;
    const int wid = tid >> 5, lane = tid & 31;
    const int wm = wid & 3, wn = wid >> 2;
    const int mBase = blockIdx.x * 128;
    const int nBase = blockIdx.y * 128;

    MMA_MAINLOOP3();

    const int gID = lane >> 2, tig = lane & 3;
    h16* __restrict__ O = p.O[z];

    if (p.trans[z]) {
#pragma unroll
        for (int rf = 0; rf < 2; rf++) {
            int r0 = mBase + wm * 32 + rf * 16 + gID;
#pragma unroll
            for (int nt = 0; nt < 8; nt++) {
                int col = nBase + wn * 64 + nt * 8 + tig * 2;
#pragma unroll
                for (int c = 0; c < 4; c++) {
                    int row = r0 + (c >> 1) * 8;
                    int cc = col + (c & 1);
                    O[(size_t)cc * MTOT + row] = __float2half(acc[rf][nt][c]);
                }
            }
        }
        return;
    }

    // staged coalesced fp16 store
    __syncthreads();
    char* smP = sm;
#pragma unroll
    for (int rf = 0; rf < 2; rf++) {
#pragma unroll
        for (int nt = 0; nt < 8; nt++) {
            int chunk = wn * 8 + nt;
#pragma unroll
            for (int half = 0; half < 2; half++) {
                int rl = wm * 32 + rf * 16 + half * 8 + gID;
                __half2 hh;
                hh.x = __float2half(acc[rf][nt][half * 2 + 0]);
                hh.y = __float2half(acc[rf][nt][half * 2 + 1]);
                uint32_t addr = rl * 256 + ((chunk ^ (rl & 15)) << 4) + tig * 4;
                *(__half2*)(smP + addr) = hh;
            }
        }
    }
    __syncthreads();
#pragma unroll
    for (int it = 0; it < 8; it++) {
        int idx = it * 256 + tid;
        int r = idx >> 4, c = idx & 15;
        uint32_t src = r * 256 + ((c ^ (r & 15)) << 4);
        size_t dst = (size_t)(mBase + r) * 256 + nBase + c * 8;
        *(uint4*)(O + dst) = *(uint4*)(smP + src);
    }
}

// ---------------- merged row stats (fp16 input) ----------------
__global__ __launch_bounds__(256) void row_stats2(
    const h16* __restrict__ Qf, const h16* __restrict__ Kf,
    float* __restrict__ qm, float* __restrict__ qv,
    float* __restrict__ km, float* __restrict__ kv) {
    int row = blockIdx.x * 8 + (threadIdx.x >> 5);
    const int lane = threadIdx.x & 31;
    const h16* X;
    float *mean, *var;
    if (row < NB) { X = Qf; mean = qm; var = qv; }
    else { row -= NB; X = Kf; mean = km; var = kv; }
    const size_t base = (size_t)row * 256;
    float s = 0.f, ss = 0.f;
#pragma unroll
    for (int c = 0; c < 256; c += 32) {
        float v = __half2float(X[base + c + lane]);
        s += v; ss += v * v;
    }
#pragma unroll
    for (int o = 16; o > 0; o >>= 1) {
        s += __shfl_xor_sync(0xffffffffu, s, o);
        ss += __shfl_xor_sync(0xffffffffu, ss, o);
    }
    if (lane == 0) {
        float m = s * (1.f / 256.f);
        mean[row] = m;
        var[row] = (ss - 256.f * m * m) * (1.f / 255.f);
    }
}

// ---------------- score MMA GEMM: single-product fp16 ----------------
struct MMArgs {
    const h16 *A[2], *B[2];
    h16* P[2];
    float* psum[2];
    const float *qm, *qv, *km, *kv;
};

__global__ __launch_bounds__(256, 2) void mma_gemm(MMArgs g) {
    extern __shared__ char sm[];
    const uint32_t sb = smem_u32(sm);
    const int z = blockIdx.z;
    const h16* __restrict__ A = g.A[z];
    const h16* __restrict__ B = g.B[z];
    const int Klen = 256;
    const int tid = threadIdx.x;
    const int wid = tid >> 5, lane = tid & 31;
    const int wm = wid & 3, wn = wid >> 2;
    const int mBase = blockIdx.x * 128;
    const int nBase = blockIdx.y * 128;

    float acc[2][8][4];
#pragma unroll
    for (int rf = 0; rf < 2; rf++)
#pragma unroll
        for (int nt = 0; nt < 8; nt++)
#pragma unroll
            for (int c = 0; c < 4; c++) acc[rf][nt][c] = 0.f;

    const int a_row = wm * 32 + (lane & 15);
    const int a_kb  = (lane >> 4) * 16;
    const int b_row = wn * 64 + ((lane >> 4) << 3) + (lane & 7);
    const int b_kb  = ((lane >> 3) & 1) * 16;
    const int lr0 = tid >> 2;
    const int lg  = (tid & 3);
    const int nIter = Klen >> 5;

    auto issue = [&](int buf, int k0) {
        uint32_t base = sb + buf * GV_STG;
#pragma unroll
        for (int h = 0; h < 2; h++) {
            int r = lr0 + h * 64;
            uint32_t off = toff(r, lg * 16);
            size_t ga = (size_t)(mBase + r) * Klen + k0 + lg * 8;
            size_t gb = (size_t)(nBase + r) * Klen + k0 + lg * 8;
            cp16(base + off,        A + ga);
            cp16(base + 8192 + off, B + gb);
        }
    };

    issue(0, 0); CP_COMMIT();
    issue(1, 32); CP_COMMIT();

    int buf = 0;
    for (int it = 0; it < nIter; it++) {
        CP_WAIT1();
        __syncthreads();
        if (it + 2 < nIter) issue((it + 2) % 3, (it + 2) * 32);
        CP_COMMIT();

        const uint32_t sbase = sb + buf * GV_STG;
#pragma unroll
        for (int ks = 0; ks < 2; ks++) {
            uint32_t ah[2][4];
#pragma unroll
            for (int rf = 0; rf < 2; rf++)
                ldsm_x4(ah[rf], sbase + toff(a_row + rf * 16, ks * 32 + a_kb));
#pragma unroll
            for (int ntp = 0; ntp < 4; ntp++) {
                uint32_t bh4[4];
                ldsm_x4(bh4, sbase + 8192 + toff(b_row + ntp * 16, ks * 32 + b_kb));
#pragma unroll
                for (int rf = 0; rf < 2; rf++) {
                    mma16816h(acc[rf][2 * ntp],     ah[rf], bh4);
                    mma16816h(acc[rf][2 * ntp + 1], ah[rf], bh4 + 2);
                }
            }
        }
        buf++; if (buf == 3) buf = 0;
    }

    const int gID = lane >> 2, tig = lane & 3;
    const int mode = (z == 0) ? 0 : 1;
    char* smP = sm;
    float* rs_sm = (float*)(sm + 32768);
    float rs[2][2];
    rs[0][0] = rs[0][1] = rs[1][0] = rs[1][1] = 0.f;

    __syncthreads();
#pragma unroll
    for (int rf = 0; rf < 2; rf++) {
        int r0 = mBase + wm * 32 + rf * 16 + gID;
        int r1 = r0 + 8;
        float qm0 = 0.f, qv0 = 0.f, qm1 = 0.f, qv1 = 0.f;
        if (mode == 1) { qm0 = g.qm[r0]; qv0 = g.qv[r0]; qm1 = g.qm[r1]; qv1 = g.qv[r1]; }
#pragma unroll
        for (int nt = 0; nt < 8; nt++) {
            int col = nBase + wn * 64 + nt * 8 + tig * 2;
            float v0 = acc[rf][nt][0], v1 = acc[rf][nt][1];
            float v2 = acc[rf][nt][2], v3 = acc[rf][nt][3];
            if (mode == 0) {
                v0 = __expf(v0 * 0.0625f); v1 = __expf(v1 * 0.0625f);
                v2 = __expf(v2 * 0.0625f); v3 = __expf(v3 * 0.0625f);
            } else {
                float km0 = g.km[col], kv0 = g.kv[col];
                float km1 = g.km[col + 1], kv1 = g.kv[col + 1];
#define SSIM(dot, QM, QV, KM, KV)                                              \
    ({ float mp = (QM) * (KM);                                                 \
       float cov = ((dot) - 256.f * mp) * (1.f / 255.f);                       \
       float num = (2.f * mp + 0.01f) * (2.f * cov + 0.03f);                   \
       float den = ((QM) * (QM) + (KM) * (KM) + 0.01f) * ((QV) + (KV) + 0.03f);\
       num / (den + 1e-8f); })
                v0 = __expf(SSIM(v0, qm0, qv0, km0, kv0));
                v1 = __expf(SSIM(v1, qm0, qv0, km1, kv1));
                v2 = __expf(SSIM(v2, qm1, qv1, km0, kv0));
                v3 = __expf(SSIM(v3, qm1, qv1, km1, kv1));
            }
            rs[rf][0] += v0 + v1;
            rs[rf][1] += v2 + v3;

            int chunk = wn * 8 + nt;
            int rl0 = wm * 32 + rf * 16 + gID;
            int rl1 = rl0 + 8;
            __half2 p0; p0.x = __float2half(v0); p0.y = __float2half(v1);
            __half2 p1; p1.x = __float2half(v2); p1.y = __float2half(v3);
            uint32_t a0 = rl0 * 256 + ((chunk ^ (rl0 & 15)) << 4) + tig * 4;
            uint32_t a1 = rl1 * 256 + ((chunk ^ (rl1 & 15)) << 4) + tig * 4;
            *(__half2*)(smP + a0) = p0;
            *(__half2*)(smP + a1) = p1;
        }
    }

#pragma unroll
    for (int rf = 0; rf < 2; rf++)
#pragma unroll
        for (int h = 0; h < 2; h++) {
            rs[rf][h] += __shfl_xor_sync(0xffffffffu, rs[rf][h], 1);
            rs[rf][h] += __shfl_xor_sync(0xffffffffu, rs[rf][h], 2);
        }
    __syncthreads();
    if (tig == 0) {
#pragma unroll
        for (int rf = 0; rf < 2; rf++)
#pragma unroll
            for (int h = 0; h < 2; h++)
                rs_sm[wn * 128 + wm * 32 + rf * 16 + h * 8 + gID] = rs[rf][h];
    }
    __syncthreads();

    h16* __restrict__ P = g.P[z];
#pragma unroll
    for (int it = 0; it < 8; it++) {
        int idx = it * 256 + tid;
        int r = idx >> 4, c = idx & 15;
        uint32_t src = r * 256 + ((c ^ (r & 15)) << 4);
        size_t dst = (size_t)(mBase + r) * 2048 + nBase + c * 8;
        *(uint4*)(P + dst) = *(uint4*)(smP + src);
    }
    if (tid < 128)
        g.psum[z][(size_t)(mBase + tid) * 16 + blockIdx.y] = rs_sm[tid] + rs_sm[128 + tid];
}

// ---------------- PV GEMM: single-product fp16 ----------------
struct PVArgs {
    const h16 *A[2], *B[2];
    float* C[2];
    const float* linv[2];
};

__global__ __launch_bounds__(256, 2) void pv_gemm(PVArgs g) {
    extern __shared__ char sm[];
    const uint32_t sb = smem_u32(sm);
    const int z = blockIdx.z;
    const h16* __restrict__ A = g.A[z];
    const h16* __restrict__ B = g.B[z];
    const int Klen = 2048;
    const int tid = threadIdx.x;
    const int wid = tid >> 5, lane = tid & 31;
    const int wm = wid & 3, wn = wid >> 2;
    const int mBase = blockIdx.x * 128;
    const int nBase = blockIdx.y * 128;

    float acc[2][8][4];
#pragma unroll
    for (int rf = 0; rf < 2; rf++)
#pragma unroll
        for (int nt = 0; nt < 8; nt++)
#pragma unroll
            for (int c = 0; c < 4; c++) acc[rf][nt][c] = 0.f;

    const int a_row = wm * 32 + (lane & 15);
    const int a_kb  = (lane >> 4) * 16;
    const int b_row = wn * 64 + ((lane >> 4) << 3) + (lane & 7);
    const int b_kb  = ((lane >> 3) & 1) * 16;
    const int lr0 = tid >> 2;
    const int lg  = (tid & 3);
    const int nIter = Klen >> 5;

    auto issue = [&](int buf, int k0) {
        uint32_t base = sb + buf * GV_STG;
#pragma unroll
        for (int h = 0; h < 2; h++) {
            int r = lr0 + h * 64;
            uint32_t off = toff(r, lg * 16);
            size_t ga = (size_t)(mBase + r) * Klen + k0 + lg * 8;
            size_t gb = (size_t)(nBase + r) * Klen + k0 + lg * 8;
            cp16(base + off,        A + ga);
            cp16(base + 8192 + off, B + gb);
        }
    };

    issue(0, 0); CP_COMMIT();
    issue(1, 32); CP_COMMIT();

    int buf = 0;
    for (int it = 0; it < nIter; it++) {
        CP_WAIT1();
        __syncthreads();
        if (it + 2 < nIter) issue((it + 2) % 3, (it + 2) * 32);
        CP_COMMIT();

        const uint32_t sbase = sb + buf * GV_STG;
#pragma unroll
        for (int ks = 0; ks < 2; ks++) {
            uint32_t af[2][4];
#pragma unroll
            for (int rf = 0; rf < 2; rf++)
                ldsm_x4(af[rf], sbase + toff(a_row + rf * 16, ks * 32 + a_kb));
#pragma unroll
            for (int ntp = 0; ntp < 4; ntp++) {
                uint32_t bf4[4];
                ldsm_x4(bf4, sbase + 8192 + toff(b_row + ntp * 16, ks * 32 + b_kb));
#pragma unroll
                for (int rf = 0; rf < 2; rf++) {
                    mma16816h(acc[rf][2 * ntp],     af[rf], bf4);
                    mma16816h(acc[rf][2 * ntp + 1], af[rf], bf4 + 2);
                }
            }
        }
        buf++; if (buf == 3) buf = 0;
    }

    const int gID = lane >> 2, tig = lane & 3;
    float* __restrict__ C = g.C[z];
    const float* __restrict__ linv = g.linv[z];
#pragma unroll
    for (int rf = 0; rf < 2; rf++) {
        int r0 = mBase + wm * 32 + rf * 16 + gID;
        int r1 = r0 + 8;
        float i0 = linv[r0], i1 = linv[r1];
#pragma unroll
        for (int nt = 0; nt < 8; nt++) {
            int col = nBase + wn * 64 + nt * 8 + tig * 2;
            *(float2*)(C + (size_t)r0 * 256 + col) =
                make_float2(acc[rf][nt][0] * i0, acc[rf][nt][1] * i0);
            *(float2*)(C + (size_t)r1 * 256 + col) =
                make_float2(acc[rf][nt][2] * i1, acc[rf][nt][3] * i1);
        }
    }
}

// ---------------- reduce partial sums -> 1/l ----------------
__global__ __launch_bounds__(256) void reduce_l2(const float* __restrict__ ps0,
                                                 const float* __restrict__ ps1,
                                                 float* __restrict__ li0,
                                                 float* __restrict__ li1) {
    int row = blockIdx.x * 256 + threadIdx.x;
    const float* p = (blockIdx.y == 0 ? ps0 : ps1) + (size_t)row * 16;
    float s = 0.f;
#pragma unroll
    for (int i = 0; i < 16; i++) s += p[i];
    (blockIdx.y == 0 ? li0 : li1)[row] = 1.f / s;
}

// ---------------- out += outS ----------------
__global__ __launch_bounds__(256) void add_out(float* __restrict__ out,
                                               const float* __restrict__ add) {
    int i = (blockIdx.x * 256 + threadIdx.x) * 4;
    float4 a = *(float4*)(out + i);
    float4 b = *(const float4*)(add + i);
    a.x += b.x; a.y += b.y; a.z += b.z; a.w += b.w;
    *(float4*)(out + i) = a;
}

// ---------------- launch ----------------
extern "C" void kernel_launch(void* const* d_in, const int* in_sizes, int n_in,
                              void* d_out, int out_size) {
    const float* x    = (const float*)d_in[0];
    const float* chm  = (const float*)d_in[1];
    const float* chwq = (const float*)d_in[2];
    const float* chwk = (const float*)d_in[3];
    const float* chwv = (const float*)d_in[4];
    const float* spm  = (const float*)d_in[5];
    const float* spwq = (const float*)d_in[6];
    const float* spwk = (const float*)d_in[7];
    const float* spwv = (const float*)d_in[8];
    float* out = (float*)d_out;

    h16 *xh, *xl, *cmh, *cml, *smh, *sml, *wh, *wl;
    h16 *Qc, *Qf, *Kc, *Kf, *Vtc, *Vtf, *P0, *P1;
    float *ps0, *ps1, *li0, *li1, *qm, *qv, *km, *kv, *outS;
    cudaGetSymbolAddress((void**)&xh, g_x_hi);    cudaGetSymbolAddress((void**)&xl, g_x_lo);
    cudaGetSymbolAddress((void**)&cmh, g_cm_hi);  cudaGetSymbolAddress((void**)&cml, g_cm_lo);
    cudaGetSymbolAddress((void**)&smh, g_sm_hi);  cudaGetSymbolAddress((void**)&sml, g_sm_lo);
    cudaGetSymbolAddress((void**)&wh, g_w_hi);    cudaGetSymbolAddress((void**)&wl, g_w_lo);
    cudaGetSymbolAddress((void**)&Qc, g_Qc);      cudaGetSymbolAddress((void**)&Qf, g_Qf);
    cudaGetSymbolAddress((void**)&Kc, g_Kc);      cudaGetSymbolAddress((void**)&Kf, g_Kf);
    cudaGetSymbolAddress((void**)&Vtc, g_Vtc);    cudaGetSymbolAddress((void**)&Vtf, g_Vtf);
    cudaGetSymbolAddress((void**)&P0, g_P0);      cudaGetSymbolAddress((void**)&P1, g_P1);
    cudaGetSymbolAddress((void**)&ps0, g_psum0);  cudaGetSymbolAddress((void**)&ps1, g_psum1);
    cudaGetSymbolAddress((void**)&li0, g_linv0);  cudaGetSymbolAddress((void**)&li1, g_linv1);
    cudaGetSymbolAddress((void**)&qm, g_qm);      cudaGetSymbolAddress((void**)&qv, g_qv);
    cudaGetSymbolAddress((void**)&km, g_km);      cudaGetSymbolAddress((void**)&kv, g_kv);
    cudaGetSymbolAddress((void**)&outS, g_OutS);

    cudaFuncSetAttribute(mma_gemm, cudaFuncAttributeMaxDynamicSharedMemorySize, GV_SMEM);
    cudaFuncSetAttribute(mma_proj, cudaFuncAttributeMaxDynamicSharedMemorySize, MM_SMEM);
    cudaFuncSetAttribute(pv_gemm, cudaFuncAttributeMaxDynamicSharedMemorySize, GV_SMEM);

    // 0: fp32 -> fp16 hi/lo
    const int WSZ = DDIM * DDIM;
    SplitArgs sp;
    sp.src[0] = x;    sp.h[0] = xh;           sp.l[0] = xl;           sp.nblk[0] = NB * DDIM / 1024;
    sp.src[1] = chm;  sp.h[1] = cmh;          sp.l[1] = cml;          sp.nblk[1] = MTOT * DDIM / 1024;
    sp.src[2] = spm;  sp.h[2] = smh;          sp.l[2] = sml;          sp.nblk[2] = MTOT * DDIM / 1024;
    sp.src[3] = spwq; sp.h[3] = wh + 0 * WSZ; sp.l[3] = wl + 0 * WSZ; sp.nblk[3] = WSZ / 1024;
    sp.src[4] = chwq; sp.h[4] = wh + 1 * WSZ; sp.l[4] = wl + 1 * WSZ; sp.nblk[4] = WSZ / 1024;
    sp.src[5] = spwk; sp.h[5] = wh + 2 * WSZ; sp.l[5] = wl + 2 * WSZ; sp.nblk[5] = WSZ / 1024;
    sp.src[6] = chwk; sp.h[6] = wh + 3 * WSZ; sp.l[6] = wl + 3 * WSZ; sp.nblk[6] = WSZ / 1024;
    sp.src[7] = chwv; sp.h[7] = wh + 4 * WSZ; sp.l[7] = wl + 4 * WSZ; sp.nblk[7] = WSZ / 1024;
    sp.src[8] = spwv; sp.h[8] = wh + 5 * WSZ; sp.l[8] = wl + 5 * WSZ; sp.nblk[8] = WSZ / 1024;
    int totBlk = 0;
    for (int i = 0; i < 9; i++) totBlk += sp.nblk[i];
    split_all<<<totBlk, 256>>>(sp);

    // 1: projections
    ProjM pm;
    pm.A_h[0] = xh;  pm.A_l[0] = xl;  pm.B_h[0] = wh + 0 * WSZ; pm.B_l[0] = wl + 0 * WSZ;
    pm.O[0] = Qf;  pm.mx[0] = NB / 128;   pm.trans[0] = 0;
    pm.A_h[1] = xh;  pm.A_l[1] = xl;  pm.B_h[1] = wh + 1 * WSZ; pm.B_l[1] = wl + 1 * WSZ;
    pm.O[1] = Qc;  pm.mx[1] = NB / 128;   pm.trans[1] = 0;
    pm.A_h[2] = smh; pm.A_l[2] = sml; pm.B_h[2] = wh + 2 * WSZ; pm.B_l[2] = wl + 2 * WSZ;
    pm.O[2] = Kf;  pm.mx[2] = MTOT / 128; pm.trans[2] = 0;
    pm.A_h[3] = cmh; pm.A_l[3] = cml; pm.B_h[3] = wh + 3 * WSZ; pm.B_l[3] = wl + 3 * WSZ;
    pm.O[3] = Kc;  pm.mx[3] = MTOT / 128; pm.trans[3] = 0;
    pm.A_h[4] = cmh; pm.A_l[4] = cml; pm.B_h[4] = wh + 4 * WSZ; pm.B_l[4] = wl + 4 * WSZ;
    pm.O[4] = Vtc; pm.mx[4] = MTOT / 128; pm.trans[4] = 1;
    pm.A_h[5] = smh; pm.A_l[5] = sml; pm.B_h[5] = wh + 5 * WSZ; pm.B_l[5] = wl + 5 * WSZ;
    pm.O[5] = Vtf; pm.mx[5] = MTOT / 128; pm.trans[5] = 1;
    mma_proj<<<dim3(NB / 128, 2, 6), 256, MM_SMEM>>>(pm);

    // 2: row stats
    row_stats2<<<(NB + MTOT) / 8, 256>>>(Qf, Kf, qm, qv, km, kv);

    // 3: score GEMMs (profiled)
    MMArgs sa;
    sa.A[0] = Qc; sa.B[0] = Kc;
    sa.A[1] = Qf; sa.B[1] = Kf;
    sa.P[0] = P0; sa.P[1] = P1;
    sa.psum[0] = ps0; sa.psum[1] = ps1;
    sa.qm = qm; sa.qv = qv; sa.km = km; sa.kv = kv;
    mma_gemm<<<dim3(NB / 128, MTOT / 128, 2), 256, GV_SMEM>>>(sa);

    // 4: reduce
    reduce_l2<<<dim3(NB / 256, 2), 256>>>(ps0, ps1, li0, li1);

    // 5: PV GEMMs
    PVArgs pa;
    pa.A[0] = P0; pa.B[0] = Vtc; pa.C[0] = out;  pa.linv[0] = li0;
    pa.A[1] = P1; pa.B[1] = Vtf; pa.C[1] = outS; pa.linv[1] = li1;
    pv_gemm<<<dim3(NB / 128, DDIM / 128, 2), 256, GV_SMEM>>>(pa);

    // 6: combine
    add_out<<<NB * DDIM / 1024, 256>>>(out, outS);
}

// round 12
// speedup vs baseline: 8.1456x; 1.0792x over previous
#include <cuda_runtime.h>
#include <cuda_fp16.h>
#include <cstdint>

#define NB   12544
#define MTOT 2048
#define DDIM 256

typedef __half h16;

// ---------------- scratch ----------------
__device__ __align__(16) h16 g_x[NB * DDIM];
__device__ __align__(16) h16 g_cm[MTOT * DDIM];
__device__ __align__(16) h16 g_sm2[MTOT * DDIM];
__device__ __align__(16) h16 g_w[6 * DDIM * DDIM];
__device__ __align__(16) h16 g_Qc[NB * DDIM];
__device__ __align__(16) h16 g_Qf[NB * DDIM];
__device__ __align__(16) h16 g_Kc[MTOT * DDIM];
__device__ __align__(16) h16 g_Kf[MTOT * DDIM];
__device__ __align__(16) h16 g_Vtc[DDIM * MTOT];
__device__ __align__(16) h16 g_Vtf[DDIM * MTOT];
__device__ __align__(16) h16 g_P0[(size_t)NB * MTOT];
__device__ __align__(16) h16 g_P1[(size_t)NB * MTOT];
__device__ float g_psum0[NB * 16], g_psum1[NB * 16];
__device__ float g_linv0[NB], g_linv1[NB];
__device__ float g_qm[NB], g_qv[NB], g_km[MTOT], g_kv[MTOT];
__device__ float g_OutS[NB * DDIM];

// ---------------- helpers ----------------
__device__ __forceinline__ uint32_t smem_u32(const void* p) {
    uint32_t a;
    asm("{ .reg .u64 t; cvta.to.shared.u64 t, %1; cvt.u32.u64 %0, t; }" : "=r"(a) : "l"(p));
    return a;
}
#define SWZ(o) ((o) ^ (((o) >> 3) & 0x70))

__device__ __forceinline__ void mma16816h(float* c, const uint32_t* a, const uint32_t* b) {
    asm volatile(
        "mma.sync.aligned.m16n8k16.row.col.f32.f16.f16.f32 "
        "{%0,%1,%2,%3}, {%4,%5,%6,%7}, {%8,%9}, {%0,%1,%2,%3};"
        : "+f"(c[0]), "+f"(c[1]), "+f"(c[2]), "+f"(c[3])
        : "r"(a[0]), "r"(a[1]), "r"(a[2]), "r"(a[3]), "r"(b[0]), "r"(b[1]));
}
__device__ __forceinline__ void ldsm_x4(uint32_t* r, uint32_t addr) {
    asm volatile("ldmatrix.sync.aligned.m8n8.x4.shared.b16 {%0,%1,%2,%3}, [%4];"
                 : "=r"(r[0]), "=r"(r[1]), "=r"(r[2]), "=r"(r[3]) : "r"(addr));
}
__device__ __forceinline__ void cp16(uint32_t dst, const void* src) {
    asm volatile("cp.async.cg.shared.global [%0], [%1], 16;" :: "r"(dst), "l"(src));
}
#define CP_COMMIT() asm volatile("cp.async.commit_group;" ::: "memory")
#define CP_WAIT1()  asm volatile("cp.async.wait_group 1;" ::: "memory")

// full 128-row x 128B tile, natural SW128 layout
__device__ __forceinline__ uint32_t toff64(int row, int cb) {
    return SWZ((uint32_t)(row * 128 + cb));
}

#define TILE_STG 32768          // A(16K) + B(16K) per stage
#define GEMM_SMEM (3 * TILE_STG)

// ---------------- fp32 -> fp16 conversion (9 arrays) ----------------
struct ConvArgs {
    const float* src[9];
    h16* dst[9];
    int nblk[9];
};
__global__ __launch_bounds__(256) void conv_all(ConvArgs a) {
    int bx = blockIdx.x, z = 0;
    while (bx >= a.nblk[z]) { bx -= a.nblk[z]; z++; }
    size_t i = ((size_t)bx * 256 + threadIdx.x) * 4;
    float4 v = *(const float4*)(a.src[z] + i);
    __half2 ha; ha.x = __float2half(v.x); ha.y = __float2half(v.y);
    __half2 hb; hb.x = __float2half(v.z); hb.y = __float2half(v.w);
    *(__half2*)(a.dst[z] + i) = ha;
    *(__half2*)(a.dst[z] + i + 2) = hb;
}

// ---------------- single-product fp16 mainloop, 64-K chunks ----------------
// Expects: sb, tid, wid, lane, wm, wn, mBase, nBase, A, B, Klen. Defines acc.
#define MMA_LOOP1()                                                             \
    float acc[2][8][4];                                                         \
    _Pragma("unroll")                                                           \
    for (int rf = 0; rf < 2; rf++)                                              \
        _Pragma("unroll")                                                       \
        for (int nt = 0; nt < 8; nt++)                                          \
            _Pragma("unroll")                                                   \
            for (int c = 0; c < 4; c++) acc[rf][nt][c] = 0.f;                   \
    const int a_row = wm * 32 + (lane & 15);                                    \
    const int a_kb  = (lane >> 4) * 16;                                         \
    const int b_row = wn * 64 + ((lane >> 4) << 3) + (lane & 7);                \
    const int b_kb  = ((lane >> 3) & 1) * 16;                                   \
    const int nIter = Klen >> 6;                                                \
    auto issue = [&](int buf, int k0) {                                         \
        uint32_t base = sb + buf * TILE_STG;                                    \
        _Pragma("unroll")                                                       \
        for (int u = 0; u < 4; u++) {                                           \
            int idx = u * 256 + tid;                                            \
            int r = idx >> 3, gch = idx & 7;                                    \
            uint32_t off = SWZ((uint32_t)(r * 128 + gch * 16));                 \
            cp16(base + off,         A + (size_t)(mBase + r) * Klen + k0 + gch * 8); \
            cp16(base + 16384 + off, B + (size_t)(nBase + r) * Klen + k0 + gch * 8); \
        }                                                                       \
    };                                                                          \
    issue(0, 0); CP_COMMIT();                                                   \
    if (nIter > 1) issue(1, 64);                                                \
    CP_COMMIT();                                                                \
    int buf = 0;                                                                \
    for (int it = 0; it < nIter; it++) {                                        \
        CP_WAIT1();                                                             \
        __syncthreads();                                                        \
        if (it + 2 < nIter) issue((it + 2) % 3, (it + 2) * 64);                 \
        CP_COMMIT();                                                            \
        const uint32_t sbase = sb + buf * TILE_STG;                             \
        _Pragma("unroll")                                                       \
        for (int ks = 0; ks < 4; ks++) {                                        \
            uint32_t ah[2][4];                                                  \
            _Pragma("unroll")                                                   \
            for (int rf = 0; rf < 2; rf++)                                      \
                ldsm_x4(ah[rf], sbase + toff64(a_row + rf * 16, ks * 32 + a_kb)); \
            _Pragma("unroll")                                                   \
            for (int ntp = 0; ntp < 4; ntp++) {                                 \
                uint32_t bh4[4];                                                \
                ldsm_x4(bh4, sbase + 16384 + toff64(b_row + ntp * 16, ks * 32 + b_kb)); \
                _Pragma("unroll")                                               \
                for (int rf = 0; rf < 2; rf++) {                                \
                    mma16816h(acc[rf][2 * ntp],     ah[rf], bh4);               \
                    mma16816h(acc[rf][2 * ntp + 1], ah[rf], bh4 + 2);           \
                }                                                               \
            }                                                                   \
        }                                                                       \
        buf++; if (buf == 3) buf = 0;                                           \
    }

// ---------------- projection GEMMs (single-product fp16) ----------------
struct ProjM {
    const h16 *A_[6], *B_[6];
    h16* O[6];
    int mx[6], trans[6];
};
__global__ __launch_bounds__(256, 2) void mma_proj(ProjM p) {
    extern __shared__ char sm[];
    const int z = blockIdx.z;
    if ((int)blockIdx.x >= p.mx[z]) return;
    const uint32_t sb = smem_u32(sm);
    const h16* __restrict__ A = p.A_[z];
    const h16* __restrict__ B = p.B_[z];
    const int Klen = 256;
    const int tid = threadIdx.x;
    const int wid = tid >> 5, lane = tid & 31;
    const int wm = wid & 3, wn = wid >> 2;
    const int mBase = blockIdx.x * 128;
    const int nBase = blockIdx.y * 128;

    MMA_LOOP1();

    const int gID = lane >> 2, tig = lane & 3;
    h16* __restrict__ O = p.O[z];

    if (p.trans[z]) {
#pragma unroll
        for (int rf = 0; rf < 2; rf++) {
            int r0 = mBase + wm * 32 + rf * 16 + gID;
#pragma unroll
            for (int nt = 0; nt < 8; nt++) {
                int col = nBase + wn * 64 + nt * 8 + tig * 2;
#pragma unroll
                for (int c = 0; c < 4; c++) {
                    int row = r0 + (c >> 1) * 8;
                    int cc = col + (c & 1);
                    O[(size_t)cc * MTOT + row] = __float2half(acc[rf][nt][c]);
                }
            }
        }
        return;
    }

    // staged coalesced fp16 store
    __syncthreads();
    char* smP = sm;
#pragma unroll
    for (int rf = 0; rf < 2; rf++) {
#pragma unroll
        for (int nt = 0; nt < 8; nt++) {
            int chunk = wn * 8 + nt;
#pragma unroll
            for (int half = 0; half < 2; half++) {
                int rl = wm * 32 + rf * 16 + half * 8 + gID;
                __half2 hh;
                hh.x = __float2half(acc[rf][nt][half * 2 + 0]);
                hh.y = __float2half(acc[rf][nt][half * 2 + 1]);
                uint32_t addr = rl * 256 + ((chunk ^ (rl & 15)) << 4) + tig * 4;
                *(__half2*)(smP + addr) = hh;
            }
        }
    }
    __syncthreads();
#pragma unroll
    for (int it = 0; it < 8; it++) {
        int idx = it * 256 + tid;
        int r = idx >> 4, c = idx & 15;
        uint32_t src = r * 256 + ((c ^ (r & 15)) << 4);
        size_t dst = (size_t)(mBase + r) * 256 + nBase + c * 8;
        *(uint4*)(O + dst) = *(uint4*)(smP + src);
    }
}

// ---------------- merged row stats (fp16 input) ----------------
__global__ __launch_bounds__(256) void row_stats2(
    const h16* __restrict__ Qf, const h16* __restrict__ Kf,
    float* __restrict__ qm, float* __restrict__ qv,
    float* __restrict__ km, float* __restrict__ kv) {
    int row = blockIdx.x * 8 + (threadIdx.x >> 5);
    const int lane = threadIdx.x & 31;
    const h16* X;
    float *mean, *var;
    if (row < NB) { X = Qf; mean = qm; var = qv; }
    else { row -= NB; X = Kf; mean = km; var = kv; }
    const size_t base = (size_t)row * 256;
    float s = 0.f, ss = 0.f;
#pragma unroll
    for (int c = 0; c < 256; c += 32) {
        float v = __half2float(X[base + c + lane]);
        s += v; ss += v * v;
    }
#pragma unroll
    for (int o = 16; o > 0; o >>= 1) {
        s += __shfl_xor_sync(0xffffffffu, s, o);
        ss += __shfl_xor_sync(0xffffffffu, ss, o);
    }
    if (lane == 0) {
        float m = s * (1.f / 256.f);
        mean[row] = m;
        var[row] = (ss - 256.f * m * m) * (1.f / 255.f);
    }
}

// ---------------- score MMA GEMM: single-product fp16 ----------------
struct MMArgs {
    const h16 *A_[2], *B_[2];
    h16* P[2];
    float* psum[2];
    const float *qm, *qv, *km, *kv;
};

__global__ __launch_bounds__(256, 2) void mma_gemm(MMArgs g) {
    extern __shared__ char sm[];
    const uint32_t sb = smem_u32(sm);
    const int z = blockIdx.z;
    const h16* __restrict__ A = g.A_[z];
    const h16* __restrict__ B = g.B_[z];
    const int Klen = 256;
    const int tid = threadIdx.x;
    const int wid = tid >> 5, lane = tid & 31;
    const int wm = wid & 3, wn = wid >> 2;
    const int mBase = blockIdx.x * 128;
    const int nBase = blockIdx.y * 128;

    MMA_LOOP1();

    const int gID = lane >> 2, tig = lane & 3;
    const int mode = (z == 0) ? 0 : 1;
    char* smP = sm;
    float* rs_sm = (float*)(sm + 32768);
    float rs[2][2];
    rs[0][0] = rs[0][1] = rs[1][0] = rs[1][1] = 0.f;

    __syncthreads();
#pragma unroll
    for (int rf = 0; rf < 2; rf++) {
        int r0 = mBase + wm * 32 + rf * 16 + gID;
        int r1 = r0 + 8;
        float qm0 = 0.f, qv0 = 0.f, qm1 = 0.f, qv1 = 0.f;
        if (mode == 1) { qm0 = g.qm[r0]; qv0 = g.qv[r0]; qm1 = g.qm[r1]; qv1 = g.qv[r1]; }
#pragma unroll
        for (int nt = 0; nt < 8; nt++) {
            int col = nBase + wn * 64 + nt * 8 + tig * 2;
            float v0 = acc[rf][nt][0], v1 = acc[rf][nt][1];
            float v2 = acc[rf][nt][2], v3 = acc[rf][nt][3];
            if (mode == 0) {
                v0 = __expf(v0 * 0.0625f); v1 = __expf(v1 * 0.0625f);
                v2 = __expf(v2 * 0.0625f); v3 = __expf(v3 * 0.0625f);
            } else {
                float km0 = g.km[col], kv0 = g.kv[col];
                float km1 = g.km[col + 1], kv1 = g.kv[col + 1];
#define SSIM(dot, QM, QV, KM, KV)                                              \
    ({ float mp = (QM) * (KM);                                                 \
       float cov = ((dot) - 256.f * mp) * (1.f / 255.f);                       \
       float num = (2.f * mp + 0.01f) * (2.f * cov + 0.03f);                   \
       float den = ((QM) * (QM) + (KM) * (KM) + 0.01f) * ((QV) + (KV) + 0.03f);\
       num / (den + 1e-8f); })
                v0 = __expf(SSIM(v0, qm0, qv0, km0, kv0));
                v1 = __expf(SSIM(v1, qm0, qv0, km1, kv1));
                v2 = __expf(SSIM(v2, qm1, qv1, km0, kv0));
                v3 = __expf(SSIM(v3, qm1, qv1, km1, kv1));
            }
            rs[rf][0] += v0 + v1;
            rs[rf][1] += v2 + v3;

            int chunk = wn * 8 + nt;
            int rl0 = wm * 32 + rf * 16 + gID;
            int rl1 = rl0 + 8;
            __half2 p0; p0.x = __float2half(v0); p0.y = __float2half(v1);
            __half2 p1; p1.x = __float2half(v2); p1.y = __float2half(v3);
            uint32_t a0 = rl0 * 256 + ((chunk ^ (rl0 & 15)) << 4) + tig * 4;
            uint32_t a1 = rl1 * 256 + ((chunk ^ (rl1 & 15)) << 4) + tig * 4;
            *(__half2*)(smP + a0) = p0;
            *(__half2*)(smP + a1) = p1;
        }
    }

#pragma unroll
    for (int rf = 0; rf < 2; rf++)
#pragma unroll
        for (int h = 0; h < 2; h++) {
            rs[rf][h] += __shfl_xor_sync(0xffffffffu, rs[rf][h], 1);
            rs[rf][h] += __shfl_xor_sync(0xffffffffu, rs[rf][h], 2);
        }
    __syncthreads();
    if (tig == 0) {
#pragma unroll
        for (int rf = 0; rf < 2; rf++)
#pragma unroll
            for (int h = 0; h < 2; h++)
                rs_sm[wn * 128 + wm * 32 + rf * 16 + h * 8 + gID] = rs[rf][h];
    }
    __syncthreads();

    h16* __restrict__ P = g.P[z];
#pragma unroll
    for (int it = 0; it < 8; it++) {
        int idx = it * 256 + tid;
        int r = idx >> 4, c = idx & 15;
        uint32_t src = r * 256 + ((c ^ (r & 15)) << 4);
        size_t dst = (size_t)(mBase + r) * 2048 + nBase + c * 8;
        *(uint4*)(P + dst) = *(uint4*)(smP + src);
    }
    if (tid < 128)
        g.psum[z][(size_t)(mBase + tid) * 16 + blockIdx.y] = rs_sm[tid] + rs_sm[128 + tid];
}

// ---------------- PV GEMM: single-product fp16 ----------------
struct PVArgs {
    const h16 *A_[2], *B_[2];
    float* C[2];
    const float* linv[2];
};

__global__ __launch_bounds__(256, 2) void pv_gemm(PVArgs g) {
    extern __shared__ char sm[];
    const uint32_t sb = smem_u32(sm);
    const int z = blockIdx.z;
    const h16* __restrict__ A = g.A_[z];
    const h16* __restrict__ B = g.B_[z];
    const int Klen = 2048;
    const int tid = threadIdx.x;
    const int wid = tid >> 5, lane = tid & 31;
    const int wm = wid & 3, wn = wid >> 2;
    const int mBase = blockIdx.x * 128;
    const int nBase = blockIdx.y * 128;

    MMA_LOOP1();

    const int gID = lane >> 2, tig = lane & 3;
    float* __restrict__ C = g.C[z];
    const float* __restrict__ linv = g.linv[z];
#pragma unroll
    for (int rf = 0; rf < 2; rf++) {
        int r0 = mBase + wm * 32 + rf * 16 + gID;
        int r1 = r0 + 8;
        float i0 = linv[r0], i1 = linv[r1];
#pragma unroll
        for (int nt = 0; nt < 8; nt++) {
            int col = nBase + wn * 64 + nt * 8 + tig * 2;
            *(float2*)(C + (size_t)r0 * 256 + col) =
                make_float2(acc[rf][nt][0] * i0, acc[rf][nt][1] * i0);
            *(float2*)(C + (size_t)r1 * 256 + col) =
                make_float2(acc[rf][nt][2] * i1, acc[rf][nt][3] * i1);
        }
    }
}

// ---------------- reduce partial sums -> 1/l ----------------
__global__ __launch_bounds__(256) void reduce_l2(const float* __restrict__ ps0,
                                                 const float* __restrict__ ps1,
                                                 float* __restrict__ li0,
                                                 float* __restrict__ li1) {
    int row = blockIdx.x * 256 + threadIdx.x;
    const float* p = (blockIdx.y == 0 ? ps0 : ps1) + (size_t)row * 16;
    float s = 0.f;
#pragma unroll
    for (int i = 0; i < 16; i++) s += p[i];
    (blockIdx.y == 0 ? li0 : li1)[row] = 1.f / s;
}

// ---------------- out += outS ----------------
__global__ __launch_bounds__(256) void add_out(float* __restrict__ out,
                                               const float* __restrict__ add) {
    int i = (blockIdx.x * 256 + threadIdx.x) * 4;
    float4 a = *(float4*)(out + i);
    float4 b = *(const float4*)(add + i);
    a.x += b.x; a.y += b.y; a.z += b.z; a.w += b.w;
    *(float4*)(out + i) = a;
}

// ---------------- launch ----------------
extern "C" void kernel_launch(void* const* d_in, const int* in_sizes, int n_in,
                              void* d_out, int out_size) {
    const float* x    = (const float*)d_in[0];
    const float* chm  = (const float*)d_in[1];
    const float* chwq = (const float*)d_in[2];
    const float* chwk = (const float*)d_in[3];
    const float* chwv = (const float*)d_in[4];
    const float* spm  = (const float*)d_in[5];
    const float* spwq = (const float*)d_in[6];
    const float* spwk = (const float*)d_in[7];
    const float* spwv = (const float*)d_in[8];
    float* out = (float*)d_out;

    h16 *xh, *cmh, *smh, *wh;
    h16 *Qc, *Qf, *Kc, *Kf, *Vtc, *Vtf, *P0, *P1;
    float *ps0, *ps1, *li0, *li1, *qm, *qv, *km, *kv, *outS;
    cudaGetSymbolAddress((void**)&xh, g_x);
    cudaGetSymbolAddress((void**)&cmh, g_cm);
    cudaGetSymbolAddress((void**)&smh, g_sm2);
    cudaGetSymbolAddress((void**)&wh, g_w);
    cudaGetSymbolAddress((void**)&Qc, g_Qc);      cudaGetSymbolAddress((void**)&Qf, g_Qf);
    cudaGetSymbolAddress((void**)&Kc, g_Kc);      cudaGetSymbolAddress((void**)&Kf, g_Kf);
    cudaGetSymbolAddress((void**)&Vtc, g_Vtc);    cudaGetSymbolAddress((void**)&Vtf, g_Vtf);
    cudaGetSymbolAddress((void**)&P0, g_P0);      cudaGetSymbolAddress((void**)&P1, g_P1);
    cudaGetSymbolAddress((void**)&ps0, g_psum0);  cudaGetSymbolAddress((void**)&ps1, g_psum1);
    cudaGetSymbolAddress((void**)&li0, g_linv0);  cudaGetSymbolAddress((void**)&li1, g_linv1);
    cudaGetSymbolAddress((void**)&qm, g_qm);      cudaGetSymbolAddress((void**)&qv, g_qv);
    cudaGetSymbolAddress((void**)&km, g_km);      cudaGetSymbolAddress((void**)&kv, g_kv);
    cudaGetSymbolAddress((void**)&outS, g_OutS);

    cudaFuncSetAttribute(mma_gemm, cudaFuncAttributeMaxDynamicSharedMemorySize, GEMM_SMEM);
    cudaFuncSetAttribute(mma_proj, cudaFuncAttributeMaxDynamicSharedMemorySize, GEMM_SMEM);
    cudaFuncSetAttribute(pv_gemm, cudaFuncAttributeMaxDynamicSharedMemorySize, GEMM_SMEM);

    // 0: fp32 -> fp16
    const int WSZ = DDIM * DDIM;
    ConvArgs cv;
    cv.src[0] = x;    cv.dst[0] = xh;           cv.nblk[0] = NB * DDIM / 1024;
    cv.src[1] = chm;  cv.dst[1] = cmh;          cv.nblk[1] = MTOT * DDIM / 1024;
    cv.src[2] = spm;  cv.dst[2] = smh;          cv.nblk[2] = MTOT * DDIM / 1024;
    cv.src[3] = spwq; cv.dst[3] = wh + 0 * WSZ; cv.nblk[3] = WSZ / 1024;
    cv.src[4] = chwq; cv.dst[4] = wh + 1 * WSZ; cv.nblk[4] = WSZ / 1024;
    cv.src[5] = spwk; cv.dst[5] = wh + 2 * WSZ; cv.nblk[5] = WSZ / 1024;
    cv.src[6] = chwk; cv.dst[6] = wh + 3 * WSZ; cv.nblk[6] = WSZ / 1024;
    cv.src[7] = chwv; cv.dst[7] = wh + 4 * WSZ; cv.nblk[7] = WSZ / 1024;
    cv.src[8] = spwv; cv.dst[8] = wh + 5 * WSZ; cv.nblk[8] = WSZ / 1024;
    int totBlk = 0;
    for (int i = 0; i < 9; i++) totBlk += cv.nblk[i];
    conv_all<<<totBlk, 256>>>(cv);

    // 1: projections (single-product fp16)
    ProjM pm;
    pm.A_[0] = xh;  pm.B_[0] = wh + 0 * WSZ; pm.O[0] = Qf;  pm.mx[0] = NB / 128;   pm.trans[0] = 0;
    pm.A_[1] = xh;  pm.B_[1] = wh + 1 * WSZ; pm.O[1] = Qc;  pm.mx[1] = NB / 128;   pm.trans[1] = 0;
    pm.A_[2] = smh; pm.B_[2] = wh + 2 * WSZ; pm.O[2] = Kf;  pm.mx[2] = MTOT / 128; pm.trans[2] = 0;
    pm.A_[3] = cmh; pm.B_[3] = wh + 3 * WSZ; pm.O[3] = Kc;  pm.mx[3] = MTOT / 128; pm.trans[3] = 0;
    pm.A_[4] = cmh; pm.B_[4] = wh + 4 * WSZ; pm.O[4] = Vtc; pm.mx[4] = MTOT / 128; pm.trans[4] = 1;
    pm.A_[5] = smh; pm.B_[5] = wh + 5 * WSZ; pm.O[5] = Vtf; pm.mx[5] = MTOT / 128; pm.trans[5] = 1;
    mma_proj<<<dim3(NB / 128, 2, 6), 256, GEMM_SMEM>>>(pm);

    // 2: row stats
    row_stats2<<<(NB + MTOT) / 8, 256>>>(Qf, Kf, qm, qv, km, kv);

    // 3: score GEMMs (profiled)
    MMArgs sa;
    sa.A_[0] = Qc; sa.B_[0] = Kc;
    sa.A_[1] = Qf; sa.B_[1] = Kf;
    sa.P[0] = P0; sa.P[1] = P1;
    sa.psum[0] = ps0; sa.psum[1] = ps1;
    sa.qm = qm; sa.qv = qv; sa.km = km; sa.kv = kv;
    mma_gemm<<<dim3(NB / 128, MTOT / 128, 2), 256, GEMM_SMEM>>>(sa);

    // 4: reduce
    reduce_l2<<<dim3(NB / 256, 2), 256>>>(ps0, ps1, li0, li1);

    // 5: PV GEMMs
    PVArgs pa;
    pa.A_[0] = P0; pa.B_[0] = Vtc; pa.C[0] = out;  pa.linv[0] = li0;
    pa.A_[1] = P1; pa.B_[1] = Vtf; pa.C[1] = outS; pa.linv[1] = li1;
    pv_gemm<<<dim3(NB / 128, DDIM / 128, 2), 256, GEMM_SMEM>>>(pa);

    // 6: combine
    add_out<<<NB * DDIM / 1024, 256>>>(out, outS);
}

// round 13
// speedup vs baseline: 9.0193x; 1.1073x over previous
#include <cuda_runtime.h>
#include <cuda_fp16.h>
#include <cstdint>

#define NB   12544
#define MTOT 2048
#define DDIM 256

typedef __half h16;

// ---------------- scratch ----------------
__device__ __align__(16) h16 g_x[NB * DDIM];
__device__ __align__(16) h16 g_cm[MTOT * DDIM];
__device__ __align__(16) h16 g_sm2[MTOT * DDIM];
__device__ __align__(16) h16 g_w[6 * DDIM * DDIM];
__device__ __align__(16) h16 g_Qc[NB * DDIM];
__device__ __align__(16) h16 g_Qf[NB * DDIM];
__device__ __align__(16) h16 g_Kc[MTOT * DDIM];
__device__ __align__(16) h16 g_Kf[MTOT * DDIM];
__device__ __align__(16) h16 g_Vtc[DDIM * MTOT];
__device__ __align__(16) h16 g_Vtf[DDIM * MTOT];
__device__ __align__(16) h16 g_P0[(size_t)NB * MTOT];
__device__ __align__(16) h16 g_P1[(size_t)NB * MTOT];
__device__ float g_psum0[NB * 16], g_psum1[NB * 16];
__device__ float g_linv0[NB], g_linv1[NB];
__device__ float g_qm[NB], g_qv[NB], g_km[MTOT], g_kv[MTOT];
__device__ float g_OutS[NB * DDIM];

// ---------------- helpers ----------------
__device__ __forceinline__ uint32_t smem_u32(const void* p) {
    uint32_t a;
    asm("{ .reg .u64 t; cvta.to.shared.u64 t, %1; cvt.u32.u64 %0, t; }" : "=r"(a) : "l"(p));
    return a;
}
#define SWZ(o) ((o) ^ (((o) >> 3) & 0x70))

__device__ __forceinline__ void mma16816h(float* c, const uint32_t* a, const uint32_t* b) {
    asm volatile(
        "mma.sync.aligned.m16n8k16.row.col.f32.f16.f16.f32 "
        "{%0,%1,%2,%3}, {%4,%5,%6,%7}, {%8,%9}, {%0,%1,%2,%3};"
        : "+f"(c[0]), "+f"(c[1]), "+f"(c[2]), "+f"(c[3])
        : "r"(a[0]), "r"(a[1]), "r"(a[2]), "r"(a[3]), "r"(b[0]), "r"(b[1]));
}
__device__ __forceinline__ void ldsm_x4(uint32_t* r, uint32_t addr) {
    asm volatile("ldmatrix.sync.aligned.m8n8.x4.shared.b16 {%0,%1,%2,%3}, [%4];"
                 : "=r"(r[0]), "=r"(r[1]), "=r"(r[2]), "=r"(r[3]) : "r"(addr));
}
__device__ __forceinline__ void cp16(uint32_t dst, const void* src) {
    asm volatile("cp.async.cg.shared.global [%0], [%1], 16;" :: "r"(dst), "l"(src));
}
#define CP_COMMIT() asm volatile("cp.async.commit_group;" ::: "memory")
#define CP_WAIT1()  asm volatile("cp.async.wait_group 1;" ::: "memory")

// packed tile addressing (32-K chunk): 128 rows x 64B -> 64 smem rows x 128B
__device__ __forceinline__ uint32_t toff32(int row, int cb) {
    return SWZ((uint32_t)((row & 63) * 128 + ((row >> 6) << 6) + cb));
}
// full 128-row x 128B tile (64-K chunk)
__device__ __forceinline__ uint32_t toff64(int row, int cb) {
    return SWZ((uint32_t)(row * 128 + cb));
}

#define TILE_STG 32768          // 64-K chunk: A(16K)+B(16K)
#define GEMM_SMEM (3 * TILE_STG)
#define SC_STG 16384            // 32-K chunk: A(8K)+B(8K)
#define SC_SMEM (3 * SC_STG)

// ---------------- fp32 -> fp16 conversion (9 arrays) ----------------
struct ConvArgs {
    const float* src[9];
    h16* dst[9];
    int nblk[9];
};
__global__ __launch_bounds__(256) void conv_all(ConvArgs a) {
    int bx = blockIdx.x, z = 0;
    while (bx >= a.nblk[z]) { bx -= a.nblk[z]; z++; }
    size_t i = ((size_t)bx * 256 + threadIdx.x) * 4;
    float4 v = *(const float4*)(a.src[z] + i);
    __half2 ha; ha.x = __float2half(v.x); ha.y = __float2half(v.y);
    __half2 hb; hb.x = __float2half(v.z); hb.y = __float2half(v.w);
    *(__half2*)(a.dst[z] + i) = ha;
    *(__half2*)(a.dst[z] + i + 2) = hb;
}

// ---------------- single-product fp16 mainloop, 64-K chunks ----------------
#define MMA_LOOP64()                                                            \
    float acc[2][8][4];                                                         \
    _Pragma("unroll")                                                           \
    for (int rf = 0; rf < 2; rf++)                                              \
        _Pragma("unroll")                                                       \
        for (int nt = 0; nt < 8; nt++)                                          \
            _Pragma("unroll")                                                   \
            for (int c = 0; c < 4; c++) acc[rf][nt][c] = 0.f;                   \
    const int a_row = wm * 32 + (lane & 15);                                    \
    const int a_kb  = (lane >> 4) * 16;                                         \
    const int b_row = wn * 64 + ((lane >> 4) << 3) + (lane & 7);                \
    const int b_kb  = ((lane >> 3) & 1) * 16;                                   \
    const int nIter = Klen >> 6;                                                \
    auto issue = [&](int buf, int k0) {                                         \
        uint32_t base = sb + buf * TILE_STG;                                    \
        _Pragma("unroll")                                                       \
        for (int u = 0; u < 4; u++) {                                           \
            int idx = u * 256 + tid;                                            \
            int r = idx >> 3, gch = idx & 7;                                    \
            uint32_t off = SWZ((uint32_t)(r * 128 + gch * 16));                 \
            cp16(base + off,         A + (size_t)(mBase + r) * Klen + k0 + gch * 8); \
            cp16(base + 16384 + off, B + (size_t)(nBase + r) * Klen + k0 + gch * 8); \
        }                                                                       \
    };                                                                          \
    issue(0, 0); CP_COMMIT();                                                   \
    if (nIter > 1) issue(1, 64);                                                \
    CP_COMMIT();                                                                \
    int buf = 0;                                                                \
    for (int it = 0; it < nIter; it++) {                                        \
        CP_WAIT1();                                                             \
        __syncthreads();                                                        \
        if (it + 2 < nIter) issue((it + 2) % 3, (it + 2) * 64);                 \
        CP_COMMIT();                                                            \
        const uint32_t sbase = sb + buf * TILE_STG;                             \
        _Pragma("unroll")                                                       \
        for (int ks = 0; ks < 4; ks++) {                                        \
            uint32_t ah[2][4];                                                  \
            _Pragma("unroll")                                                   \
            for (int rf = 0; rf < 2; rf++)                                      \
                ldsm_x4(ah[rf], sbase + toff64(a_row + rf * 16, ks * 32 + a_kb)); \
            _Pragma("unroll")                                                   \
            for (int ntp = 0; ntp < 4; ntp++) {                                 \
                uint32_t bh4[4];                                                \
                ldsm_x4(bh4, sbase + 16384 + toff64(b_row + ntp * 16, ks * 32 + b_kb)); \
                _Pragma("unroll")                                               \
                for (int rf = 0; rf < 2; rf++) {                                \
                    mma16816h(acc[rf][2 * ntp],     ah[rf], bh4);               \
                    mma16816h(acc[rf][2 * ntp + 1], ah[rf], bh4 + 2);           \
                }                                                               \
            }                                                                   \
        }                                                                       \
        buf++; if (buf == 3) buf = 0;                                           \
    }

// ---------------- projection GEMMs (single-product fp16, 64-K) ----------------
struct ProjM {
    const h16 *A_[6], *B_[6];
    h16* O[6];
    int mx[6], trans[6];
};
__global__ __launch_bounds__(256, 2) void mma_proj(ProjM p) {
    extern __shared__ char sm[];
    const int z = blockIdx.z;
    if ((int)blockIdx.x >= p.mx[z]) return;
    const uint32_t sb = smem_u32(sm);
    const h16* __restrict__ A = p.A_[z];
    const h16* __restrict__ B = p.B_[z];
    const int Klen = 256;
    const int tid = threadIdx.x;
    const int wid = tid >> 5, lane = tid & 31;
    const int wm = wid & 3, wn = wid >> 2;
    const int mBase = blockIdx.x * 128;
    const int nBase = blockIdx.y * 128;

    MMA_LOOP64();

    const int gID = lane >> 2, tig = lane & 3;
    h16* __restrict__ O = p.O[z];

    if (p.trans[z]) {
#pragma unroll
        for (int rf = 0; rf < 2; rf++) {
            int r0 = mBase + wm * 32 + rf * 16 + gID;
#pragma unroll
            for (int nt = 0; nt < 8; nt++) {
                int col = nBase + wn * 64 + nt * 8 + tig * 2;
#pragma unroll
                for (int c = 0; c < 4; c++) {
                    int row = r0 + (c >> 1) * 8;
                    int cc = col + (c & 1);
                    O[(size_t)cc * MTOT + row] = __float2half(acc[rf][nt][c]);
                }
            }
        }
        return;
    }

    __syncthreads();
    char* smP = sm;
#pragma unroll
    for (int rf = 0; rf < 2; rf++) {
#pragma unroll
        for (int nt = 0; nt < 8; nt++) {
            int chunk = wn * 8 + nt;
#pragma unroll
            for (int half = 0; half < 2; half++) {
                int rl = wm * 32 + rf * 16 + half * 8 + gID;
                __half2 hh;
                hh.x = __float2half(acc[rf][nt][half * 2 + 0]);
                hh.y = __float2half(acc[rf][nt][half * 2 + 1]);
                uint32_t addr = rl * 256 + ((chunk ^ (rl & 15)) << 4) + tig * 4;
                *(__half2*)(smP + addr) = hh;
            }
        }
    }
    __syncthreads();
#pragma unroll
    for (int it = 0; it < 8; it++) {
        int idx = it * 256 + tid;
        int r = idx >> 4, c = idx & 15;
        uint32_t src = r * 256 + ((c ^ (r & 15)) << 4);
        size_t dst = (size_t)(mBase + r) * 256 + nBase + c * 8;
        *(uint4*)(O + dst) = *(uint4*)(smP + src);
    }
}

// ---------------- merged row stats (fp16 input) ----------------
__global__ __launch_bounds__(256) void row_stats2(
    const h16* __restrict__ Qf, const h16* __restrict__ Kf,
    float* __restrict__ qm, float* __restrict__ qv,
    float* __restrict__ km, float* __restrict__ kv) {
    int row = blockIdx.x * 8 + (threadIdx.x >> 5);
    const int lane = threadIdx.x & 31;
    const h16* X;
    float *mean, *var;
    if (row < NB) { X = Qf; mean = qm; var = qv; }
    else { row -= NB; X = Kf; mean = km; var = kv; }
    const size_t base = (size_t)row * 256;
    float s = 0.f, ss = 0.f;
#pragma unroll
    for (int c = 0; c < 256; c += 32) {
        float v = __half2float(X[base + c + lane]);
        s += v; ss += v * v;
    }
#pragma unroll
    for (int o = 16; o > 0; o >>= 1) {
        s += __shfl_xor_sync(0xffffffffu, s, o);
        ss += __shfl_xor_sync(0xffffffffu, ss, o);
    }
    if (lane == 0) {
        float m = s * (1.f / 256.f);
        mean[row] = m;
        var[row] = (ss - 256.f * m * m) * (1.f / 255.f);
    }
}

// ---------------- score MMA GEMM: single-product fp16, 32-K chunks ----------------
struct MMArgs {
    const h16 *A_[2], *B_[2];
    h16* P[2];
    float* psum[2];
    const float *qm, *qv, *km, *kv;
};

__global__ __launch_bounds__(256, 2) void mma_gemm(MMArgs g) {
    extern __shared__ char sm[];
    const uint32_t sb = smem_u32(sm);
    const int z = blockIdx.z;
    const h16* __restrict__ A = g.A_[z];
    const h16* __restrict__ B = g.B_[z];
    const int Klen = 256;
    const int tid = threadIdx.x;
    const int wid = tid >> 5, lane = tid & 31;
    const int wm = wid & 3, wn = wid >> 2;
    const int mBase = blockIdx.x * 128;
    const int nBase = blockIdx.y * 128;

    float acc[2][8][4];
#pragma unroll
    for (int rf = 0; rf < 2; rf++)
#pragma unroll
        for (int nt = 0; nt < 8; nt++)
#pragma unroll
            for (int c = 0; c < 4; c++) acc[rf][nt][c] = 0.f;

    const int a_row = wm * 32 + (lane & 15);
    const int a_kb  = (lane >> 4) * 16;
    const int b_row = wn * 64 + ((lane >> 4) << 3) + (lane & 7);
    const int b_kb  = ((lane >> 3) & 1) * 16;
    const int lr0 = tid >> 2;
    const int lg  = (tid & 3);
    const int nIter = Klen >> 5;        // 8

    auto issue = [&](int buf, int k0) {
        uint32_t base = sb + buf * SC_STG;
#pragma unroll
        for (int h = 0; h < 2; h++) {
            int r = lr0 + h * 64;
            uint32_t off = toff32(r, lg * 16);
            cp16(base + off,        A + (size_t)(mBase + r) * Klen + k0 + lg * 8);
            cp16(base + 8192 + off, B + (size_t)(nBase + r) * Klen + k0 + lg * 8);
        }
    };

    issue(0, 0); CP_COMMIT();
    issue(1, 32); CP_COMMIT();

    int buf = 0;
    for (int it = 0; it < nIter; it++) {
        CP_WAIT1();
        __syncthreads();
        if (it + 2 < nIter) issue((it + 2) % 3, (it + 2) * 32);
        CP_COMMIT();

        const uint32_t sbase = sb + buf * SC_STG;
#pragma unroll
        for (int ks = 0; ks < 2; ks++) {
            uint32_t ah[2][4];
#pragma unroll
            for (int rf = 0; rf < 2; rf++)
                ldsm_x4(ah[rf], sbase + toff32(a_row + rf * 16, ks * 32 + a_kb));
#pragma unroll
            for (int ntp = 0; ntp < 4; ntp++) {
                uint32_t bh4[4];
                ldsm_x4(bh4, sbase + 8192 + toff32(b_row + ntp * 16, ks * 32 + b_kb));
#pragma unroll
                for (int rf = 0; rf < 2; rf++) {
                    mma16816h(acc[rf][2 * ntp],     ah[rf], bh4);
                    mma16816h(acc[rf][2 * ntp + 1], ah[rf], bh4 + 2);
                }
            }
        }
        buf++; if (buf == 3) buf = 0;
    }

    const int gID = lane >> 2, tig = lane & 3;
    const int mode = (z == 0) ? 0 : 1;
    char* smP = sm;                         // 32KB P staging
    float* rs_sm = (float*)(sm + 32768);    // 1KB row sums
    float* kmS  = (float*)(sm + 33792);     // 512B km
    float* km2S = (float*)(sm + 34304);     // 512B km^2+0.01
    float* kvS  = (float*)(sm + 34816);     // 512B kv+0.03
    float rs[2][2];
    rs[0][0] = rs[0][1] = rs[1][0] = rs[1][1] = 0.f;

    __syncthreads();                        // pipeline smem free
    if (mode == 1 && tid < 128) {
        float kmv = g.km[nBase + tid];
        float kvv = g.kv[nBase + tid];
        kmS[tid]  = kmv;
        km2S[tid] = kmv * kmv + 0.01f;
        kvS[tid]  = kvv + 0.03f;
    }
    __syncthreads();

#pragma unroll
    for (int rf = 0; rf < 2; rf++) {
        int r0 = mBase + wm * 32 + rf * 16 + gID;
        int r1 = r0 + 8;
        float qm0 = 0.f, qv0 = 0.f, qm1 = 0.f, qv1 = 0.f, qm0sq = 0.f, qm1sq = 0.f;
        if (mode == 1) {
            qm0 = g.qm[r0]; qv0 = g.qv[r0]; qm0sq = qm0 * qm0;
            qm1 = g.qm[r1]; qv1 = g.qv[r1]; qm1sq = qm1 * qm1;
        }
#pragma unroll
        for (int nt = 0; nt < 8; nt++) {
            int lcol = wn * 64 + nt * 8 + tig * 2;
            float v0 = acc[rf][nt][0], v1 = acc[rf][nt][1];
            float v2 = acc[rf][nt][2], v3 = acc[rf][nt][3];
            if (mode == 0) {
                v0 = __expf(v0 * 0.0625f); v1 = __expf(v1 * 0.0625f);
                v2 = __expf(v2 * 0.0625f); v3 = __expf(v3 * 0.0625f);
            } else {
                float km0 = kmS[lcol],  km20 = km2S[lcol],  kv0c = kvS[lcol];
                float km1 = kmS[lcol + 1], km21 = km2S[lcol + 1], kv1c = kvS[lcol + 1];
#define SSIMF(dot, QM, QMSQ, QV, KM, KM2, KVC)                                  \
    ({ float mp = (QM) * (KM);                                                  \
       float a = fmaf(2.f, mp, 0.01f);                                          \
       float t = fmaf((dot), 2.f / 255.f, fmaf(mp, -512.f / 255.f, 0.03f));     \
       float num = a * t;                                                       \
       float den = ((QMSQ) + (KM2)) * ((QV) + (KVC)) + 1e-8f;                   \
       __fdividef(num, den); })
                v0 = __expf(SSIMF(v0, qm0, qm0sq, qv0, km0, km20, kv0c));
                v1 = __expf(SSIMF(v1, qm0, qm0sq, qv0, km1, km21, kv1c));
                v2 = __expf(SSIMF(v2, qm1, qm1sq, qv1, km0, km20, kv0c));
                v3 = __expf(SSIMF(v3, qm1, qm1sq, qv1, km1, km21, kv1c));
            }
            rs[rf][0] += v0 + v1;
            rs[rf][1] += v2 + v3;

            int chunk = wn * 8 + nt;
            int rl0 = wm * 32 + rf * 16 + gID;
            int rl1 = rl0 + 8;
            __half2 p0; p0.x = __float2half(v0); p0.y = __float2half(v1);
            __half2 p1; p1.x = __float2half(v2); p1.y = __float2half(v3);
            uint32_t a0 = rl0 * 256 + ((chunk ^ (rl0 & 15)) << 4) + tig * 4;
            uint32_t a1 = rl1 * 256 + ((chunk ^ (rl1 & 15)) << 4) + tig * 4;
            *(__half2*)(smP + a0) = p0;
            *(__half2*)(smP + a1) = p1;
        }
    }

#pragma unroll
    for (int rf = 0; rf < 2; rf++)
#pragma unroll
        for (int h = 0; h < 2; h++) {
            rs[rf][h] += __shfl_xor_sync(0xffffffffu, rs[rf][h], 1);
            rs[rf][h] += __shfl_xor_sync(0xffffffffu, rs[rf][h], 2);
        }
    __syncthreads();
    if (tig == 0) {
#pragma unroll
        for (int rf = 0; rf < 2; rf++)
#pragma unroll
            for (int h = 0; h < 2; h++)
                rs_sm[wn * 128 + wm * 32 + rf * 16 + h * 8 + gID] = rs[rf][h];
    }
    __syncthreads();

    h16* __restrict__ P = g.P[z];
#pragma unroll
    for (int it = 0; it < 8; it++) {
        int idx = it * 256 + tid;
        int r = idx >> 4, c = idx & 15;
        uint32_t src = r * 256 + ((c ^ (r & 15)) << 4);
        size_t dst = (size_t)(mBase + r) * 2048 + nBase + c * 8;
        *(uint4*)(P + dst) = *(uint4*)(smP + src);
    }
    if (tid < 128)
        g.psum[z][(size_t)(mBase + tid) * 16 + blockIdx.y] = rs_sm[tid] + rs_sm[128 + tid];
}

// ---------------- PV GEMM: single-product fp16, 64-K chunks ----------------
struct PVArgs {
    const h16 *A_[2], *B_[2];
    float* C[2];
    const float* linv[2];
};

__global__ __launch_bounds__(256, 2) void pv_gemm(PVArgs g) {
    extern __shared__ char sm[];
    const uint32_t sb = smem_u32(sm);
    const int z = blockIdx.z;
    const h16* __restrict__ A = g.A_[z];
    const h16* __restrict__ B = g.B_[z];
    const int Klen = 2048;
    const int tid = threadIdx.x;
    const int wid = tid >> 5, lane = tid & 31;
    const int wm = wid & 3, wn = wid >> 2;
    const int mBase = blockIdx.x * 128;
    const int nBase = blockIdx.y * 128;

    MMA_LOOP64();

    const int gID = lane >> 2, tig = lane & 3;
    float* __restrict__ C = g.C[z];
    const float* __restrict__ linv = g.linv[z];
#pragma unroll
    for (int rf = 0; rf < 2; rf++) {
        int r0 = mBase + wm * 32 + rf * 16 + gID;
        int r1 = r0 + 8;
        float i0 = linv[r0], i1 = linv[r1];
#pragma unroll
        for (int nt = 0; nt < 8; nt++) {
            int col = nBase + wn * 64 + nt * 8 + tig * 2;
            *(float2*)(C + (size_t)r0 * 256 + col) =
                make_float2(acc[rf][nt][0] * i0, acc[rf][nt][1] * i0);
            *(float2*)(C + (size_t)r1 * 256 + col) =
                make_float2(acc[rf][nt][2] * i1, acc[rf][nt][3] * i1);
        }
    }
}

// ---------------- reduce partial sums -> 1/l ----------------
__global__ __launch_bounds__(256) void reduce_l2(const float* __restrict__ ps0,
                                                 const float* __restrict__ ps1,
                                                 float* __restrict__ li0,
                                                 float* __restrict__ li1) {
    int row = blockIdx.x * 256 + threadIdx.x;
    const float* p = (blockIdx.y == 0 ? ps0 : ps1) + (size_t)row * 16;
    float s = 0.f;
#pragma unroll
    for (int i = 0; i < 16; i++) s += p[i];
    (blockIdx.y == 0 ? li0 : li1)[row] = 1.f / s;
}

// ---------------- out += outS ----------------
__global__ __launch_bounds__(256) void add_out(float* __restrict__ out,
                                               const float* __restrict__ add) {
    int i = (blockIdx.x * 256 + threadIdx.x) * 4;
    float4 a = *(float4*)(out + i);
    float4 b = *(const float4*)(add + i);
    a.x += b.x; a.y += b.y; a.z += b.z; a.w += b.w;
    *(float4*)(out + i) = a;
}

// ---------------- launch ----------------
extern "C" void kernel_launch(void* const* d_in, const int* in_sizes, int n_in,
                              void* d_out, int out_size) {
    const float* x    = (const float*)d_in[0];
    const float* chm  = (const float*)d_in[1];
    const float* chwq = (const float*)d_in[2];
    const float* chwk = (const float*)d_in[3];
    const float* chwv = (const float*)d_in[4];
    const float* spm  = (const float*)d_in[5];
    const float* spwq = (const float*)d_in[6];
    const float* spwk = (const float*)d_in[7];
    const float* spwv = (const float*)d_in[8];
    float* out = (float*)d_out;

    h16 *xh, *cmh, *smh, *wh;
    h16 *Qc, *Qf, *Kc, *Kf, *Vtc, *Vtf, *P0, *P1;
    float *ps0, *ps1, *li0, *li1, *qm, *qv, *km, *kv, *outS;
    cudaGetSymbolAddress((void**)&xh, g_x);
    cudaGetSymbolAddress((void**)&cmh, g_cm);
    cudaGetSymbolAddress((void**)&smh, g_sm2);
    cudaGetSymbolAddress((void**)&wh, g_w);
    cudaGetSymbolAddress((void**)&Qc, g_Qc);      cudaGetSymbolAddress((void**)&Qf, g_Qf);
    cudaGetSymbolAddress((void**)&Kc, g_Kc);      cudaGetSymbolAddress((void**)&Kf, g_Kf);
    cudaGetSymbolAddress((void**)&Vtc, g_Vtc);    cudaGetSymbolAddress((void**)&Vtf, g_Vtf);
    cudaGetSymbolAddress((void**)&P0, g_P0);      cudaGetSymbolAddress((void**)&P1, g_P1);
    cudaGetSymbolAddress((void**)&ps0, g_psum0);  cudaGetSymbolAddress((void**)&ps1, g_psum1);
    cudaGetSymbolAddress((void**)&li0, g_linv0);  cudaGetSymbolAddress((void**)&li1, g_linv1);
    cudaGetSymbolAddress((void**)&qm, g_qm);      cudaGetSymbolAddress((void**)&qv, g_qv);
    cudaGetSymbolAddress((void**)&km, g_km);      cudaGetSymbolAddress((void**)&kv, g_kv);
    cudaGetSymbolAddress((void**)&outS, g_OutS);

    cudaFuncSetAttribute(mma_gemm, cudaFuncAttributeMaxDynamicSharedMemorySize, SC_SMEM);
    cudaFuncSetAttribute(mma_proj, cudaFuncAttributeMaxDynamicSharedMemorySize, GEMM_SMEM);
    cudaFuncSetAttribute(pv_gemm, cudaFuncAttributeMaxDynamicSharedMemorySize, GEMM_SMEM);

    // 0: fp32 -> fp16
    const int WSZ = DDIM * DDIM;
    ConvArgs cv;
    cv.src[0] = x;    cv.dst[0] = xh;           cv.nblk[0] = NB * DDIM / 1024;
    cv.src[1] = chm;  cv.dst[1] = cmh;          cv.nblk[1] = MTOT * DDIM / 1024;
    cv.src[2] = spm;  cv.dst[2] = smh;          cv.nblk[2] = MTOT * DDIM / 1024;
    cv.src[3] = spwq; cv.dst[3] = wh + 0 * WSZ; cv.nblk[3] = WSZ / 1024;
    cv.src[4] = chwq; cv.dst[4] = wh + 1 * WSZ; cv.nblk[4] = WSZ / 1024;
    cv.src[5] = spwk; cv.dst[5] = wh + 2 * WSZ; cv.nblk[5] = WSZ / 1024;
    cv.src[6] = chwk; cv.dst[6] = wh + 3 * WSZ; cv.nblk[6] = WSZ / 1024;
    cv.src[7] = chwv; cv.dst[7] = wh + 4 * WSZ; cv.nblk[7] = WSZ / 1024;
    cv.src[8] = spwv; cv.dst[8] = wh + 5 * WSZ; cv.nblk[8] = WSZ / 1024;
    int totBlk = 0;
    for (int i = 0; i < 9; i++) totBlk += cv.nblk[i];
    conv_all<<<totBlk, 256>>>(cv);

    // 1: projections
    ProjM pm;
    pm.A_[0] = xh;  pm.B_[0] = wh + 0 * WSZ; pm.O[0] = Qf;  pm.mx[0] = NB / 128;   pm.trans[0] = 0;
    pm.A_[1] = xh;  pm.B_[1] = wh + 1 * WSZ; pm.O[1] = Qc;  pm.mx[1] = NB / 128;   pm.trans[1] = 0;
    pm.A_[2] = smh; pm.B_[2] = wh + 2 * WSZ; pm.O[2] = Kf;  pm.mx[2] = MTOT / 128; pm.trans[2] = 0;
    pm.A_[3] = cmh; pm.B_[3] = wh + 3 * WSZ; pm.O[3] = Kc;  pm.mx[3] = MTOT / 128; pm.trans[3] = 0;
    pm.A_[4] = cmh; pm.B_[4] = wh + 4 * WSZ; pm.O[4] = Vtc; pm.mx[4] = MTOT / 128; pm.trans[4] = 1;
    pm.A_[5] = smh; pm.B_[5] = wh + 5 * WSZ; pm.O[5] = Vtf; pm.mx[5] = MTOT / 128; pm.trans[5] = 1;
    mma_proj<<<dim3(NB / 128, 2, 6), 256, GEMM_SMEM>>>(pm);

    // 2: row stats
    row_stats2<<<(NB + MTOT) / 8, 256>>>(Qf, Kf, qm, qv, km, kv);

    // 3: score GEMMs (profiled)
    MMArgs sa;
    sa.A_[0] = Qc; sa.B_[0] = Kc;
    sa.A_[1] = Qf; sa.B_[1] = Kf;
    sa.P[0] = P0; sa.P[1] = P1;
    sa.psum[0] = ps0; sa.psum[1] = ps1;
    sa.qm = qm; sa.qv = qv; sa.km = km; sa.kv = kv;
    mma_gemm<<<dim3(NB / 128, MTOT / 128, 2), 256, SC_SMEM>>>(sa);

    // 4: reduce
    reduce_l2<<<dim3(NB / 256, 2), 256>>>(ps0, ps1, li0, li1);

    // 5: PV GEMMs
    PVArgs pa;
    pa.A_[0] = P0; pa.B_[0] = Vtc; pa.C[0] = out;  pa.linv[0] = li0;
    pa.A_[1] = P1; pa.B_[1] = Vtf; pa.C[1] = outS; pa.linv[1] = li1;
    pv_gemm<<<dim3(NB / 128, DDIM / 128, 2), 256, GEMM_SMEM>>>(pa);

    // 6: combine
    add_out<<<NB * DDIM / 1024, 256>>>(out, outS);
}